// round 1
// baseline (speedup 1.0000x reference)
#include <cuda_runtime.h>

#define NA    32      // agents per group
#define HH    64      // hidden
#define HS    65      // padded smem row stride (conflict-free lane-strided access)
#define NINV  16
#define NLAY  4
#define OBSW  20      // INV + 4

#define SMEM_FLOATS (3*NA*HS + NA*HH + NA*NA + 2*HH*HH + 5*HH + 6*NA)
#define SMEM_BYTES  (SMEM_FLOATS * 4)

__device__ __forceinline__ float siluf(float x) {
    return x / (1.0f + __expf(-x));
}

__device__ __forceinline__ float wredsum(float v) {
    v += __shfl_down_sync(0xffffffffu, v, 16);
    v += __shfl_down_sync(0xffffffffu, v, 8);
    v += __shfl_down_sync(0xffffffffu, v, 4);
    v += __shfl_down_sync(0xffffffffu, v, 2);
    v += __shfl_down_sync(0xffffffffu, v, 1);
    return v;
}

// DSTR[64] = silu(SRCR[64] @ WSH[64x64] + BSH[64]); registers in/out, smem weights.
// Fully unrolled: 4096 FFMA + 1024 broadcast LDS.128 per call.
#define MLP64(SRCR, DSTR, WSH, BSH)                                              \
    _Pragma("unroll")                                                            \
    for (int kt = 0; kt < HH; kt += 8) {                                         \
        float a0 = BSH[kt+0], a1 = BSH[kt+1], a2 = BSH[kt+2], a3 = BSH[kt+3];    \
        float a4 = BSH[kt+4], a5 = BSH[kt+5], a6 = BSH[kt+6], a7 = BSH[kt+7];    \
        _Pragma("unroll")                                                        \
        for (int c = 0; c < HH; c++) {                                           \
            float4 wa = *(const float4*)&WSH[c*HH + kt];                         \
            float4 wb = *(const float4*)&WSH[c*HH + kt + 4];                     \
            float mv = SRCR[c];                                                  \
            a0 += mv*wa.x; a1 += mv*wa.y; a2 += mv*wa.z; a3 += mv*wa.w;          \
            a4 += mv*wb.x; a5 += mv*wb.y; a6 += mv*wb.z; a7 += mv*wb.w;          \
        }                                                                        \
        DSTR[kt+0] = siluf(a0); DSTR[kt+1] = siluf(a1);                          \
        DSTR[kt+2] = siluf(a2); DSTR[kt+3] = siluf(a3);                          \
        DSTR[kt+4] = siluf(a4); DSTR[kt+5] = siluf(a5);                          \
        DSTR[kt+6] = siluf(a6); DSTR[kt+7] = siluf(a7);                          \
    }

__global__ void __launch_bounds__(256, 1)
egnn_kernel(const float* __restrict__ obs,
            const float* __restrict__ scl,
            const float* __restrict__ mn,
            const float* __restrict__ embW,
            const float* __restrict__ embb,
            const float* __restrict__ We1,
            const float* __restrict__ be1,
            const float* __restrict__ We2,
            const float* __restrict__ be2,
            const float* __restrict__ Wc1,
            const float* __restrict__ bc1,
            const float* __restrict__ Wc2,
            const float* __restrict__ bc2,
            const float* __restrict__ Wv1,
            const float* __restrict__ bv1,
            const float* __restrict__ Wv2,
            const float* __restrict__ bv2,
            const float* __restrict__ Wn1,
            const float* __restrict__ bn1,
            const float* __restrict__ Wn2,
            const float* __restrict__ bn2,
            float* __restrict__ out)
{
    extern __shared__ float sm[];
    float* hS    = sm;                 // [NA][HS]
    float* AS    = hS    + NA*HS;      // [NA][HS]  A = h@We1[:64]+be1 ; reused as U
    float* BS    = AS    + NA*HS;      // [NA][HS]  B = h@We1[64:128] ; also obs staging
    float* maggS = BS    + NA*HS;      // [NA][HH]
    float* eaS   = maggS + NA*HH;      // [NA][NA]
    float* We2s  = eaS   + NA*NA;      // [HH*HH]
    float* Wc1s  = We2s  + HH*HH;      // [HH*HH]
    float* w128s = Wc1s  + HH*HH;      // [HH]
    float* w129s = w128s + HH;         // [HH]
    float* be2s  = w129s + HH;         // [HH]
    float* bc1s  = be2s  + HH;         // [HH]
    float* Wc2s  = bc1s  + HH;         // [HH]
    float* locS  = Wc2s  + HH;         // [NA*2]
    float* velS  = locS  + NA*2;       // [NA*2]
    float* aggS  = velS  + NA*2;       // [NA*2]

    const int tid  = threadIdx.x;
    const int w    = tid >> 5;         // warp id (0..7)
    const int lane = tid & 31;
    const int g    = blockIdx.x;

    // ---- stage obs for this group into BS scratch ----
    const float* obsg = obs + (size_t)g * NA * OBSW;
    for (int t = tid; t < NA*OBSW; t += 256) BS[t] = obsg[t];
    __syncthreads();

    if (tid < NA*2) {
        int i = tid >> 1, c = tid & 1;
        locS[tid] = BS[i*OBSW + NINV + c];
        velS[tid] = BS[i*OBSW + NINV + 2 + c];
    }
    __syncthreads();

    // edge_attr from INITIAL loc (stop_gradient term)
    for (int p = tid; p < NA*NA; p += 256) {
        int i = p >> 5, j = p & 31;
        float dx = locS[i*2+0] - locS[j*2+0];
        float dy = locS[i*2+1] - locS[j*2+1];
        eaS[p] = dx*dx + dy*dy;
    }

    // h = inv @ embW + embb   (warp w owns rows 4w..4w+3; lane owns cols lane, lane+32)
    {
        float a0[4], a1[4];
        #pragma unroll
        for (int r = 0; r < 4; r++) { a0[r] = embb[lane]; a1[r] = embb[lane+32]; }
        #pragma unroll
        for (int c = 0; c < NINV; c++) {
            float w0 = embW[c*HH + lane];
            float w1 = embW[c*HH + lane + 32];
            #pragma unroll
            for (int r = 0; r < 4; r++) {
                float iv = BS[(w*4+r)*OBSW + c];
                a0[r] += iv*w0; a1[r] += iv*w1;
            }
        }
        #pragma unroll
        for (int r = 0; r < 4; r++) {
            hS[(w*4+r)*HS + lane]      = a0[r];
            hS[(w*4+r)*HS + lane + 32] = a1[r];
        }
    }
    __syncthreads();

    #pragma unroll 1
    for (int l = 0; l < NLAY; l++) {
        // ---- stage hot per-layer weights into smem ----
        const float* We2l = We2 + l*HH*HH;
        const float* Wc1l = Wc1 + l*HH*HH;
        for (int t = tid; t < HH*HH; t += 256) {
            We2s[t] = We2l[t];
            Wc1s[t] = Wc1l[t];
        }
        if (tid < HH) {
            w128s[tid] = We1[(l*130 + 128)*HH + tid];
            w129s[tid] = We1[(l*130 + 129)*HH + tid];
            be2s[tid]  = be2[l*HH + tid];
            bc1s[tid]  = bc1[l*HH + tid];
            Wc2s[tid]  = Wc2[l*HH + tid];
        }

        // ---- node projections: A = h@We1[:64]+be1, B = h@We1[64:128] ----
        {
            float a0[4], a1[4], b0[4], b1[4];
            #pragma unroll
            for (int r = 0; r < 4; r++) {
                a0[r] = be1[l*HH + lane]; a1[r] = be1[l*HH + lane + 32];
                b0[r] = 0.f; b1[r] = 0.f;
            }
            #pragma unroll 4
            for (int c = 0; c < HH; c++) {
                const float* wrA = We1 + (l*130 + c)*HH;
                const float* wrB = We1 + (l*130 + 64 + c)*HH;
                float wa0 = wrA[lane], wa1 = wrA[lane+32];
                float wb0 = wrB[lane], wb1 = wrB[lane+32];
                #pragma unroll
                for (int r = 0; r < 4; r++) {
                    float hv = hS[(w*4+r)*HS + c];
                    a0[r] += hv*wa0; a1[r] += hv*wa1;
                    b0[r] += hv*wb0; b1[r] += hv*wb1;
                }
            }
            #pragma unroll
            for (int r = 0; r < 4; r++) {
                AS[(w*4+r)*HS + lane]      = a0[r];
                AS[(w*4+r)*HS + lane + 32] = a1[r];
                BS[(w*4+r)*HS + lane]      = b0[r];
                BS[(w*4+r)*HS + lane + 32] = b1[r];
            }
        }
        __syncthreads();

        // ---- edge phase: warp = receiver i, lane = sender j ----
        #pragma unroll 1
        for (int ib = 0; ib < 4; ib++) {
            const int i = ib*8 + w;
            const int j = lane;
            float dx = locS[i*2+0] - locS[j*2+0];
            float dy = locS[i*2+1] - locS[j*2+1];
            float radial = dx*dx + dy*dy;
            float invr = 1.0f / (sqrtf(radial) + 1.0f);
            float dnx = dx * invr, dny = dy * invr;
            float eav = eaS[i*NA + j];

            float m1r[HH], m2r[HH];
            #pragma unroll
            for (int k = 0; k < HH; k++) {
                float v = AS[i*HS + k] + BS[j*HS + k]
                        + radial * w128s[k] + eav * w129s[k];
                m1r[k] = siluf(v);
            }

            MLP64(m1r, m2r, We2s, be2s);   // m2 = silu(m1@We2+be2)  (this is "m")
            MLP64(m2r, m1r, Wc1s, bc1s);   // t  = silu(m2@Wc1+bc1) -> reuse m1r

            float cs = bc2[l];
            #pragma unroll
            for (int k = 0; k < HH; k++) cs += m1r[k] * Wc2s[k];

            float vm = (j == i) ? 0.0f : 1.0f;
            float tx = wredsum(vm * dnx * cs);
            float ty = wredsum(vm * dny * cs);
            if (lane == 0) { aggS[i*2+0] = tx; aggS[i*2+1] = ty; }

            #pragma unroll
            for (int k = 0; k < HH; k++) {
                float v = wredsum(vm * m2r[k]);
                if (lane == 0) maggS[i*HH + k] = v;
            }
        }
        __syncthreads();

        // ---- node phase: phi_v, vel/loc update ----
        {
            float a0[4], a1[4];
            #pragma unroll
            for (int r = 0; r < 4; r++) { a0[r] = bv1[l*HH+lane]; a1[r] = bv1[l*HH+lane+32]; }
            #pragma unroll 4
            for (int c = 0; c < HH; c++) {
                const float* wr = Wv1 + (l*HH + c)*HH;
                float w0 = wr[lane], w1 = wr[lane+32];
                #pragma unroll
                for (int r = 0; r < 4; r++) {
                    float hv = hS[(w*4+r)*HS + c];
                    a0[r] += hv*w0; a1[r] += hv*w1;
                }
            }
            float wv2a = Wv2[l*HH + lane], wv2b = Wv2[l*HH + lane + 32];
            #pragma unroll
            for (int r = 0; r < 4; r++) {
                float part = wredsum(siluf(a0[r])*wv2a + siluf(a1[r])*wv2b);
                if (lane == 0) {
                    int i = w*4 + r;
                    float phi = part + bv2[l];
                    float vx = phi*velS[i*2+0] + aggS[i*2+0]*(1.0f/31.0f);
                    float vy = phi*velS[i*2+1] + aggS[i*2+1]*(1.0f/31.0f);
                    velS[i*2+0] = vx; velS[i*2+1] = vy;
                    locS[i*2+0] += vx; locS[i*2+1] += vy;
                }
            }
        }

        // ---- U = silu([h, magg] @ Wn1 + bn1) -> AS ----
        {
            float a0[4], a1[4];
            #pragma unroll
            for (int r = 0; r < 4; r++) { a0[r] = bn1[l*HH+lane]; a1[r] = bn1[l*HH+lane+32]; }
            #pragma unroll 4
            for (int c = 0; c < HH; c++) {
                const float* wr = Wn1 + (l*128 + c)*HH;
                float w0 = wr[lane], w1 = wr[lane+32];
                #pragma unroll
                for (int r = 0; r < 4; r++) {
                    float hv = hS[(w*4+r)*HS + c];
                    a0[r] += hv*w0; a1[r] += hv*w1;
                }
            }
            #pragma unroll 4
            for (int c = 0; c < HH; c++) {
                const float* wr = Wn1 + (l*128 + 64 + c)*HH;
                float w0 = wr[lane], w1 = wr[lane+32];
                #pragma unroll
                for (int r = 0; r < 4; r++) {
                    float mv = maggS[(w*4+r)*HH + c];
                    a0[r] += mv*w0; a1[r] += mv*w1;
                }
            }
            #pragma unroll
            for (int r = 0; r < 4; r++) {
                AS[(w*4+r)*HS + lane]      = siluf(a0[r]);
                AS[(w*4+r)*HS + lane + 32] = siluf(a1[r]);
            }
        }

        // ---- h += U @ Wn2 + bn2 ----  (warp reads/writes only its own rows)
        {
            float a0[4], a1[4];
            #pragma unroll
            for (int r = 0; r < 4; r++) { a0[r] = bn2[l*HH+lane]; a1[r] = bn2[l*HH+lane+32]; }
            #pragma unroll 4
            for (int c = 0; c < HH; c++) {
                const float* wr = Wn2 + (l*HH + c)*HH;
                float w0 = wr[lane], w1 = wr[lane+32];
                #pragma unroll
                for (int r = 0; r < 4; r++) {
                    float uv = AS[(w*4+r)*HS + c];
                    a0[r] += uv*w0; a1[r] += uv*w1;
                }
            }
            #pragma unroll
            for (int r = 0; r < 4; r++) {
                hS[(w*4+r)*HS + lane]      += a0[r];
                hS[(w*4+r)*HS + lane + 32] += a1[r];
            }
        }
        __syncthreads();
    }

    // ---- output: scale * vel + mean ----
    if (tid < NA*2) {
        int i = tid >> 1, c = tid & 1;
        out[((size_t)g*NA + i)*2 + c] = scl[c]*velS[tid] + mn[c];
    }
}

extern "C" void kernel_launch(void* const* d_in, const int* in_sizes, int n_in,
                              void* d_out, int out_size) {
    const float* obs  = (const float*)d_in[0];
    // d_in[1] = rows, d_in[2] = cols : edge structure is static, not needed
    const float* scl  = (const float*)d_in[3];
    const float* mn   = (const float*)d_in[4];
    const float* embW = (const float*)d_in[5];
    const float* embb = (const float*)d_in[6];
    const float* We1  = (const float*)d_in[7];
    const float* be1  = (const float*)d_in[8];
    const float* We2  = (const float*)d_in[9];
    const float* be2  = (const float*)d_in[10];
    const float* Wc1  = (const float*)d_in[11];
    const float* bc1  = (const float*)d_in[12];
    const float* Wc2  = (const float*)d_in[13];
    const float* bc2  = (const float*)d_in[14];
    const float* Wv1  = (const float*)d_in[15];
    const float* bv1  = (const float*)d_in[16];
    const float* Wv2  = (const float*)d_in[17];
    const float* bv2  = (const float*)d_in[18];
    const float* Wn1  = (const float*)d_in[19];
    const float* bn1  = (const float*)d_in[20];
    const float* Wn2  = (const float*)d_in[21];
    const float* bn2  = (const float*)d_in[22];
    float* out = (float*)d_out;

    int n_nodes = in_sizes[0] / OBSW;
    int groups  = n_nodes / NA;

    cudaFuncSetAttribute(egnn_kernel, cudaFuncAttributeMaxDynamicSharedMemorySize, SMEM_BYTES);
    egnn_kernel<<<groups, 256, SMEM_BYTES>>>(
        obs, scl, mn, embW, embb,
        We1, be1, We2, be2, Wc1, bc1, Wc2, bc2,
        Wv1, bv1, Wv2, bv2, Wn1, bn1, Wn2, bn2, out);
}

// round 2
// speedup vs baseline: 1.6531x; 1.6531x over previous
#include <cuda_runtime.h>

#define NA    32      // agents per group
#define HH    64      // hidden
#define HS    65      // padded smem row stride (conflict-free lane-strided access)
#define NINV  16
#define NLAY  4
#define OBSW  20      // INV + 4

#define SMEM_FLOATS (3*NA*HS + NA*HH + NA*NA + 2*HH*HH + 5*HH + 6*NA)
#define SMEM_BYTES  (SMEM_FLOATS * 4)

typedef unsigned long long ull;

__device__ __forceinline__ float siluf(float x) {
    // fast silu: MUFU.EX2 + MUFU.RCP + FMUL (no IEEE div sequence)
    return __fdividef(x, 1.0f + __expf(-x));
}

__device__ __forceinline__ ull packf2(float x) {
    unsigned int u = __float_as_uint(x);
    ull r;
    asm("mov.b64 %0, {%1, %1};" : "=l"(r) : "r"(u));
    return r;
}

__device__ __forceinline__ void fma2(ull &d, ull a, ull b) {
    asm("fma.rn.f32x2 %0, %1, %2, %0;" : "+l"(d) : "l"(a), "l"(b));
}

__device__ __forceinline__ float2 unpackf2(ull v) {
    unsigned int lo, hi;
    asm("mov.b64 {%0, %1}, %2;" : "=r"(lo), "=r"(hi) : "l"(v));
    return make_float2(__uint_as_float(lo), __uint_as_float(hi));
}

__device__ __forceinline__ float wredsum(float v) {
    v += __shfl_down_sync(0xffffffffu, v, 16);
    v += __shfl_down_sync(0xffffffffu, v, 8);
    v += __shfl_down_sync(0xffffffffu, v, 4);
    v += __shfl_down_sync(0xffffffffu, v, 2);
    v += __shfl_down_sync(0xffffffffu, v, 1);
    return v;
}

// DSTR[64] = silu(SRCR[64] @ WSH[64x64] + BSH[64])
// Packed f32x2: per input channel c -> 8 FFMA2 (16 MACs) + 4 LDS.128 + 1 pack.
#define MLP64P(SRCR, DSTR, WSH, BSH)                                             \
    _Pragma("unroll")                                                            \
    for (int kt = 0; kt < HH; kt += 16) {                                        \
        ull acc0, acc1, acc2, acc3, acc4, acc5, acc6, acc7;                      \
        {                                                                        \
            const ulonglong2* bp = (const ulonglong2*)&BSH[kt];                  \
            ulonglong2 b01 = bp[0], b23 = bp[1], b45 = bp[2], b67 = bp[3];       \
            acc0 = b01.x; acc1 = b01.y; acc2 = b23.x; acc3 = b23.y;              \
            acc4 = b45.x; acc5 = b45.y; acc6 = b67.x; acc7 = b67.y;              \
        }                                                                        \
        _Pragma("unroll")                                                        \
        for (int c = 0; c < HH; c++) {                                           \
            const ulonglong2* wp = (const ulonglong2*)&WSH[c*HH + kt];           \
            ulonglong2 w01 = wp[0], w23 = wp[1];                                 \
            ull mv2 = packf2(SRCR[c]);                                           \
            fma2(acc0, mv2, w01.x); fma2(acc1, mv2, w01.y);                      \
            fma2(acc2, mv2, w23.x); fma2(acc3, mv2, w23.y);                      \
            ulonglong2 w45 = wp[2], w67 = wp[3];                                 \
            fma2(acc4, mv2, w45.x); fma2(acc5, mv2, w45.y);                      \
            fma2(acc6, mv2, w67.x); fma2(acc7, mv2, w67.y);                      \
        }                                                                        \
        float2 f;                                                                \
        f = unpackf2(acc0); DSTR[kt+ 0] = siluf(f.x); DSTR[kt+ 1] = siluf(f.y);  \
        f = unpackf2(acc1); DSTR[kt+ 2] = siluf(f.x); DSTR[kt+ 3] = siluf(f.y);  \
        f = unpackf2(acc2); DSTR[kt+ 4] = siluf(f.x); DSTR[kt+ 5] = siluf(f.y);  \
        f = unpackf2(acc3); DSTR[kt+ 6] = siluf(f.x); DSTR[kt+ 7] = siluf(f.y);  \
        f = unpackf2(acc4); DSTR[kt+ 8] = siluf(f.x); DSTR[kt+ 9] = siluf(f.y);  \
        f = unpackf2(acc5); DSTR[kt+10] = siluf(f.x); DSTR[kt+11] = siluf(f.y);  \
        f = unpackf2(acc6); DSTR[kt+12] = siluf(f.x); DSTR[kt+13] = siluf(f.y);  \
        f = unpackf2(acc7); DSTR[kt+14] = siluf(f.x); DSTR[kt+15] = siluf(f.y);  \
    }

__global__ void __launch_bounds__(256, 1)
egnn_kernel(const float* __restrict__ obs,
            const float* __restrict__ scl,
            const float* __restrict__ mn,
            const float* __restrict__ embW,
            const float* __restrict__ embb,
            const float* __restrict__ We1,
            const float* __restrict__ be1,
            const float* __restrict__ We2,
            const float* __restrict__ be2,
            const float* __restrict__ Wc1,
            const float* __restrict__ bc1,
            const float* __restrict__ Wc2,
            const float* __restrict__ bc2,
            const float* __restrict__ Wv1,
            const float* __restrict__ bv1,
            const float* __restrict__ Wv2,
            const float* __restrict__ bv2,
            const float* __restrict__ Wn1,
            const float* __restrict__ bn1,
            const float* __restrict__ Wn2,
            const float* __restrict__ bn2,
            float* __restrict__ out)
{
    extern __shared__ float sm[];
    float* hS    = sm;                 // [NA][HS]
    float* AS    = hS    + NA*HS;      // [NA][HS]  A = h@We1[:64]+be1 ; reused as U
    float* BS    = AS    + NA*HS;      // [NA][HS]  B = h@We1[64:128] ; also obs staging
    float* maggS = BS    + NA*HS;      // [NA][HH]
    float* eaS   = maggS + NA*HH;      // [NA][NA]
    float* We2s  = eaS   + NA*NA;      // [HH*HH]
    float* Wc1s  = We2s  + HH*HH;      // [HH*HH]
    float* w128s = Wc1s  + HH*HH;      // [HH]
    float* w129s = w128s + HH;         // [HH]
    float* be2s  = w129s + HH;         // [HH]
    float* bc1s  = be2s  + HH;         // [HH]
    float* Wc2s  = bc1s  + HH;         // [HH]
    float* locS  = Wc2s  + HH;         // [NA*2]
    float* velS  = locS  + NA*2;       // [NA*2]
    float* aggS  = velS  + NA*2;       // [NA*2]

    const int tid  = threadIdx.x;
    const int w    = tid >> 5;         // warp id (0..7)
    const int lane = tid & 31;
    const int g    = blockIdx.x;

    // ---- stage obs for this group into BS scratch ----
    const float* obsg = obs + (size_t)g * NA * OBSW;
    for (int t = tid; t < NA*OBSW; t += 256) BS[t] = obsg[t];
    __syncthreads();

    if (tid < NA*2) {
        int i = tid >> 1, c = tid & 1;
        locS[tid] = BS[i*OBSW + NINV + c];
        velS[tid] = BS[i*OBSW + NINV + 2 + c];
    }
    __syncthreads();

    // edge_attr from INITIAL loc (stop_gradient term)
    for (int p = tid; p < NA*NA; p += 256) {
        int i = p >> 5, j = p & 31;
        float dx = locS[i*2+0] - locS[j*2+0];
        float dy = locS[i*2+1] - locS[j*2+1];
        eaS[p] = dx*dx + dy*dy;
    }

    // h = inv @ embW + embb   (warp w owns rows 4w..4w+3; lane owns cols lane, lane+32)
    {
        float a0[4], a1[4];
        #pragma unroll
        for (int r = 0; r < 4; r++) { a0[r] = embb[lane]; a1[r] = embb[lane+32]; }
        #pragma unroll
        for (int c = 0; c < NINV; c++) {
            float w0 = embW[c*HH + lane];
            float w1 = embW[c*HH + lane + 32];
            #pragma unroll
            for (int r = 0; r < 4; r++) {
                float iv = BS[(w*4+r)*OBSW + c];
                a0[r] += iv*w0; a1[r] += iv*w1;
            }
        }
        #pragma unroll
        for (int r = 0; r < 4; r++) {
            hS[(w*4+r)*HS + lane]      = a0[r];
            hS[(w*4+r)*HS + lane + 32] = a1[r];
        }
    }
    __syncthreads();

    #pragma unroll 1
    for (int l = 0; l < NLAY; l++) {
        // ---- stage hot per-layer weights into smem ----
        const float* We2l = We2 + l*HH*HH;
        const float* Wc1l = Wc1 + l*HH*HH;
        for (int t = tid; t < HH*HH; t += 256) {
            We2s[t] = We2l[t];
            Wc1s[t] = Wc1l[t];
        }
        if (tid < HH) {
            w128s[tid] = We1[(l*130 + 128)*HH + tid];
            w129s[tid] = We1[(l*130 + 129)*HH + tid];
            be2s[tid]  = be2[l*HH + tid];
            bc1s[tid]  = bc1[l*HH + tid];
            Wc2s[tid]  = Wc2[l*HH + tid];
        }

        // ---- node projections: A = h@We1[:64]+be1, B = h@We1[64:128] ----
        {
            float a0[4], a1[4], b0[4], b1[4];
            #pragma unroll
            for (int r = 0; r < 4; r++) {
                a0[r] = be1[l*HH + lane]; a1[r] = be1[l*HH + lane + 32];
                b0[r] = 0.f; b1[r] = 0.f;
            }
            #pragma unroll 4
            for (int c = 0; c < HH; c++) {
                const float* wrA = We1 + (l*130 + c)*HH;
                const float* wrB = We1 + (l*130 + 64 + c)*HH;
                float wa0 = wrA[lane], wa1 = wrA[lane+32];
                float wb0 = wrB[lane], wb1 = wrB[lane+32];
                #pragma unroll
                for (int r = 0; r < 4; r++) {
                    float hv = hS[(w*4+r)*HS + c];
                    a0[r] += hv*wa0; a1[r] += hv*wa1;
                    b0[r] += hv*wb0; b1[r] += hv*wb1;
                }
            }
            #pragma unroll
            for (int r = 0; r < 4; r++) {
                AS[(w*4+r)*HS + lane]      = a0[r];
                AS[(w*4+r)*HS + lane + 32] = a1[r];
                BS[(w*4+r)*HS + lane]      = b0[r];
                BS[(w*4+r)*HS + lane + 32] = b1[r];
            }
        }
        __syncthreads();

        // ---- edge phase: warp = receiver i, lane = sender j ----
        #pragma unroll 1
        for (int ib = 0; ib < 4; ib++) {
            const int i = ib*8 + w;
            const int j = lane;
            float dx = locS[i*2+0] - locS[j*2+0];
            float dy = locS[i*2+1] - locS[j*2+1];
            float radial = dx*dx + dy*dy;
            float invr = __fdividef(1.0f, sqrtf(radial) + 1.0f);
            float dnx = dx * invr, dny = dy * invr;
            float eav = eaS[i*NA + j];

            float m1r[HH], m2r[HH];
            #pragma unroll
            for (int k = 0; k < HH; k++) {
                float v = AS[i*HS + k] + BS[j*HS + k]
                        + radial * w128s[k] + eav * w129s[k];
                m1r[k] = siluf(v);
            }

            MLP64P(m1r, m2r, We2s, be2s);   // m2 = silu(m1@We2+be2)  (this is "m")
            MLP64P(m2r, m1r, Wc1s, bc1s);   // t  = silu(m2@Wc1+bc1) -> reuse m1r

            float cs = bc2[l];
            #pragma unroll
            for (int k = 0; k < HH; k++) cs += m1r[k] * Wc2s[k];

            float vm = (j == i) ? 0.0f : 1.0f;
            float tx = wredsum(vm * dnx * cs);
            float ty = wredsum(vm * dny * cs);
            if (lane == 0) { aggS[i*2+0] = tx; aggS[i*2+1] = ty; }

            #pragma unroll
            for (int k = 0; k < HH; k++) {
                float v = wredsum(vm * m2r[k]);
                if (lane == 0) maggS[i*HH + k] = v;
            }
        }
        __syncthreads();

        // ---- node phase: phi_v, vel/loc update ----
        {
            float a0[4], a1[4];
            #pragma unroll
            for (int r = 0; r < 4; r++) { a0[r] = bv1[l*HH+lane]; a1[r] = bv1[l*HH+lane+32]; }
            #pragma unroll 4
            for (int c = 0; c < HH; c++) {
                const float* wr = Wv1 + (l*HH + c)*HH;
                float w0 = wr[lane], w1 = wr[lane+32];
                #pragma unroll
                for (int r = 0; r < 4; r++) {
                    float hv = hS[(w*4+r)*HS + c];
                    a0[r] += hv*w0; a1[r] += hv*w1;
                }
            }
            float wv2a = Wv2[l*HH + lane], wv2b = Wv2[l*HH + lane + 32];
            #pragma unroll
            for (int r = 0; r < 4; r++) {
                float part = wredsum(siluf(a0[r])*wv2a + siluf(a1[r])*wv2b);
                if (lane == 0) {
                    int i = w*4 + r;
                    float phi = part + bv2[l];
                    float vx = phi*velS[i*2+0] + aggS[i*2+0]*(1.0f/31.0f);
                    float vy = phi*velS[i*2+1] + aggS[i*2+1]*(1.0f/31.0f);
                    velS[i*2+0] = vx; velS[i*2+1] = vy;
                    locS[i*2+0] += vx; locS[i*2+1] += vy;
                }
            }
        }

        // ---- U = silu([h, magg] @ Wn1 + bn1) -> AS ----
        {
            float a0[4], a1[4];
            #pragma unroll
            for (int r = 0; r < 4; r++) { a0[r] = bn1[l*HH+lane]; a1[r] = bn1[l*HH+lane+32]; }
            #pragma unroll 4
            for (int c = 0; c < HH; c++) {
                const float* wr = Wn1 + (l*128 + c)*HH;
                float w0 = wr[lane], w1 = wr[lane+32];
                #pragma unroll
                for (int r = 0; r < 4; r++) {
                    float hv = hS[(w*4+r)*HS + c];
                    a0[r] += hv*w0; a1[r] += hv*w1;
                }
            }
            #pragma unroll 4
            for (int c = 0; c < HH; c++) {
                const float* wr = Wn1 + (l*128 + 64 + c)*HH;
                float w0 = wr[lane], w1 = wr[lane+32];
                #pragma unroll
                for (int r = 0; r < 4; r++) {
                    float mv = maggS[(w*4+r)*HH + c];
                    a0[r] += mv*w0; a1[r] += mv*w1;
                }
            }
            #pragma unroll
            for (int r = 0; r < 4; r++) {
                AS[(w*4+r)*HS + lane]      = siluf(a0[r]);
                AS[(w*4+r)*HS + lane + 32] = siluf(a1[r]);
            }
        }

        // ---- h += U @ Wn2 + bn2 ----  (warp reads/writes only its own rows)
        {
            float a0[4], a1[4];
            #pragma unroll
            for (int r = 0; r < 4; r++) { a0[r] = bn2[l*HH+lane]; a1[r] = bn2[l*HH+lane+32]; }
            #pragma unroll 4
            for (int c = 0; c < HH; c++) {
                const float* wr = Wn2 + (l*HH + c)*HH;
                float w0 = wr[lane], w1 = wr[lane+32];
                #pragma unroll
                for (int r = 0; r < 4; r++) {
                    float uv = AS[(w*4+r)*HS + c];
                    a0[r] += uv*w0; a1[r] += uv*w1;
                }
            }
            #pragma unroll
            for (int r = 0; r < 4; r++) {
                hS[(w*4+r)*HS + lane]      += a0[r];
                hS[(w*4+r)*HS + lane + 32] += a1[r];
            }
        }
        __syncthreads();
    }

    // ---- output: scale * vel + mean ----
    if (tid < NA*2) {
        int i = tid >> 1, c = tid & 1;
        out[((size_t)g*NA + i)*2 + c] = scl[c]*velS[tid] + mn[c];
    }
}

extern "C" void kernel_launch(void* const* d_in, const int* in_sizes, int n_in,
                              void* d_out, int out_size) {
    const float* obs  = (const float*)d_in[0];
    // d_in[1] = rows, d_in[2] = cols : edge structure is static, not needed
    const float* scl  = (const float*)d_in[3];
    const float* mn   = (const float*)d_in[4];
    const float* embW = (const float*)d_in[5];
    const float* embb = (const float*)d_in[6];
    const float* We1  = (const float*)d_in[7];
    const float* be1  = (const float*)d_in[8];
    const float* We2  = (const float*)d_in[9];
    const float* be2  = (const float*)d_in[10];
    const float* Wc1  = (const float*)d_in[11];
    const float* bc1  = (const float*)d_in[12];
    const float* Wc2  = (const float*)d_in[13];
    const float* bc2  = (const float*)d_in[14];
    const float* Wv1  = (const float*)d_in[15];
    const float* bv1  = (const float*)d_in[16];
    const float* Wv2  = (const float*)d_in[17];
    const float* bv2  = (const float*)d_in[18];
    const float* Wn1  = (const float*)d_in[19];
    const float* bn1  = (const float*)d_in[20];
    const float* Wn2  = (const float*)d_in[21];
    const float* bn2  = (const float*)d_in[22];
    float* out = (float*)d_out;

    int n_nodes = in_sizes[0] / OBSW;
    int groups  = n_nodes / NA;

    cudaFuncSetAttribute(egnn_kernel, cudaFuncAttributeMaxDynamicSharedMemorySize, SMEM_BYTES);
    egnn_kernel<<<groups, 256, SMEM_BYTES>>>(
        obs, scl, mn, embW, embb,
        We1, be1, We2, be2, Wc1, bc1, Wc2, bc2,
        Wv1, bv1, Wv2, bv2, Wn1, bn1, Wn2, bn2, out);
}

// round 3
// speedup vs baseline: 2.4709x; 1.4947x over previous
#include <cuda_runtime.h>

#define NA    32      // agents per group
#define HH    64      // hidden
#define HS    65      // padded smem row stride (conflict-free lane-strided access)
#define NINV  16
#define NLAY  4
#define OBSW  20      // INV + 4

#define SMEM_FLOATS (3*NA*HS + NA*HH + NA*NA + 8*HH*HH + 10*HH + 6*NA)
#define SMEM_BYTES  (SMEM_FLOATS * 4)

typedef unsigned long long ull;

__device__ __forceinline__ float siluf(float x) {
    // silu(x) = x * sigmoid(x) = hx*tanh(hx) + hx, hx = x/2.  1 MUFU.TANH + FMUL + FFMA.
    float hx = 0.5f * x;
    float t;
    asm("tanh.approx.f32 %0, %1;" : "=f"(t) : "f"(hx));
    return fmaf(hx, t, hx);
}

__device__ __forceinline__ ull packf2(float x) {
    unsigned int u = __float_as_uint(x);
    ull r;
    asm("mov.b64 %0, {%1, %1};" : "=l"(r) : "r"(u));
    return r;
}

__device__ __forceinline__ void fma2(ull &d, ull a, ull b) {
    asm("fma.rn.f32x2 %0, %1, %2, %0;" : "+l"(d) : "l"(a), "l"(b));
}

__device__ __forceinline__ float2 unpackf2(ull v) {
    unsigned int lo, hi;
    asm("mov.b64 {%0, %1}, %2;" : "=r"(lo), "=r"(hi) : "l"(v));
    return make_float2(__uint_as_float(lo), __uint_as_float(hi));
}

__device__ __forceinline__ float wredsum(float v) {
    v += __shfl_down_sync(0xffffffffu, v, 16);
    v += __shfl_down_sync(0xffffffffu, v, 8);
    v += __shfl_down_sync(0xffffffffu, v, 4);
    v += __shfl_down_sync(0xffffffffu, v, 2);
    v += __shfl_down_sync(0xffffffffu, v, 1);
    return v;
}

// DSTR[64] = silu(SRCR[64] @ WSH[64x64] + BSH[64])
// Packed f32x2: per input channel c -> 8 FFMA2 (16 MACs) + 4 LDS.128 + 1 pack.
#define MLP64P(SRCR, DSTR, WSH, BSH)                                             \
    _Pragma("unroll")                                                            \
    for (int kt = 0; kt < HH; kt += 16) {                                        \
        ull acc0, acc1, acc2, acc3, acc4, acc5, acc6, acc7;                      \
        {                                                                        \
            const ulonglong2* bp = (const ulonglong2*)&BSH[kt];                  \
            ulonglong2 b01 = bp[0], b23 = bp[1], b45 = bp[2], b67 = bp[3];       \
            acc0 = b01.x; acc1 = b01.y; acc2 = b23.x; acc3 = b23.y;              \
            acc4 = b45.x; acc5 = b45.y; acc6 = b67.x; acc7 = b67.y;              \
        }                                                                        \
        _Pragma("unroll")                                                        \
        for (int c = 0; c < HH; c++) {                                           \
            const ulonglong2* wp = (const ulonglong2*)&WSH[c*HH + kt];           \
            ulonglong2 w01 = wp[0], w23 = wp[1];                                 \
            ull mv2 = packf2(SRCR[c]);                                           \
            fma2(acc0, mv2, w01.x); fma2(acc1, mv2, w01.y);                      \
            fma2(acc2, mv2, w23.x); fma2(acc3, mv2, w23.y);                      \
            ulonglong2 w45 = wp[2], w67 = wp[3];                                 \
            fma2(acc4, mv2, w45.x); fma2(acc5, mv2, w45.y);                      \
            fma2(acc6, mv2, w67.x); fma2(acc7, mv2, w67.y);                      \
        }                                                                        \
        float2 f;                                                                \
        f = unpackf2(acc0); DSTR[kt+ 0] = siluf(f.x); DSTR[kt+ 1] = siluf(f.y);  \
        f = unpackf2(acc1); DSTR[kt+ 2] = siluf(f.x); DSTR[kt+ 3] = siluf(f.y);  \
        f = unpackf2(acc2); DSTR[kt+ 4] = siluf(f.x); DSTR[kt+ 5] = siluf(f.y);  \
        f = unpackf2(acc3); DSTR[kt+ 6] = siluf(f.x); DSTR[kt+ 7] = siluf(f.y);  \
        f = unpackf2(acc4); DSTR[kt+ 8] = siluf(f.x); DSTR[kt+ 9] = siluf(f.y);  \
        f = unpackf2(acc5); DSTR[kt+10] = siluf(f.x); DSTR[kt+11] = siluf(f.y);  \
        f = unpackf2(acc6); DSTR[kt+12] = siluf(f.x); DSTR[kt+13] = siluf(f.y);  \
        f = unpackf2(acc7); DSTR[kt+14] = siluf(f.x); DSTR[kt+15] = siluf(f.y);  \
    }

__global__ void __launch_bounds__(256, 1)
egnn_kernel(const float* __restrict__ obs,
            const float* __restrict__ scl,
            const float* __restrict__ mn,
            const float* __restrict__ embW,
            const float* __restrict__ embb,
            const float* __restrict__ We1,
            const float* __restrict__ be1,
            const float* __restrict__ We2,
            const float* __restrict__ be2,
            const float* __restrict__ Wc1,
            const float* __restrict__ bc1,
            const float* __restrict__ Wc2,
            const float* __restrict__ bc2,
            const float* __restrict__ Wv1,
            const float* __restrict__ bv1,
            const float* __restrict__ Wv2,
            const float* __restrict__ bv2,
            const float* __restrict__ Wn1,
            const float* __restrict__ bn1,
            const float* __restrict__ Wn2,
            const float* __restrict__ bn2,
            float* __restrict__ out)
{
    extern __shared__ float sm[];
    float* hS    = sm;                 // [NA][HS]
    float* AS    = hS    + NA*HS;      // [NA][HS]  A = h@We1[:64]+be1 ; reused as U
    float* BS    = AS    + NA*HS;      // [NA][HS]  B = h@We1[64:128] ; also obs staging
    float* maggS = BS    + NA*HS;      // [NA][HH]
    float* eaS   = maggS + NA*HH;      // [NA][NA]
    float* We2s  = eaS   + NA*NA;      // [HH*HH]
    float* Wc1s  = We2s  + HH*HH;      // [HH*HH]
    float* We1As = Wc1s  + HH*HH;      // [HH*HH]  We1[l][0:64]
    float* We1Bs = We1As + HH*HH;      // [HH*HH]  We1[l][64:128]
    float* Wv1s  = We1Bs + HH*HH;      // [HH*HH]
    float* Wn2s  = Wv1s  + HH*HH;      // [HH*HH]
    float* Wn1s  = Wn2s  + HH*HH;      // [2*HH*HH]
    float* w128s = Wn1s  + 2*HH*HH;    // [HH]
    float* w129s = w128s + HH;         // [HH]
    float* be2s  = w129s + HH;         // [HH]
    float* bc1s  = be2s  + HH;         // [HH]
    float* Wc2s  = bc1s  + HH;         // [HH]
    float* be1s  = Wc2s  + HH;         // [HH]
    float* bv1s  = be1s  + HH;         // [HH]
    float* bn1s  = bv1s  + HH;         // [HH]
    float* bn2s  = bn1s  + HH;         // [HH]
    float* Wv2s  = bn2s  + HH;         // [HH]
    float* locS  = Wv2s  + HH;         // [NA*2]
    float* velS  = locS  + NA*2;       // [NA*2]
    float* aggS  = velS  + NA*2;       // [NA*2]

    const int tid  = threadIdx.x;
    const int w    = tid >> 5;         // warp id (0..7)
    const int lane = tid & 31;
    const int g    = blockIdx.x;

    // ---- stage obs for this group into BS scratch ----
    const float* obsg = obs + (size_t)g * NA * OBSW;
    for (int t = tid; t < NA*OBSW; t += 256) BS[t] = obsg[t];
    __syncthreads();

    if (tid < NA*2) {
        int i = tid >> 1, c = tid & 1;
        locS[tid] = BS[i*OBSW + NINV + c];
        velS[tid] = BS[i*OBSW + NINV + 2 + c];
    }
    __syncthreads();

    // edge_attr from INITIAL loc (stop_gradient term)
    for (int p = tid; p < NA*NA; p += 256) {
        int i = p >> 5, j = p & 31;
        float dx = locS[i*2+0] - locS[j*2+0];
        float dy = locS[i*2+1] - locS[j*2+1];
        eaS[p] = dx*dx + dy*dy;
    }

    // h = inv @ embW + embb   (warp w owns rows 4w..4w+3; lane owns cols lane, lane+32)
    {
        float a0[4], a1[4];
        #pragma unroll
        for (int r = 0; r < 4; r++) { a0[r] = embb[lane]; a1[r] = embb[lane+32]; }
        #pragma unroll
        for (int c = 0; c < NINV; c++) {
            float w0 = embW[c*HH + lane];
            float w1 = embW[c*HH + lane + 32];
            #pragma unroll
            for (int r = 0; r < 4; r++) {
                float iv = BS[(w*4+r)*OBSW + c];
                a0[r] += iv*w0; a1[r] += iv*w1;
            }
        }
        #pragma unroll
        for (int r = 0; r < 4; r++) {
            hS[(w*4+r)*HS + lane]      = a0[r];
            hS[(w*4+r)*HS + lane + 32] = a1[r];
        }
    }
    __syncthreads();

    #pragma unroll 1
    for (int l = 0; l < NLAY; l++) {
        // ---- stage ALL per-layer weights into smem (float4 vectorized) ----
        {
            const float4* We2l  = (const float4*)(We2 + l*HH*HH);
            const float4* Wc1l  = (const float4*)(Wc1 + l*HH*HH);
            const float4* We1l  = (const float4*)(We1 + l*130*HH);
            const float4* Wv1l  = (const float4*)(Wv1 + l*HH*HH);
            const float4* Wn2l  = (const float4*)(Wn2 + l*HH*HH);
            const float4* Wn1l  = (const float4*)(Wn1 + l*2*HH*HH);
            float4* We2s4  = (float4*)We2s;
            float4* Wc1s4  = (float4*)Wc1s;
            float4* We1As4 = (float4*)We1As;
            float4* We1Bs4 = (float4*)We1Bs;
            float4* Wv1s4  = (float4*)Wv1s;
            float4* Wn2s4  = (float4*)Wn2s;
            float4* Wn1s4  = (float4*)Wn1s;
            #pragma unroll
            for (int t = tid; t < HH*HH/4; t += 256) {
                We2s4[t]  = We2l[t];
                Wc1s4[t]  = Wc1l[t];
                We1As4[t] = We1l[t];
                We1Bs4[t] = We1l[t + HH*HH/4];
                Wv1s4[t]  = Wv1l[t];
                Wn2s4[t]  = Wn2l[t];
            }
            #pragma unroll
            for (int t = tid; t < 2*HH*HH/4; t += 256) Wn1s4[t] = Wn1l[t];
            if (tid < HH) {
                w128s[tid] = We1[(l*130 + 128)*HH + tid];
                w129s[tid] = We1[(l*130 + 129)*HH + tid];
                be2s[tid]  = be2[l*HH + tid];
                bc1s[tid]  = bc1[l*HH + tid];
                Wc2s[tid]  = Wc2[l*HH + tid];
                be1s[tid]  = be1[l*HH + tid];
                bv1s[tid]  = bv1[l*HH + tid];
                bn1s[tid]  = bn1[l*HH + tid];
                bn2s[tid]  = bn2[l*HH + tid];
                Wv2s[tid]  = Wv2[l*HH + tid];
            }
        }
        const float bc2l = bc2[l];
        const float bv2l = bv2[l];
        __syncthreads();

        // ---- node projections: A = h@We1[:64]+be1, B = h@We1[64:128] ----
        {
            float a0[4], a1[4], b0[4], b1[4];
            #pragma unroll
            for (int r = 0; r < 4; r++) {
                a0[r] = be1s[lane]; a1[r] = be1s[lane + 32];
                b0[r] = 0.f; b1[r] = 0.f;
            }
            #pragma unroll 4
            for (int c = 0; c < HH; c++) {
                const float* wrA = We1As + c*HH;
                const float* wrB = We1Bs + c*HH;
                float wa0 = wrA[lane], wa1 = wrA[lane+32];
                float wb0 = wrB[lane], wb1 = wrB[lane+32];
                #pragma unroll
                for (int r = 0; r < 4; r++) {
                    float hv = hS[(w*4+r)*HS + c];
                    a0[r] += hv*wa0; a1[r] += hv*wa1;
                    b0[r] += hv*wb0; b1[r] += hv*wb1;
                }
            }
            #pragma unroll
            for (int r = 0; r < 4; r++) {
                AS[(w*4+r)*HS + lane]      = a0[r];
                AS[(w*4+r)*HS + lane + 32] = a1[r];
                BS[(w*4+r)*HS + lane]      = b0[r];
                BS[(w*4+r)*HS + lane + 32] = b1[r];
            }
        }
        __syncthreads();

        // ---- edge phase: warp = receiver i, lane = sender j ----
        #pragma unroll 1
        for (int ib = 0; ib < 4; ib++) {
            const int i = ib*8 + w;
            const int j = lane;
            float dx = locS[i*2+0] - locS[j*2+0];
            float dy = locS[i*2+1] - locS[j*2+1];
            float radial = dx*dx + dy*dy;
            float invr = __fdividef(1.0f, sqrtf(radial) + 1.0f);
            float dnx = dx * invr, dny = dy * invr;
            float eav = eaS[i*NA + j];

            float m1r[HH], m2r[HH];
            #pragma unroll
            for (int k = 0; k < HH; k++) {
                float v = AS[i*HS + k] + BS[j*HS + k]
                        + radial * w128s[k] + eav * w129s[k];
                m1r[k] = siluf(v);
            }

            MLP64P(m1r, m2r, We2s, be2s);   // m2 = silu(m1@We2+be2)  (this is "m")
            MLP64P(m2r, m1r, Wc1s, bc1s);   // t  = silu(m2@Wc1+bc1) -> reuse m1r

            // cs = t . Wc2 + bc2  (4 parallel chains)
            float cs0 = bc2l, cs1 = 0.f, cs2 = 0.f, cs3 = 0.f;
            #pragma unroll
            for (int k = 0; k < HH; k += 4) {
                cs0 += m1r[k+0] * Wc2s[k+0];
                cs1 += m1r[k+1] * Wc2s[k+1];
                cs2 += m1r[k+2] * Wc2s[k+2];
                cs3 += m1r[k+3] * Wc2s[k+3];
            }
            float cs = (cs0 + cs1) + (cs2 + cs3);

            float vm = (j == i) ? 0.0f : 1.0f;
            float tx = wredsum(vm * dnx * cs);
            float ty = wredsum(vm * dny * cs);
            if (lane == 0) { aggS[i*2+0] = tx; aggS[i*2+1] = ty; }

            // magg: recursive-halving reduction of m2r over lanes.
            // After 5 stages, lane l holds channel sums for channels 2l, 2l+1.
            #pragma unroll
            for (int k = 0; k < HH; k++) m2r[k] *= vm;
            #pragma unroll
            for (int s = 0; s < 5; s++) {
                const int mask = 16 >> s;
                const int half = 32 >> s;
                const bool up = (lane & mask) != 0;
                #pragma unroll
                for (int k = 0; k < half; k++) {
                    float send = up ? m2r[k] : m2r[k + half];
                    float recv = __shfl_xor_sync(0xffffffffu, send, mask);
                    m2r[k] = (up ? m2r[k + half] : m2r[k]) + recv;
                }
            }
            ((float2*)(maggS + i*HH))[lane] = make_float2(m2r[0], m2r[1]);
        }
        __syncthreads();

        // ---- node phase: phi_v, vel/loc update ----
        {
            float a0[4], a1[4];
            #pragma unroll
            for (int r = 0; r < 4; r++) { a0[r] = bv1s[lane]; a1[r] = bv1s[lane+32]; }
            #pragma unroll 4
            for (int c = 0; c < HH; c++) {
                const float* wr = Wv1s + c*HH;
                float w0 = wr[lane], w1 = wr[lane+32];
                #pragma unroll
                for (int r = 0; r < 4; r++) {
                    float hv = hS[(w*4+r)*HS + c];
                    a0[r] += hv*w0; a1[r] += hv*w1;
                }
            }
            float wv2a = Wv2s[lane], wv2b = Wv2s[lane + 32];
            #pragma unroll
            for (int r = 0; r < 4; r++) {
                float part = wredsum(siluf(a0[r])*wv2a + siluf(a1[r])*wv2b);
                if (lane == 0) {
                    int i = w*4 + r;
                    float phi = part + bv2l;
                    float vx = phi*velS[i*2+0] + aggS[i*2+0]*(1.0f/31.0f);
                    float vy = phi*velS[i*2+1] + aggS[i*2+1]*(1.0f/31.0f);
                    velS[i*2+0] = vx; velS[i*2+1] = vy;
                    locS[i*2+0] += vx; locS[i*2+1] += vy;
                }
            }
        }

        // ---- U = silu([h, magg] @ Wn1 + bn1) -> AS ----
        {
            float a0[4], a1[4];
            #pragma unroll
            for (int r = 0; r < 4; r++) { a0[r] = bn1s[lane]; a1[r] = bn1s[lane+32]; }
            #pragma unroll 4
            for (int c = 0; c < HH; c++) {
                const float* wr = Wn1s + c*HH;
                float w0 = wr[lane], w1 = wr[lane+32];
                #pragma unroll
                for (int r = 0; r < 4; r++) {
                    float hv = hS[(w*4+r)*HS + c];
                    a0[r] += hv*w0; a1[r] += hv*w1;
                }
            }
            #pragma unroll 4
            for (int c = 0; c < HH; c++) {
                const float* wr = Wn1s + (HH + c)*HH;
                float w0 = wr[lane], w1 = wr[lane+32];
                #pragma unroll
                for (int r = 0; r < 4; r++) {
                    float mv = maggS[(w*4+r)*HH + c];
                    a0[r] += mv*w0; a1[r] += mv*w1;
                }
            }
            #pragma unroll
            for (int r = 0; r < 4; r++) {
                AS[(w*4+r)*HS + lane]      = siluf(a0[r]);
                AS[(w*4+r)*HS + lane + 32] = siluf(a1[r]);
            }
        }

        // ---- h += U @ Wn2 + bn2 ----  (warp reads/writes only its own rows)
        {
            float a0[4], a1[4];
            #pragma unroll
            for (int r = 0; r < 4; r++) { a0[r] = bn2s[lane]; a1[r] = bn2s[lane+32]; }
            #pragma unroll 4
            for (int c = 0; c < HH; c++) {
                const float* wr = Wn2s + c*HH;
                float w0 = wr[lane], w1 = wr[lane+32];
                #pragma unroll
                for (int r = 0; r < 4; r++) {
                    float uv = AS[(w*4+r)*HS + c];
                    a0[r] += uv*w0; a1[r] += uv*w1;
                }
            }
            #pragma unroll
            for (int r = 0; r < 4; r++) {
                hS[(w*4+r)*HS + lane]      += a0[r];
                hS[(w*4+r)*HS + lane + 32] += a1[r];
            }
        }
        __syncthreads();
    }

    // ---- output: scale * vel + mean ----
    if (tid < NA*2) {
        int i = tid >> 1, c = tid & 1;
        out[((size_t)g*NA + i)*2 + c] = scl[c]*velS[tid] + mn[c];
    }
}

extern "C" void kernel_launch(void* const* d_in, const int* in_sizes, int n_in,
                              void* d_out, int out_size) {
    const float* obs  = (const float*)d_in[0];
    // d_in[1] = rows, d_in[2] = cols : edge structure is static, not needed
    const float* scl  = (const float*)d_in[3];
    const float* mn   = (const float*)d_in[4];
    const float* embW = (const float*)d_in[5];
    const float* embb = (const float*)d_in[6];
    const float* We1  = (const float*)d_in[7];
    const float* be1  = (const float*)d_in[8];
    const float* We2  = (const float*)d_in[9];
    const float* be2  = (const float*)d_in[10];
    const float* Wc1  = (const float*)d_in[11];
    const float* bc1  = (const float*)d_in[12];
    const float* Wc2  = (const float*)d_in[13];
    const float* bc2  = (const float*)d_in[14];
    const float* Wv1  = (const float*)d_in[15];
    const float* bv1  = (const float*)d_in[16];
    const float* Wv2  = (const float*)d_in[17];
    const float* bv2  = (const float*)d_in[18];
    const float* Wn1  = (const float*)d_in[19];
    const float* bn1  = (const float*)d_in[20];
    const float* Wn2  = (const float*)d_in[21];
    const float* bn2  = (const float*)d_in[22];
    float* out = (float*)d_out;

    int n_nodes = in_sizes[0] / OBSW;
    int groups  = n_nodes / NA;

    cudaFuncSetAttribute(egnn_kernel, cudaFuncAttributeMaxDynamicSharedMemorySize, SMEM_BYTES);
    egnn_kernel<<<groups, 256, SMEM_BYTES>>>(
        obs, scl, mn, embW, embb,
        We1, be1, We2, be2, Wc1, bc1, Wc2, bc2,
        Wv1, bv1, Wv2, bv2, Wn1, bn1, Wn2, bn2, out);
}

// round 4
// speedup vs baseline: 2.7678x; 1.1202x over previous
#include <cuda_runtime.h>

#define NA    32
#define HH    64
#define HS    65      // h/A/B row stride
#define MT    260     // m1T/m2T row stride (mult of 4 for float4 alignment)
#define NINV  16
#define NLAY  4
#define OBSW  20

// ---- smem layout (float offsets) ----
#define SM_H     0
#define SM_A     (SM_H    + NA*HS)
#define SM_B     (SM_A    + NA*HS)
#define SM_MAGG  (SM_B    + NA*HS)
#define SM_EA    (SM_MAGG + NA*HH)
#define SM_WE2   (SM_EA   + NA*NA)
#define SM_WC1   (SM_WE2  + HH*HH)
#define SM_M1    (SM_WC1  + HH*HH)
#define SM_M2    (SM_M1   + HH*MT)
#define SM_VEC   (SM_M2   + HH*MT)   // 10 x 64 vectors
#define SM_LOC   (SM_VEC  + 10*HH)
#define SM_VEL   (SM_LOC  + 2*NA)
#define SM_AGG   (SM_VEL  + 2*NA)
#define SM_DNX   (SM_AGG  + 2*NA)
#define SM_DNY   (SM_DNX  + 256)
#define SM_CS    (SM_DNY  + 256)
#define SMEM_FLOATS (SM_CS + 256)
#define SMEM_BYTES  (SMEM_FLOATS * 4)

// vector slots in SM_VEC
#define V_W128 0
#define V_W129 1
#define V_BE1  2
#define V_BE2  3
#define V_BC1  4
#define V_WC2  5
#define V_BV1  6
#define V_BN1  7
#define V_BN2  8
#define V_WV2  9

typedef unsigned long long ull;

__device__ __forceinline__ float siluf(float x) {
    float hx = 0.5f * x;
    float t;
    asm("tanh.approx.f32 %0, %1;" : "=f"(t) : "f"(hx));
    return fmaf(hx, t, hx);
}

__device__ __forceinline__ ull packf2(float x) {
    unsigned int u = __float_as_uint(x);
    ull r;
    asm("mov.b64 %0, {%1, %1};" : "=l"(r) : "r"(u));
    return r;
}

__device__ __forceinline__ void fma2(ull &d, ull a, ull b) {
    asm("fma.rn.f32x2 %0, %1, %2, %0;" : "+l"(d) : "l"(a), "l"(b));
}

__device__ __forceinline__ float2 unpackf2(ull v) {
    unsigned int lo, hi;
    asm("mov.b64 {%0, %1}, %2;" : "=r"(lo), "=r"(hi) : "l"(v));
    return make_float2(__uint_as_float(lo), __uint_as_float(hi));
}

__device__ __forceinline__ float wredsum(float v) {
    v += __shfl_down_sync(0xffffffffu, v, 16);
    v += __shfl_down_sync(0xffffffffu, v, 8);
    v += __shfl_down_sync(0xffffffffu, v, 4);
    v += __shfl_down_sync(0xffffffffu, v, 2);
    v += __shfl_down_sync(0xffffffffu, v, 1);
    return v;
}

// Warp-tiled GEMM: 32 edges x 64 outputs, K=64.
// sp = src + eBase + eg*8 (activations, [k][edge] layout stride MT)
// wp = W + og*8          (weights, [k][out] row-major stride HH)
// acc[e][p] = f32x2 pair {out(8og+2p), out(8og+2p+1)} for edge 8eg+e.
__device__ __forceinline__ void wgemm64(const float* __restrict__ sp,
                                        const float* __restrict__ wp,
                                        const float* __restrict__ bias,
                                        int og, ull (&acc)[8][4])
{
    ulonglong2 b01 = *(const ulonglong2*)(bias + og*8);
    ulonglong2 b23 = *(const ulonglong2*)(bias + og*8 + 4);
    #pragma unroll
    for (int e = 0; e < 8; e++) {
        acc[e][0] = b01.x; acc[e][1] = b01.y; acc[e][2] = b23.x; acc[e][3] = b23.y;
    }
    #pragma unroll 16
    for (int k = 0; k < HH; k++) {
        float4 a0 = *(const float4*)(sp + k*MT);
        float4 a1 = *(const float4*)(sp + k*MT + 4);
        ulonglong2 w01 = *(const ulonglong2*)(wp + k*HH);
        ulonglong2 w23 = *(const ulonglong2*)(wp + k*HH + 4);
        ull a;
        a = packf2(a0.x);
        fma2(acc[0][0],a,w01.x); fma2(acc[0][1],a,w01.y); fma2(acc[0][2],a,w23.x); fma2(acc[0][3],a,w23.y);
        a = packf2(a0.y);
        fma2(acc[1][0],a,w01.x); fma2(acc[1][1],a,w01.y); fma2(acc[1][2],a,w23.x); fma2(acc[1][3],a,w23.y);
        a = packf2(a0.z);
        fma2(acc[2][0],a,w01.x); fma2(acc[2][1],a,w01.y); fma2(acc[2][2],a,w23.x); fma2(acc[2][3],a,w23.y);
        a = packf2(a0.w);
        fma2(acc[3][0],a,w01.x); fma2(acc[3][1],a,w01.y); fma2(acc[3][2],a,w23.x); fma2(acc[3][3],a,w23.y);
        a = packf2(a1.x);
        fma2(acc[4][0],a,w01.x); fma2(acc[4][1],a,w01.y); fma2(acc[4][2],a,w23.x); fma2(acc[4][3],a,w23.y);
        a = packf2(a1.y);
        fma2(acc[5][0],a,w01.x); fma2(acc[5][1],a,w01.y); fma2(acc[5][2],a,w23.x); fma2(acc[5][3],a,w23.y);
        a = packf2(a1.z);
        fma2(acc[6][0],a,w01.x); fma2(acc[6][1],a,w01.y); fma2(acc[6][2],a,w23.x); fma2(acc[6][3],a,w23.y);
        a = packf2(a1.w);
        fma2(acc[7][0],a,w01.x); fma2(acc[7][1],a,w01.y); fma2(acc[7][2],a,w23.x); fma2(acc[7][3],a,w23.y);
    }
}

__global__ void __launch_bounds__(256, 1)
egnn_kernel(const float* __restrict__ obs,
            const float* __restrict__ scl,
            const float* __restrict__ mn,
            const float* __restrict__ embW,
            const float* __restrict__ embb,
            const float* __restrict__ We1,
            const float* __restrict__ be1,
            const float* __restrict__ We2,
            const float* __restrict__ be2,
            const float* __restrict__ Wc1,
            const float* __restrict__ bc1,
            const float* __restrict__ Wc2,
            const float* __restrict__ bc2,
            const float* __restrict__ Wv1,
            const float* __restrict__ bv1,
            const float* __restrict__ Wv2,
            const float* __restrict__ bv2,
            const float* __restrict__ Wn1,
            const float* __restrict__ bn1,
            const float* __restrict__ Wn2,
            const float* __restrict__ bn2,
            float* __restrict__ out)
{
    extern __shared__ float sm[];
    float* hS    = sm + SM_H;
    float* AS    = sm + SM_A;
    float* BS    = sm + SM_B;
    float* maggS = sm + SM_MAGG;
    float* eaS   = sm + SM_EA;
    float* We2s  = sm + SM_WE2;
    float* Wc1s  = sm + SM_WC1;
    float* m1T   = sm + SM_M1;
    float* m2T   = sm + SM_M2;
    float* vecS  = sm + SM_VEC;
    float* locS  = sm + SM_LOC;
    float* velS  = sm + SM_VEL;
    float* aggS  = sm + SM_AGG;
    float* dnxS  = sm + SM_DNX;
    float* dnyS  = sm + SM_DNY;
    float* csS   = sm + SM_CS;

    float* w128s = vecS + V_W128*HH;
    float* w129s = vecS + V_W129*HH;
    float* be1s  = vecS + V_BE1*HH;
    float* be2s  = vecS + V_BE2*HH;
    float* bc1s  = vecS + V_BC1*HH;
    float* Wc2s  = vecS + V_WC2*HH;
    float* bv1s  = vecS + V_BV1*HH;
    float* bn1s  = vecS + V_BN1*HH;
    float* bn2s  = vecS + V_BN2*HH;
    float* Wv2s  = vecS + V_WV2*HH;

    const int tid  = threadIdx.x;
    const int w    = tid >> 5;         // warp id (0..7)
    const int lane = tid & 31;
    const int eg   = lane >> 3;        // edge group 0..3 (8 edges each)
    const int og   = lane & 7;         // output group 0..7 (8 outputs each)
    const int g    = blockIdx.x;

    // ---- stage obs into BS scratch ----
    const float* obsg = obs + (size_t)g * NA * OBSW;
    for (int t = tid; t < NA*OBSW; t += 256) BS[t] = obsg[t];
    __syncthreads();

    if (tid < NA*2) {
        int i = tid >> 1, c = tid & 1;
        locS[tid] = BS[i*OBSW + NINV + c];
        velS[tid] = BS[i*OBSW + NINV + 2 + c];
    }
    __syncthreads();

    // edge_attr from INITIAL loc
    for (int p = tid; p < NA*NA; p += 256) {
        int i = p >> 5, j = p & 31;
        float dx = locS[i*2+0] - locS[j*2+0];
        float dy = locS[i*2+1] - locS[j*2+1];
        eaS[p] = dx*dx + dy*dy;
    }

    // h = inv @ embW + embb  (warp w: rows 4w..4w+3; lane: cols lane, lane+32)
    {
        float a0[4], a1[4];
        #pragma unroll
        for (int r = 0; r < 4; r++) { a0[r] = embb[lane]; a1[r] = embb[lane+32]; }
        #pragma unroll
        for (int c = 0; c < NINV; c++) {
            float w0 = embW[c*HH + lane];
            float w1 = embW[c*HH + lane + 32];
            #pragma unroll
            for (int r = 0; r < 4; r++) {
                float iv = BS[(w*4+r)*OBSW + c];
                a0[r] += iv*w0; a1[r] += iv*w1;
            }
        }
        #pragma unroll
        for (int r = 0; r < 4; r++) {
            hS[(w*4+r)*HS + lane]      = a0[r];
            hS[(w*4+r)*HS + lane + 32] = a1[r];
        }
    }
    __syncthreads();

    #pragma unroll 1
    for (int l = 0; l < NLAY; l++) {
        // ==== stage per-layer weights ====
        {
            const float4* We2l = (const float4*)(We2 + l*HH*HH);
            const float4* Wc1l = (const float4*)(Wc1 + l*HH*HH);
            const float4* We1l = (const float4*)(We1 + l*130*HH);  // rows 0..127 -> m2T scratch
            float4* We2s4 = (float4*)We2s;
            float4* Wc1s4 = (float4*)Wc1s;
            float4* scr4  = (float4*)m2T;
            #pragma unroll
            for (int t = tid; t < HH*HH/4; t += 256) {
                We2s4[t] = We2l[t];
                Wc1s4[t] = Wc1l[t];
                scr4[t]           = We1l[t];            // We1A
                scr4[t + HH*HH/4] = We1l[t + HH*HH/4];  // We1B
            }
            if (tid < HH) {
                w128s[tid] = We1[(l*130 + 128)*HH + tid];
                w129s[tid] = We1[(l*130 + 129)*HH + tid];
                be1s[tid]  = be1[l*HH + tid];
                be2s[tid]  = be2[l*HH + tid];
                bc1s[tid]  = bc1[l*HH + tid];
                Wc2s[tid]  = Wc2[l*HH + tid];
                bv1s[tid]  = bv1[l*HH + tid];
                bn1s[tid]  = bn1[l*HH + tid];
                bn2s[tid]  = bn2[l*HH + tid];
                Wv2s[tid]  = Wv2[l*HH + tid];
            }
        }
        const float bc2l = bc2[l];
        const float bv2l = bv2[l];
        __syncthreads();

        // ==== phase A: A = h@We1A + be1, B = h@We1B (weights in m2T scratch) ====
        {
            const float* We1As = m2T;
            const float* We1Bs = m2T + HH*HH;
            float a0[4], a1[4], b0[4], b1[4];
            #pragma unroll
            for (int r = 0; r < 4; r++) {
                a0[r] = be1s[lane]; a1[r] = be1s[lane + 32];
                b0[r] = 0.f; b1[r] = 0.f;
            }
            #pragma unroll 4
            for (int c = 0; c < HH; c++) {
                const float* wrA = We1As + c*HH;
                const float* wrB = We1Bs + c*HH;
                float wa0 = wrA[lane], wa1 = wrA[lane+32];
                float wb0 = wrB[lane], wb1 = wrB[lane+32];
                #pragma unroll
                for (int r = 0; r < 4; r++) {
                    float hv = hS[(w*4+r)*HS + c];
                    a0[r] += hv*wa0; a1[r] += hv*wa1;
                    b0[r] += hv*wb0; b1[r] += hv*wb1;
                }
            }
            #pragma unroll
            for (int r = 0; r < 4; r++) {
                AS[(w*4+r)*HS + lane]      = a0[r];
                AS[(w*4+r)*HS + lane + 32] = a1[r];
                BS[(w*4+r)*HS + lane]      = b0[r];
                BS[(w*4+r)*HS + lane + 32] = b1[r];
            }
        }
        __syncthreads();

        // ==== edge phase: warp w owns receiver i = ib*8 + w, 32 sender edges ====
        const int eBase = w * 32;
        #pragma unroll 1
        for (int ib = 0; ib < 4; ib++) {
            const int i = ib*8 + w;       // receiver agent id

            // -- m1 construction: lane = sender j, column e = eBase + j --
            {
                const int j = lane;
                float dx = locS[i*2+0] - locS[j*2+0];
                float dy = locS[i*2+1] - locS[j*2+1];
                float radial = dx*dx + dy*dy;
                float invr = __fdividef(1.0f, sqrtf(radial) + 1.0f);
                dnxS[eBase + j] = dx * invr;
                dnyS[eBase + j] = dy * invr;
                float eav = eaS[i*NA + j];
                float* col = m1T + eBase + j;
                const float* Ai = AS + i*HS;
                const float* Bj = BS + j*HS;
                #pragma unroll 8
                for (int c = 0; c < HH; c++) {
                    float v = Ai[c] + Bj[c] + radial * w128s[c] + eav * w129s[c];
                    col[c*MT] = siluf(v);
                }
            }
            __syncwarp();

            // -- GEMM1: m2 = silu(m1 @ We2 + be2) -> m2T --
            {
                ull acc[8][4];
                wgemm64(m1T + eBase + eg*8, We2s + og*8, be2s, og, acc);
                #pragma unroll
                for (int p = 0; p < 4; p++) {
                    float ex[8], ey[8];
                    #pragma unroll
                    for (int e = 0; e < 8; e++) {
                        float2 f = unpackf2(acc[e][p]);
                        ex[e] = siluf(f.x); ey[e] = siluf(f.y);
                    }
                    int o0 = og*8 + 2*p;
                    float* r0 = m2T + o0*MT + eBase + eg*8;
                    ((float4*)r0)[0] = make_float4(ex[0],ex[1],ex[2],ex[3]);
                    ((float4*)r0)[1] = make_float4(ex[4],ex[5],ex[6],ex[7]);
                    float* r1 = m2T + (o0+1)*MT + eBase + eg*8;
                    ((float4*)r1)[0] = make_float4(ey[0],ey[1],ey[2],ey[3]);
                    ((float4*)r1)[1] = make_float4(ey[4],ey[5],ey[6],ey[7]);
                }
            }
            __syncwarp();

            // -- magg: column sums of m2 over this warp's 32 edges, minus diagonal --
            #pragma unroll
            for (int cc = 0; cc < 2; cc++) {
                int c = lane + cc*32;
                const float* row = m2T + c*MT + eBase;
                float tot = 0.f;
                #pragma unroll
                for (int q = 0; q < 8; q++) {
                    float4 t4 = ((const float4*)row)[q];
                    tot += (t4.x + t4.y) + (t4.z + t4.w);
                }
                tot -= row[i];            // exclude self-edge j == i
                maggS[i*HH + c] = tot;
            }

            // -- GEMM2: t = silu(m2 @ Wc1 + bc1); cs = t . Wc2 + bc2 --
            {
                ull acc[8][4];
                wgemm64(m2T + eBase + eg*8, Wc1s + og*8, bc1s, og, acc);
                float4 wcA = *(const float4*)(Wc2s + og*8);
                float4 wcB = *(const float4*)(Wc2s + og*8 + 4);
                #pragma unroll
                for (int e = 0; e < 8; e++) {
                    float2 f0 = unpackf2(acc[e][0]);
                    float2 f1 = unpackf2(acc[e][1]);
                    float2 f2 = unpackf2(acc[e][2]);
                    float2 f3 = unpackf2(acc[e][3]);
                    float v = siluf(f0.x)*wcA.x + siluf(f0.y)*wcA.y
                            + siluf(f1.x)*wcA.z + siluf(f1.y)*wcA.w
                            + siluf(f2.x)*wcB.x + siluf(f2.y)*wcB.y
                            + siluf(f3.x)*wcB.z + siluf(f3.y)*wcB.w;
                    // reduce over og (8 consecutive lanes share the edge set)
                    v += __shfl_down_sync(0xffffffffu, v, 4);
                    v += __shfl_down_sync(0xffffffffu, v, 2);
                    v += __shfl_down_sync(0xffffffffu, v, 1);
                    if (og == 0) csS[eBase + eg*8 + e] = v + bc2l;
                }
            }
            __syncwarp();

            // -- trans aggregation (diagonal self-cancels: dnx=dny=0) --
            {
                float cj = csS[eBase + lane];
                float tx = wredsum(dnxS[eBase + lane] * cj);
                float ty = wredsum(dnyS[eBase + lane] * cj);
                if (lane == 0) { aggS[i*2+0] = tx; aggS[i*2+1] = ty; }
            }
            __syncwarp();
        }
        __syncthreads();

        // ==== restage node weights into m1T scratch ====
        {
            const float4* Wv1l = (const float4*)(Wv1 + l*HH*HH);
            const float4* Wn1l = (const float4*)(Wn1 + l*2*HH*HH);
            const float4* Wn2l = (const float4*)(Wn2 + l*HH*HH);
            float4* d = (float4*)m1T;
            #pragma unroll
            for (int t = tid; t < HH*HH/4; t += 256) {
                d[t]                = Wv1l[t];
                d[t + HH*HH/4]      = Wn1l[t];
                d[t + 2*(HH*HH/4)]  = Wn1l[t + HH*HH/4];
                d[t + 3*(HH*HH/4)]  = Wn2l[t];
            }
        }
        __syncthreads();
        const float* Wv1s = m1T;
        const float* Wn1s = m1T + HH*HH;
        const float* Wn2s = m1T + 3*HH*HH;

        // ==== node phase: phi_v, vel/loc update ====
        {
            float a0[4], a1[4];
            #pragma unroll
            for (int r = 0; r < 4; r++) { a0[r] = bv1s[lane]; a1[r] = bv1s[lane+32]; }
            #pragma unroll 4
            for (int c = 0; c < HH; c++) {
                const float* wr = Wv1s + c*HH;
                float w0 = wr[lane], w1 = wr[lane+32];
                #pragma unroll
                for (int r = 0; r < 4; r++) {
                    float hv = hS[(w*4+r)*HS + c];
                    a0[r] += hv*w0; a1[r] += hv*w1;
                }
            }
            float wv2a = Wv2s[lane], wv2b = Wv2s[lane + 32];
            #pragma unroll
            for (int r = 0; r < 4; r++) {
                float part = wredsum(siluf(a0[r])*wv2a + siluf(a1[r])*wv2b);
                if (lane == 0) {
                    int i = w*4 + r;
                    float phi = part + bv2l;
                    float vx = phi*velS[i*2+0] + aggS[i*2+0]*(1.0f/31.0f);
                    float vy = phi*velS[i*2+1] + aggS[i*2+1]*(1.0f/31.0f);
                    velS[i*2+0] = vx; velS[i*2+1] = vy;
                    locS[i*2+0] += vx; locS[i*2+1] += vy;
                }
            }
        }

        // ==== U = silu([h, magg] @ Wn1 + bn1) -> AS ====
        {
            float a0[4], a1[4];
            #pragma unroll
            for (int r = 0; r < 4; r++) { a0[r] = bn1s[lane]; a1[r] = bn1s[lane+32]; }
            #pragma unroll 4
            for (int c = 0; c < HH; c++) {
                const float* wr = Wn1s + c*HH;
                float w0 = wr[lane], w1 = wr[lane+32];
                #pragma unroll
                for (int r = 0; r < 4; r++) {
                    float hv = hS[(w*4+r)*HS + c];
                    a0[r] += hv*w0; a1[r] += hv*w1;
                }
            }
            #pragma unroll 4
            for (int c = 0; c < HH; c++) {
                const float* wr = Wn1s + (HH + c)*HH;
                float w0 = wr[lane], w1 = wr[lane+32];
                #pragma unroll
                for (int r = 0; r < 4; r++) {
                    float mv = maggS[(w*4+r)*HH + c];
                    a0[r] += mv*w0; a1[r] += mv*w1;
                }
            }
            #pragma unroll
            for (int r = 0; r < 4; r++) {
                AS[(w*4+r)*HS + lane]      = siluf(a0[r]);
                AS[(w*4+r)*HS + lane + 32] = siluf(a1[r]);
            }
        }

        // ==== h += U @ Wn2 + bn2 ====
        {
            float a0[4], a1[4];
            #pragma unroll
            for (int r = 0; r < 4; r++) { a0[r] = bn2s[lane]; a1[r] = bn2s[lane+32]; }
            #pragma unroll 4
            for (int c = 0; c < HH; c++) {
                const float* wr = Wn2s + c*HH;
                float w0 = wr[lane], w1 = wr[lane+32];
                #pragma unroll
                for (int r = 0; r < 4; r++) {
                    float uv = AS[(w*4+r)*HS + c];
                    a0[r] += uv*w0; a1[r] += uv*w1;
                }
            }
            #pragma unroll
            for (int r = 0; r < 4; r++) {
                hS[(w*4+r)*HS + lane]      += a0[r];
                hS[(w*4+r)*HS + lane + 32] += a1[r];
            }
        }
        __syncthreads();
    }

    // ---- output: scale * vel + mean ----
    if (tid < NA*2) {
        int i = tid >> 1, c = tid & 1;
        out[((size_t)g*NA + i)*2 + c] = scl[c]*velS[tid] + mn[c];
    }
}

extern "C" void kernel_launch(void* const* d_in, const int* in_sizes, int n_in,
                              void* d_out, int out_size) {
    const float* obs  = (const float*)d_in[0];
    const float* scl  = (const float*)d_in[3];
    const float* mn   = (const float*)d_in[4];
    const float* embW = (const float*)d_in[5];
    const float* embb = (const float*)d_in[6];
    const float* We1  = (const float*)d_in[7];
    const float* be1  = (const float*)d_in[8];
    const float* We2  = (const float*)d_in[9];
    const float* be2  = (const float*)d_in[10];
    const float* Wc1  = (const float*)d_in[11];
    const float* bc1  = (const float*)d_in[12];
    const float* Wc2  = (const float*)d_in[13];
    const float* bc2  = (const float*)d_in[14];
    const float* Wv1  = (const float*)d_in[15];
    const float* bv1  = (const float*)d_in[16];
    const float* Wv2  = (const float*)d_in[17];
    const float* bv2  = (const float*)d_in[18];
    const float* Wn1  = (const float*)d_in[19];
    const float* bn1  = (const float*)d_in[20];
    const float* Wn2  = (const float*)d_in[21];
    const float* bn2  = (const float*)d_in[22];
    float* out = (float*)d_out;

    int n_nodes = in_sizes[0] / OBSW;
    int groups  = n_nodes / NA;

    cudaFuncSetAttribute(egnn_kernel, cudaFuncAttributeMaxDynamicSharedMemorySize, SMEM_BYTES);
    egnn_kernel<<<groups, 256, SMEM_BYTES>>>(
        obs, scl, mn, embW, embb,
        We1, be1, We2, be2, Wc1, bc1, Wc2, bc2,
        Wv1, bv1, Wv2, bv2, Wn1, bn1, Wn2, bn2, out);
}

// round 5
// speedup vs baseline: 3.0138x; 1.0889x over previous
#include <cuda_runtime.h>

#define NA    32
#define HH    64
#define HS    68      // h/A/B row stride (float4-aligned, bank-spread)
#define ES    64      // edge slab row stride
#define NINV  16
#define NLAY  4
#define OBSW  20

// ---- smem layout (float offsets) ----
#define SM_H     0
#define SM_A     (SM_H    + NA*HS)
#define SM_B     (SM_A    + NA*HS)
#define SM_MAGG  (SM_B    + NA*HS)
#define SM_EA    (SM_MAGG + NA*HH)
#define SM_WE2   (SM_EA   + NA*NA)     // plane layout
#define SM_WC1   (SM_WE2  + HH*HH)     // plane layout
#define SM_EDGE  (SM_WC1  + HH*HH)     // 8 warps x 64x64 slabs (also weight scratch)
#define SM_VEC   (SM_EDGE + 8*HH*ES)   // 10 x 64 vectors
#define SM_LOC   (SM_VEC  + 10*HH)
#define SM_VEL   (SM_LOC  + 2*NA)
#define SM_AGG   (SM_VEL  + 2*NA)
#define SM_CS    (SM_AGG  + 2*NA)      // 8 warps x 64
#define SMEM_FLOATS (SM_CS + 8*64)
#define SMEM_BYTES  (SMEM_FLOATS * 4)

#define V_W128 0
#define V_W129 1
#define V_BE1  2
#define V_BE2  3
#define V_BC1  4
#define V_WC2  5
#define V_BV1  6
#define V_BN1  7
#define V_BN2  8
#define V_WV2  9

typedef unsigned long long ull;

#define F4C(v,i) (((const float*)&(v))[i])

__device__ __forceinline__ float siluf(float x) {
    float hx = 0.5f * x;
    float t;
    asm("tanh.approx.f32 %0, %1;" : "=f"(t) : "f"(hx));
    return fmaf(hx, t, hx);
}

__device__ __forceinline__ ull packf2(float x) {
    unsigned int u = __float_as_uint(x);
    ull r;
    asm("mov.b64 %0, {%1, %1};" : "=l"(r) : "r"(u));
    return r;
}

__device__ __forceinline__ void fma2(ull &d, ull a, ull b) {
    asm("fma.rn.f32x2 %0, %1, %2, %0;" : "+l"(d) : "l"(a), "l"(b));
}

__device__ __forceinline__ float2 unpackf2(ull v) {
    unsigned int lo, hi;
    asm("mov.b64 {%0, %1}, %2;" : "=r"(lo), "=r"(hi) : "l"(v));
    return make_float2(__uint_as_float(lo), __uint_as_float(hi));
}

__device__ __forceinline__ float wredsum(float v) {
    v += __shfl_down_sync(0xffffffffu, v, 16);
    v += __shfl_down_sync(0xffffffffu, v, 8);
    v += __shfl_down_sync(0xffffffffu, v, 4);
    v += __shfl_down_sync(0xffffffffu, v, 2);
    v += __shfl_down_sync(0xffffffffu, v, 1);
    return v;
}

// 64 edges x 64 outputs, K=64. Lane (eg,og): 16 edges x 8 outputs.
// slabw: [k][edge] with XOR swizzle; Wp: plane layout; acc[e][p] = outputs (og*8+2p, +1).
__device__ __forceinline__ void wgemm(const float* __restrict__ slabw,
                                      const float* __restrict__ Wp,
                                      const float* __restrict__ bias,
                                      int eg4, int og, ull (&acc)[16][4])
{
    ulonglong2 b01 = *(const ulonglong2*)(bias + og*8);
    ulonglong2 b23 = *(const ulonglong2*)(bias + og*8 + 4);
    #pragma unroll
    for (int e = 0; e < 16; e++) {
        acc[e][0] = b01.x; acc[e][1] = b01.y; acc[e][2] = b23.x; acc[e][3] = b23.y;
    }
    #pragma unroll 4
    for (int k = 0; k < HH; k++) {
        int sw = (k & 56) ^ ((k & 32) >> 2);
        const float* rowk = slabw + k*ES;
        int ex = eg4 ^ (sw & 8);
        int qb = sw & 48;
        float av[16];
        *(float4*)(av+0)  = *(const float4*)(rowk + ((0  ^ qb) + ex));
        *(float4*)(av+4)  = *(const float4*)(rowk + ((16 ^ qb) + ex));
        *(float4*)(av+8)  = *(const float4*)(rowk + ((32 ^ qb) + ex));
        *(float4*)(av+12) = *(const float4*)(rowk + ((48 ^ qb) + ex));
        ulonglong2 w01 = *(const ulonglong2*)(Wp + k*64 + og*4);
        ulonglong2 w23 = *(const ulonglong2*)(Wp + k*64 + 32 + og*4);
        #pragma unroll
        for (int e = 0; e < 16; e++) {
            ull a = packf2(av[e]);
            fma2(acc[e][0], a, w01.x);
            fma2(acc[e][1], a, w01.y);
            fma2(acc[e][2], a, w23.x);
            fma2(acc[e][3], a, w23.y);
        }
    }
}

__global__ void __launch_bounds__(256, 1)
egnn_kernel(const float* __restrict__ obs,
            const float* __restrict__ scl,
            const float* __restrict__ mn,
            const float* __restrict__ embW,
            const float* __restrict__ embb,
            const float* __restrict__ We1,
            const float* __restrict__ be1,
            const float* __restrict__ We2,
            const float* __restrict__ be2,
            const float* __restrict__ Wc1,
            const float* __restrict__ bc1,
            const float* __restrict__ Wc2,
            const float* __restrict__ bc2,
            const float* __restrict__ Wv1,
            const float* __restrict__ bv1,
            const float* __restrict__ Wv2,
            const float* __restrict__ bv2,
            const float* __restrict__ Wn1,
            const float* __restrict__ bn1,
            const float* __restrict__ Wn2,
            const float* __restrict__ bn2,
            float* __restrict__ out)
{
    extern __shared__ float sm[];
    float* hS    = sm + SM_H;
    float* AS    = sm + SM_A;
    float* BS    = sm + SM_B;
    float* maggS = sm + SM_MAGG;
    float* eaS   = sm + SM_EA;
    float* We2p  = sm + SM_WE2;
    float* Wc1p  = sm + SM_WC1;
    float* edgeS = sm + SM_EDGE;
    float* vecS  = sm + SM_VEC;
    float* locS  = sm + SM_LOC;
    float* velS  = sm + SM_VEL;
    float* aggS  = sm + SM_AGG;
    float* csS   = sm + SM_CS;

    float* w128s = vecS + V_W128*HH;
    float* w129s = vecS + V_W129*HH;
    float* be1s  = vecS + V_BE1*HH;
    float* be2s  = vecS + V_BE2*HH;
    float* bc1s  = vecS + V_BC1*HH;
    float* Wc2s  = vecS + V_WC2*HH;
    float* bv1s  = vecS + V_BV1*HH;
    float* bn1s  = vecS + V_BN1*HH;
    float* bn2s  = vecS + V_BN2*HH;
    float* Wv2s  = vecS + V_WV2*HH;

    const int tid  = threadIdx.x;
    const int w    = tid >> 5;
    const int lane = tid & 31;
    const int eg   = lane >> 3;
    const int og   = lane & 7;
    const int eg4  = eg * 4;
    const int g    = blockIdx.x;

    float* slabw = edgeS + w * (HH*ES);
    float* csWw  = csS + w * 64;

    // ---- stage obs into BS scratch ----
    const float* obsg = obs + (size_t)g * NA * OBSW;
    for (int t = tid; t < NA*OBSW; t += 256) BS[t] = obsg[t];
    __syncthreads();

    if (tid < NA*2) {
        int i = tid >> 1, c = tid & 1;
        locS[tid] = BS[i*OBSW + NINV + c];
        velS[tid] = BS[i*OBSW + NINV + 2 + c];
    }
    __syncthreads();

    for (int p = tid; p < NA*NA; p += 256) {
        int i = p >> 5, j = p & 31;
        float dx = locS[i*2+0] - locS[j*2+0];
        float dy = locS[i*2+1] - locS[j*2+1];
        eaS[p] = dx*dx + dy*dy;
    }

    // h = inv @ embW + embb
    {
        float a0[4], a1[4];
        #pragma unroll
        for (int r = 0; r < 4; r++) { a0[r] = embb[lane]; a1[r] = embb[lane+32]; }
        #pragma unroll
        for (int c = 0; c < NINV; c++) {
            float w0 = embW[c*HH + lane];
            float w1 = embW[c*HH + lane + 32];
            #pragma unroll
            for (int r = 0; r < 4; r++) {
                float iv = BS[(w*4+r)*OBSW + c];
                a0[r] += iv*w0; a1[r] += iv*w1;
            }
        }
        #pragma unroll
        for (int r = 0; r < 4; r++) {
            hS[(w*4+r)*HS + lane]      = a0[r];
            hS[(w*4+r)*HS + lane + 32] = a1[r];
        }
    }
    __syncthreads();

    #pragma unroll 1
    for (int l = 0; l < NLAY; l++) {
        // ==== stage per-layer weights ====
        {
            const float4* We2l = (const float4*)(We2 + l*HH*HH);
            const float4* Wc1l = (const float4*)(Wc1 + l*HH*HH);
            float4* d2 = (float4*)We2p;
            float4* dc = (float4*)Wc1p;
            #pragma unroll
            for (int t = tid; t < 1024; t += 256) {
                int k = t >> 4, o4 = t & 15;
                int ogx = o4 >> 1, h = o4 & 1;
                int dst = k*16 + h*8 + ogx;       // de-interleaved planes
                d2[dst] = We2l[t];
                dc[dst] = Wc1l[t];
            }
            // We1 rows 0..127 -> edge slab scratch (plain layout)
            const float4* We1l = (const float4*)(We1 + l*130*HH);
            float4* scr = (float4*)edgeS;
            #pragma unroll
            for (int t = tid; t < 2048; t += 256) scr[t] = We1l[t];
            if (tid < HH) {
                w128s[tid] = We1[(l*130 + 128)*HH + tid];
                w129s[tid] = We1[(l*130 + 129)*HH + tid];
                be1s[tid]  = be1[l*HH + tid];
                be2s[tid]  = be2[l*HH + tid];
                bc1s[tid]  = bc1[l*HH + tid];
                Wc2s[tid]  = Wc2[l*HH + tid];
                bv1s[tid]  = bv1[l*HH + tid];
                bn1s[tid]  = bn1[l*HH + tid];
                bn2s[tid]  = bn2[l*HH + tid];
                Wv2s[tid]  = Wv2[l*HH + tid];
            }
        }
        const float bc2l = bc2[l];
        const float bv2l = bv2[l];
        __syncthreads();

        // ==== phase A: A = h@We1A + be1, B = h@We1B ====
        {
            const float* We1As = edgeS;
            const float* We1Bs = edgeS + HH*HH;
            float a0[4], a1[4], b0[4], b1[4];
            #pragma unroll
            for (int r = 0; r < 4; r++) {
                a0[r] = be1s[lane]; a1[r] = be1s[lane + 32];
                b0[r] = 0.f; b1[r] = 0.f;
            }
            #pragma unroll 4
            for (int c = 0; c < HH; c++) {
                const float* wrA = We1As + c*HH;
                const float* wrB = We1Bs + c*HH;
                float wa0 = wrA[lane], wa1 = wrA[lane+32];
                float wb0 = wrB[lane], wb1 = wrB[lane+32];
                #pragma unroll
                for (int r = 0; r < 4; r++) {
                    float hv = hS[(w*4+r)*HS + c];
                    a0[r] += hv*wa0; a1[r] += hv*wa1;
                    b0[r] += hv*wb0; b1[r] += hv*wb1;
                }
            }
            #pragma unroll
            for (int r = 0; r < 4; r++) {
                AS[(w*4+r)*HS + lane]      = a0[r];
                AS[(w*4+r)*HS + lane + 32] = a1[r];
                BS[(w*4+r)*HS + lane]      = b0[r];
                BS[(w*4+r)*HS + lane + 32] = b1[r];
            }
        }
        __syncthreads();

        // ==== edge phase: 2 iterations x 2 receivers per warp ====
        #pragma unroll 1
        for (int it = 0; it < 2; it++) {
            int iR[2];
            iR[0] = it*16 + w;
            iR[1] = it*16 + 8 + w;

            // -- m1 construction (lane = sender j, both receivers) --
            float dnx[2], dny[2];
            {
                float lx = locS[lane*2+0], ly = locS[lane*2+1];
                float rad[2], eav[2];
                #pragma unroll
                for (int r = 0; r < 2; r++) {
                    float dx = locS[iR[r]*2+0] - lx;
                    float dy = locS[iR[r]*2+1] - ly;
                    rad[r] = dx*dx + dy*dy;
                    float invr = __fdividef(1.0f, sqrtf(rad[r]) + 1.0f);
                    dnx[r] = dx * invr; dny[r] = dy * invr;
                    eav[r] = eaS[iR[r]*NA + lane];
                }
                const float* Bj  = BS + lane*HS;
                const float* Ai0 = AS + iR[0]*HS;
                const float* Ai1 = AS + iR[1]*HS;
                #pragma unroll
                for (int c4 = 0; c4 < 16; c4++) {
                    float4 wA  = *(const float4*)(w128s + c4*4);
                    float4 wB  = *(const float4*)(w129s + c4*4);
                    float4 b4  = *(const float4*)(Bj  + c4*4);
                    float4 a04 = *(const float4*)(Ai0 + c4*4);
                    float4 a14 = *(const float4*)(Ai1 + c4*4);
                    #pragma unroll
                    for (int cc = 0; cc < 4; cc++) {
                        int c  = c4*4 + cc;
                        int sw = (c & 56) ^ ((c & 32) >> 2);
                        int lx2 = lane ^ (sw & 24);
                        float wa = F4C(wA,cc), wb = F4C(wB,cc);
                        float bb = F4C(b4,cc);
                        float v0 = siluf(F4C(a04,cc) + bb + rad[0]*wa + eav[0]*wb);
                        float v1 = siluf(F4C(a14,cc) + bb + rad[1]*wa + eav[1]*wb);
                        slabw[c*ES + ((0  ^ (sw & 32)) + lx2)] = v0;
                        slabw[c*ES + ((32 ^ (sw & 32)) + lx2)] = v1;
                    }
                }
            }
            __syncwarp();

            // self-edge mask for magg (logical col -> (r, j))
            float vmv[16];
            #pragma unroll
            for (int e = 0; e < 16; e++) {
                int q = e >> 2;
                int j = (q & 1)*16 + eg4 + (e & 3);
                vmv[e] = (j == iR[q >> 1]) ? 0.f : 1.f;
            }

            ull acc[16][4];

            // -- GEMM1: m2 = silu(m1 @ We2 + be2), in-place over slab --
            wgemm(slabw, We2p, be2s, eg4, og, acc);
            __syncwarp();
            {
                float part[2][8];
                #pragma unroll
                for (int r = 0; r < 2; r++)
                    #pragma unroll
                    for (int s = 0; s < 8; s++) part[r][s] = 0.f;
                #pragma unroll
                for (int p = 0; p < 4; p++) {
                    #pragma unroll
                    for (int x = 0; x < 2; x++) {
                        float v[16];
                        #pragma unroll
                        for (int e = 0; e < 16; e++) {
                            float2 f = unpackf2(acc[e][p]);
                            v[e] = siluf(x ? f.y : f.x);
                        }
                        #pragma unroll
                        for (int e = 0; e < 16; e++)
                            part[e>>3][p*2+x] = fmaf(vmv[e], v[e], part[e>>3][p*2+x]);
                        int row = og*8 + p*2 + x;
                        int sw  = (row & 56) ^ ((row & 32) >> 2);
                        int ex  = eg4 ^ (sw & 8);
                        int qb  = sw & 48;
                        float* rw = slabw + row*ES;
                        *(float4*)(rw + ((0  ^ qb) + ex)) = make_float4(v[0], v[1], v[2], v[3]);
                        *(float4*)(rw + ((16 ^ qb) + ex)) = make_float4(v[4], v[5], v[6], v[7]);
                        *(float4*)(rw + ((32 ^ qb) + ex)) = make_float4(v[8], v[9], v[10], v[11]);
                        *(float4*)(rw + ((48 ^ qb) + ex)) = make_float4(v[12], v[13], v[14], v[15]);
                    }
                }
                __syncwarp();
                // magg: reduce partials over eg (lane bits 3,4)
                #pragma unroll
                for (int r = 0; r < 2; r++) {
                    #pragma unroll
                    for (int s = 0; s < 8; s++) {
                        float vv = part[r][s];
                        vv += __shfl_xor_sync(0xffffffffu, vv, 8);
                        vv += __shfl_xor_sync(0xffffffffu, vv, 16);
                        if (lane < 8) maggS[iR[r]*HH + lane*8 + s] = vv;
                    }
                }
            }

            // -- GEMM2: t = silu(m2 @ Wc1 + bc1); cs = t.Wc2 + bc2 --
            wgemm(slabw, Wc1p, bc1s, eg4, og, acc);
            {
                float wc[8];
                *(float4*)(wc+0) = *(const float4*)(Wc2s + og*8);
                *(float4*)(wc+4) = *(const float4*)(Wc2s + og*8 + 4);
                float csp[16];
                #pragma unroll
                for (int e = 0; e < 16; e++) csp[e] = 0.f;
                #pragma unroll
                for (int p = 0; p < 4; p++) {
                    #pragma unroll
                    for (int e = 0; e < 16; e++) {
                        float2 f = unpackf2(acc[e][p]);
                        csp[e] += siluf(f.x)*wc[2*p] + siluf(f.y)*wc[2*p+1];
                    }
                }
                #pragma unroll
                for (int e = 0; e < 16; e++) {
                    float vv = csp[e];
                    vv += __shfl_down_sync(0xffffffffu, vv, 4);
                    vv += __shfl_down_sync(0xffffffffu, vv, 2);
                    vv += __shfl_down_sync(0xffffffffu, vv, 1);
                    csp[e] = vv;
                }
                if (og == 0) {
                    #pragma unroll
                    for (int e = 0; e < 16; e++) {
                        int col = (e >> 2)*16 + eg4 + (e & 3);
                        csWw[col] = csp[e] + bc2l;
                    }
                }
            }
            __syncwarp();

            // -- trans aggregation (self-edge has dn = 0) --
            #pragma unroll
            for (int r = 0; r < 2; r++) {
                float cj = csWw[r*32 + lane];
                float tx = wredsum(dnx[r] * cj);
                float ty = wredsum(dny[r] * cj);
                if (lane == 0) { aggS[iR[r]*2+0] = tx; aggS[iR[r]*2+1] = ty; }
            }
            __syncwarp();
        }
        __syncthreads();

        // ==== restage node weights into edge slab ====
        {
            const float4* Wv1l = (const float4*)(Wv1 + l*HH*HH);
            const float4* Wn1l = (const float4*)(Wn1 + l*2*HH*HH);
            const float4* Wn2l = (const float4*)(Wn2 + l*HH*HH);
            float4* d = (float4*)edgeS;
            #pragma unroll
            for (int t = tid; t < 1024; t += 256) {
                d[t]        = Wv1l[t];
                d[t + 1024] = Wn1l[t];
                d[t + 2048] = Wn1l[t + 1024];
                d[t + 3072] = Wn2l[t];
            }
        }
        __syncthreads();
        const float* Wv1s = edgeS;
        const float* Wn1s = edgeS + HH*HH;
        const float* Wn2s = edgeS + 3*HH*HH;

        // ==== node phase: phi_v, vel/loc update ====
        {
            float a0[4], a1[4];
            #pragma unroll
            for (int r = 0; r < 4; r++) { a0[r] = bv1s[lane]; a1[r] = bv1s[lane+32]; }
            #pragma unroll 4
            for (int c = 0; c < HH; c++) {
                const float* wr = Wv1s + c*HH;
                float w0 = wr[lane], w1 = wr[lane+32];
                #pragma unroll
                for (int r = 0; r < 4; r++) {
                    float hv = hS[(w*4+r)*HS + c];
                    a0[r] += hv*w0; a1[r] += hv*w1;
                }
            }
            float wv2a = Wv2s[lane], wv2b = Wv2s[lane + 32];
            #pragma unroll
            for (int r = 0; r < 4; r++) {
                float part = wredsum(siluf(a0[r])*wv2a + siluf(a1[r])*wv2b);
                if (lane == 0) {
                    int i = w*4 + r;
                    float phi = part + bv2l;
                    float vx = phi*velS[i*2+0] + aggS[i*2+0]*(1.0f/31.0f);
                    float vy = phi*velS[i*2+1] + aggS[i*2+1]*(1.0f/31.0f);
                    velS[i*2+0] = vx; velS[i*2+1] = vy;
                    locS[i*2+0] += vx; locS[i*2+1] += vy;
                }
            }
        }

        // ==== U = silu([h, magg] @ Wn1 + bn1) -> AS ====
        {
            float a0[4], a1[4];
            #pragma unroll
            for (int r = 0; r < 4; r++) { a0[r] = bn1s[lane]; a1[r] = bn1s[lane+32]; }
            #pragma unroll 4
            for (int c = 0; c < HH; c++) {
                const float* wr = Wn1s + c*HH;
                float w0 = wr[lane], w1 = wr[lane+32];
                #pragma unroll
                for (int r = 0; r < 4; r++) {
                    float hv = hS[(w*4+r)*HS + c];
                    a0[r] += hv*w0; a1[r] += hv*w1;
                }
            }
            #pragma unroll 4
            for (int c = 0; c < HH; c++) {
                const float* wr = Wn1s + (HH + c)*HH;
                float w0 = wr[lane], w1 = wr[lane+32];
                #pragma unroll
                for (int r = 0; r < 4; r++) {
                    float mv = maggS[(w*4+r)*HH + c];
                    a0[r] += mv*w0; a1[r] += mv*w1;
                }
            }
            #pragma unroll
            for (int r = 0; r < 4; r++) {
                AS[(w*4+r)*HS + lane]      = siluf(a0[r]);
                AS[(w*4+r)*HS + lane + 32] = siluf(a1[r]);
            }
        }

        // ==== h += U @ Wn2 + bn2 ====
        {
            float a0[4], a1[4];
            #pragma unroll
            for (int r = 0; r < 4; r++) { a0[r] = bn2s[lane]; a1[r] = bn2s[lane+32]; }
            #pragma unroll 4
            for (int c = 0; c < HH; c++) {
                const float* wr = Wn2s + c*HH;
                float w0 = wr[lane], w1 = wr[lane+32];
                #pragma unroll
                for (int r = 0; r < 4; r++) {
                    float uv = AS[(w*4+r)*HS + c];
                    a0[r] += uv*w0; a1[r] += uv*w1;
                }
            }
            #pragma unroll
            for (int r = 0; r < 4; r++) {
                hS[(w*4+r)*HS + lane]      += a0[r];
                hS[(w*4+r)*HS + lane + 32] += a1[r];
            }
        }
        __syncthreads();
    }

    // ---- output ----
    if (tid < NA*2) {
        int i = tid >> 1, c = tid & 1;
        out[((size_t)g*NA + i)*2 + c] = scl[c]*velS[tid] + mn[c];
    }
}

extern "C" void kernel_launch(void* const* d_in, const int* in_sizes, int n_in,
                              void* d_out, int out_size) {
    const float* obs  = (const float*)d_in[0];
    const float* scl  = (const float*)d_in[3];
    const float* mn   = (const float*)d_in[4];
    const float* embW = (const float*)d_in[5];
    const float* embb = (const float*)d_in[6];
    const float* We1  = (const float*)d_in[7];
    const float* be1  = (const float*)d_in[8];
    const float* We2  = (const float*)d_in[9];
    const float* be2  = (const float*)d_in[10];
    const float* Wc1  = (const float*)d_in[11];
    const float* bc1  = (const float*)d_in[12];
    const float* Wc2  = (const float*)d_in[13];
    const float* bc2  = (const float*)d_in[14];
    const float* Wv1  = (const float*)d_in[15];
    const float* bv1  = (const float*)d_in[16];
    const float* Wv2  = (const float*)d_in[17];
    const float* bv2  = (const float*)d_in[18];
    const float* Wn1  = (const float*)d_in[19];
    const float* bn1  = (const float*)d_in[20];
    const float* Wn2  = (const float*)d_in[21];
    const float* bn2  = (const float*)d_in[22];
    float* out = (float*)d_out;

    int n_nodes = in_sizes[0] / OBSW;
    int groups  = n_nodes / NA;

    cudaFuncSetAttribute(egnn_kernel, cudaFuncAttributeMaxDynamicSharedMemorySize, SMEM_BYTES);
    egnn_kernel<<<groups, 256, SMEM_BYTES>>>(
        obs, scl, mn, embW, embb,
        We1, be1, We2, be2, Wc1, bc1, Wc2, bc2,
        Wv1, bv1, Wv2, bv2, Wn1, bn1, Wn2, bn2, out);
}

// round 6
// speedup vs baseline: 3.4302x; 1.1381x over previous
#include <cuda_runtime.h>

#define NA    32
#define HH    64
#define HS    68      // h/A/B row stride (float4-aligned, bank-spread)
#define ES    64      // edge slab row stride
#define NINV  16
#define NLAY  4
#define OBSW  20

// ---- smem layout (float offsets) ----
#define SM_H     0
#define SM_A     (SM_H    + NA*HS)
#define SM_B     (SM_A    + NA*HS)
#define SM_MAGG  (SM_B    + NA*HS)
#define SM_EA    (SM_MAGG + NA*HH)
#define SM_WE2   (SM_EA   + NA*NA)     // plane layout
#define SM_WC1   (SM_WE2  + HH*HH)     // plane layout
#define SM_EDGE  (SM_WC1  + HH*HH)     // 8 warps x 64x64 slabs (also weight scratch)
#define SM_VEC   (SM_EDGE + 8*HH*ES)   // 10 x 64 vectors
#define SM_LOC   (SM_VEC  + 10*HH)
#define SM_VEL   (SM_LOC  + 2*NA)
#define SM_AGG   (SM_VEL  + 2*NA)
#define SM_CS    (SM_AGG  + 2*NA)      // 8 warps x 64
#define SMEM_FLOATS (SM_CS + 8*64)
#define SMEM_BYTES  (SMEM_FLOATS * 4)

#define V_W128 0
#define V_W129 1
#define V_BE1  2
#define V_BE2  3
#define V_BC1  4
#define V_WC2  5
#define V_BV1  6
#define V_BN1  7
#define V_BN2  8
#define V_WV2  9

typedef unsigned long long ull;

#define F4C(v,i) (((const float*)&(v))[i])

__device__ __forceinline__ float siluf(float x) {
    float hx = 0.5f * x;
    float t;
    asm("tanh.approx.f32 %0, %1;" : "=f"(t) : "f"(hx));
    return fmaf(hx, t, hx);
}

__device__ __forceinline__ ull packf2(float x) {
    unsigned int u = __float_as_uint(x);
    ull r;
    asm("mov.b64 %0, {%1, %1};" : "=l"(r) : "r"(u));
    return r;
}

__device__ __forceinline__ void fma2(ull &d, ull a, ull b) {
    asm("fma.rn.f32x2 %0, %1, %2, %0;" : "+l"(d) : "l"(a), "l"(b));
}

__device__ __forceinline__ float2 unpackf2(ull v) {
    unsigned int lo, hi;
    asm("mov.b64 {%0, %1}, %2;" : "=r"(lo), "=r"(hi) : "l"(v));
    return make_float2(__uint_as_float(lo), __uint_as_float(hi));
}

__device__ __forceinline__ float wredsum(float v) {
    v += __shfl_down_sync(0xffffffffu, v, 16);
    v += __shfl_down_sync(0xffffffffu, v, 8);
    v += __shfl_down_sync(0xffffffffu, v, 4);
    v += __shfl_down_sync(0xffffffffu, v, 2);
    v += __shfl_down_sync(0xffffffffu, v, 1);
    return v;
}

// 64 edges x 64 outputs, K=64. Lane (eg,og): 16 edges x 8 outputs.
// acc[o][ep]: output og*8+o, edge-pair ep (f32x2 over two adjacent phys edges).
// Weights packed (8 movs/k); activations consumed directly as f32x2 from LDS.128.
// Swizzle constants hoisted: invariant over each 8-k block.
__device__ __forceinline__ void wgemm(const float* __restrict__ slabw,
                                      const float* __restrict__ Wp,
                                      const float* __restrict__ bias,
                                      int eg4, int og, ull (&acc)[8][8])
{
    {
        float b[8];
        *(float4*)(b+0) = *(const float4*)(bias + og*8);
        *(float4*)(b+4) = *(const float4*)(bias + og*8 + 4);
        #pragma unroll
        for (int o = 0; o < 8; o++) {
            ull bp = packf2(b[o]);
            #pragma unroll
            for (int ep = 0; ep < 8; ep++) acc[o][ep] = bp;
        }
    }
    #pragma unroll 1
    for (int kt = 0; kt < 8; kt++) {
        const int k0 = kt * 8;
        const int sw = (k0 & 56) ^ ((k0 & 32) >> 2);
        const int ex = eg4 ^ (sw & 8);
        const int qb = sw & 48;
        const float* rowk = slabw + k0*ES;
        const float* wpk  = Wp + k0*64;
        #pragma unroll
        for (int u = 0; u < 8; u++) {
            ull a[8];
            *(ulonglong2*)(a+0) = *(const ulonglong2*)(rowk + u*ES + ((0  ^ qb) + ex));
            *(ulonglong2*)(a+2) = *(const ulonglong2*)(rowk + u*ES + ((16 ^ qb) + ex));
            *(ulonglong2*)(a+4) = *(const ulonglong2*)(rowk + u*ES + ((32 ^ qb) + ex));
            *(ulonglong2*)(a+6) = *(const ulonglong2*)(rowk + u*ES + ((48 ^ qb) + ex));
            float wv[8];
            *(float4*)(wv+0) = *(const float4*)(wpk + u*64 + og*4);
            *(float4*)(wv+4) = *(const float4*)(wpk + u*64 + 32 + og*4);
            #pragma unroll
            for (int o = 0; o < 8; o++) {
                ull wq = packf2(wv[o]);
                fma2(acc[o][0], wq, a[0]);
                fma2(acc[o][1], wq, a[1]);
                fma2(acc[o][2], wq, a[2]);
                fma2(acc[o][3], wq, a[3]);
                fma2(acc[o][4], wq, a[4]);
                fma2(acc[o][5], wq, a[5]);
                fma2(acc[o][6], wq, a[6]);
                fma2(acc[o][7], wq, a[7]);
            }
        }
    }
}

__global__ void __launch_bounds__(256, 1)
egnn_kernel(const float* __restrict__ obs,
            const float* __restrict__ scl,
            const float* __restrict__ mn,
            const float* __restrict__ embW,
            const float* __restrict__ embb,
            const float* __restrict__ We1,
            const float* __restrict__ be1,
            const float* __restrict__ We2,
            const float* __restrict__ be2,
            const float* __restrict__ Wc1,
            const float* __restrict__ bc1,
            const float* __restrict__ Wc2,
            const float* __restrict__ bc2,
            const float* __restrict__ Wv1,
            const float* __restrict__ bv1,
            const float* __restrict__ Wv2,
            const float* __restrict__ bv2,
            const float* __restrict__ Wn1,
            const float* __restrict__ bn1,
            const float* __restrict__ Wn2,
            const float* __restrict__ bn2,
            float* __restrict__ out)
{
    extern __shared__ float sm[];
    float* hS    = sm + SM_H;
    float* AS    = sm + SM_A;
    float* BS    = sm + SM_B;
    float* maggS = sm + SM_MAGG;
    float* eaS   = sm + SM_EA;
    float* We2p  = sm + SM_WE2;
    float* Wc1p  = sm + SM_WC1;
    float* edgeS = sm + SM_EDGE;
    float* vecS  = sm + SM_VEC;
    float* locS  = sm + SM_LOC;
    float* velS  = sm + SM_VEL;
    float* aggS  = sm + SM_AGG;
    float* csS   = sm + SM_CS;

    float* w128s = vecS + V_W128*HH;
    float* w129s = vecS + V_W129*HH;
    float* be1s  = vecS + V_BE1*HH;
    float* be2s  = vecS + V_BE2*HH;
    float* bc1s  = vecS + V_BC1*HH;
    float* Wc2s  = vecS + V_WC2*HH;
    float* bv1s  = vecS + V_BV1*HH;
    float* bn1s  = vecS + V_BN1*HH;
    float* bn2s  = vecS + V_BN2*HH;
    float* Wv2s  = vecS + V_WV2*HH;

    const int tid  = threadIdx.x;
    const int w    = tid >> 5;
    const int lane = tid & 31;
    const int eg   = lane >> 3;
    const int og   = lane & 7;
    const int eg4  = eg * 4;
    const int g    = blockIdx.x;

    float* slabw = edgeS + w * (HH*ES);
    float* csWw  = csS + w * 64;

    // ---- stage obs into BS scratch ----
    const float* obsg = obs + (size_t)g * NA * OBSW;
    for (int t = tid; t < NA*OBSW; t += 256) BS[t] = obsg[t];
    __syncthreads();

    if (tid < NA*2) {
        int i = tid >> 1, c = tid & 1;
        locS[tid] = BS[i*OBSW + NINV + c];
        velS[tid] = BS[i*OBSW + NINV + 2 + c];
    }
    __syncthreads();

    for (int p = tid; p < NA*NA; p += 256) {
        int i = p >> 5, j = p & 31;
        float dx = locS[i*2+0] - locS[j*2+0];
        float dy = locS[i*2+1] - locS[j*2+1];
        eaS[p] = dx*dx + dy*dy;
    }

    // h = inv @ embW + embb
    {
        float a0[4], a1[4];
        #pragma unroll
        for (int r = 0; r < 4; r++) { a0[r] = embb[lane]; a1[r] = embb[lane+32]; }
        #pragma unroll
        for (int c = 0; c < NINV; c++) {
            float w0 = embW[c*HH + lane];
            float w1 = embW[c*HH + lane + 32];
            #pragma unroll
            for (int r = 0; r < 4; r++) {
                float iv = BS[(w*4+r)*OBSW + c];
                a0[r] += iv*w0; a1[r] += iv*w1;
            }
        }
        #pragma unroll
        for (int r = 0; r < 4; r++) {
            hS[(w*4+r)*HS + lane]      = a0[r];
            hS[(w*4+r)*HS + lane + 32] = a1[r];
        }
    }
    __syncthreads();

    #pragma unroll 1
    for (int l = 0; l < NLAY; l++) {
        // ==== stage per-layer weights ====
        {
            const float4* We2l = (const float4*)(We2 + l*HH*HH);
            const float4* Wc1l = (const float4*)(Wc1 + l*HH*HH);
            float4* d2 = (float4*)We2p;
            float4* dc = (float4*)Wc1p;
            #pragma unroll
            for (int t = tid; t < 1024; t += 256) {
                int k = t >> 4, o4 = t & 15;
                int ogx = o4 >> 1, h = o4 & 1;
                int dst = k*16 + h*8 + ogx;       // de-interleaved planes
                d2[dst] = We2l[t];
                dc[dst] = Wc1l[t];
            }
            // We1 rows 0..127 -> edge slab scratch (plain layout)
            const float4* We1l = (const float4*)(We1 + l*130*HH);
            float4* scr = (float4*)edgeS;
            #pragma unroll
            for (int t = tid; t < 2048; t += 256) scr[t] = We1l[t];
            if (tid < HH) {
                w128s[tid] = We1[(l*130 + 128)*HH + tid];
                w129s[tid] = We1[(l*130 + 129)*HH + tid];
                be1s[tid]  = be1[l*HH + tid];
                be2s[tid]  = be2[l*HH + tid];
                bc1s[tid]  = bc1[l*HH + tid];
                Wc2s[tid]  = Wc2[l*HH + tid];
                bv1s[tid]  = bv1[l*HH + tid];
                bn1s[tid]  = bn1[l*HH + tid];
                bn2s[tid]  = bn2[l*HH + tid];
                Wv2s[tid]  = Wv2[l*HH + tid];
            }
        }
        const float bc2l = bc2[l];
        const float bv2l = bv2[l];
        __syncthreads();

        // ==== phase A: A = h@We1A + be1, B = h@We1B ====
        {
            const float* We1As = edgeS;
            const float* We1Bs = edgeS + HH*HH;
            float a0[4], a1[4], b0[4], b1[4];
            #pragma unroll
            for (int r = 0; r < 4; r++) {
                a0[r] = be1s[lane]; a1[r] = be1s[lane + 32];
                b0[r] = 0.f; b1[r] = 0.f;
            }
            #pragma unroll 4
            for (int c = 0; c < HH; c++) {
                const float* wrA = We1As + c*HH;
                const float* wrB = We1Bs + c*HH;
                float wa0 = wrA[lane], wa1 = wrA[lane+32];
                float wb0 = wrB[lane], wb1 = wrB[lane+32];
                #pragma unroll
                for (int r = 0; r < 4; r++) {
                    float hv = hS[(w*4+r)*HS + c];
                    a0[r] += hv*wa0; a1[r] += hv*wa1;
                    b0[r] += hv*wb0; b1[r] += hv*wb1;
                }
            }
            #pragma unroll
            for (int r = 0; r < 4; r++) {
                AS[(w*4+r)*HS + lane]      = a0[r];
                AS[(w*4+r)*HS + lane + 32] = a1[r];
                BS[(w*4+r)*HS + lane]      = b0[r];
                BS[(w*4+r)*HS + lane + 32] = b1[r];
            }
        }
        __syncthreads();

        // ==== edge phase: 2 iterations x 2 receivers per warp ====
        #pragma unroll 1
        for (int it = 0; it < 2; it++) {
            int iR[2];
            iR[0] = it*16 + w;
            iR[1] = it*16 + 8 + w;

            // -- m1 construction (lane = sender j, both receivers) --
            float dnx[2], dny[2];
            {
                float lx = locS[lane*2+0], ly = locS[lane*2+1];
                float rad[2], eav[2];
                #pragma unroll
                for (int r = 0; r < 2; r++) {
                    float dx = locS[iR[r]*2+0] - lx;
                    float dy = locS[iR[r]*2+1] - ly;
                    rad[r] = dx*dx + dy*dy;
                    float invr = __fdividef(1.0f, sqrtf(rad[r]) + 1.0f);
                    dnx[r] = dx * invr; dny[r] = dy * invr;
                    eav[r] = eaS[iR[r]*NA + lane];
                }
                const float* Bj  = BS + lane*HS;
                const float* Ai0 = AS + iR[0]*HS;
                const float* Ai1 = AS + iR[1]*HS;
                #pragma unroll
                for (int c4 = 0; c4 < 16; c4++) {
                    float4 wA  = *(const float4*)(w128s + c4*4);
                    float4 wB  = *(const float4*)(w129s + c4*4);
                    float4 b4  = *(const float4*)(Bj  + c4*4);
                    float4 a04 = *(const float4*)(Ai0 + c4*4);
                    float4 a14 = *(const float4*)(Ai1 + c4*4);
                    #pragma unroll
                    for (int cc = 0; cc < 4; cc++) {
                        int c  = c4*4 + cc;
                        int sw = (c & 56) ^ ((c & 32) >> 2);
                        int lx2 = lane ^ (sw & 24);
                        float wa = F4C(wA,cc), wb = F4C(wB,cc);
                        float bb = F4C(b4,cc);
                        float v0 = siluf(F4C(a04,cc) + bb + rad[0]*wa + eav[0]*wb);
                        float v1 = siluf(F4C(a14,cc) + bb + rad[1]*wa + eav[1]*wb);
                        slabw[c*ES + ((0  ^ (sw & 32)) + lx2)] = v0;
                        slabw[c*ES + ((32 ^ (sw & 32)) + lx2)] = v1;
                    }
                }
            }
            __syncwarp();

            // self-edge mask (phys-ordered e: q=e>>2, j=(q&1)*16+eg4+(e&3), r=q>>1)
            float vmv[16];
            #pragma unroll
            for (int e = 0; e < 16; e++) {
                int q = e >> 2;
                int j = (q & 1)*16 + eg4 + (e & 3);
                vmv[e] = (j == iR[q >> 1]) ? 0.f : 1.f;
            }

            ull acc[8][8];

            // -- GEMM1: m2 = silu(m1 @ We2 + be2), in-place over slab --
            wgemm(slabw, We2p, be2s, eg4, og, acc);
            __syncwarp();
            {
                float part[2][8];
                #pragma unroll
                for (int r = 0; r < 2; r++)
                    #pragma unroll
                    for (int s = 0; s < 8; s++) part[r][s] = 0.f;
                #pragma unroll
                for (int o = 0; o < 8; o++) {
                    int row = og*8 + o;
                    int swr = (row & 56) ^ ((row & 32) >> 2);
                    int exr = eg4 ^ (swr & 8);
                    int qbr = swr & 48;
                    float v[16];
                    #pragma unroll
                    for (int ep = 0; ep < 8; ep++) {
                        float2 f = unpackf2(acc[o][ep]);
                        v[2*ep]   = siluf(f.x);
                        v[2*ep+1] = siluf(f.y);
                    }
                    #pragma unroll
                    for (int e = 0; e < 16; e++)
                        part[e>>3][o] = fmaf(vmv[e], v[e], part[e>>3][o]);
                    float* rw = slabw + row*ES;
                    *(float4*)(rw + ((0  ^ qbr) + exr)) = make_float4(v[0], v[1], v[2], v[3]);
                    *(float4*)(rw + ((16 ^ qbr) + exr)) = make_float4(v[4], v[5], v[6], v[7]);
                    *(float4*)(rw + ((32 ^ qbr) + exr)) = make_float4(v[8], v[9], v[10], v[11]);
                    *(float4*)(rw + ((48 ^ qbr) + exr)) = make_float4(v[12], v[13], v[14], v[15]);
                }
                __syncwarp();
                // magg: reduce partials over eg (lane bits 3,4)
                #pragma unroll
                for (int r = 0; r < 2; r++) {
                    #pragma unroll
                    for (int s = 0; s < 8; s++) {
                        float vv = part[r][s];
                        vv += __shfl_xor_sync(0xffffffffu, vv, 8);
                        vv += __shfl_xor_sync(0xffffffffu, vv, 16);
                        if (lane < 8) maggS[iR[r]*HH + lane*8 + s] = vv;
                    }
                }
            }

            // -- GEMM2: t = silu(m2 @ Wc1 + bc1); cs = t.Wc2 + bc2 --
            wgemm(slabw, Wc1p, bc1s, eg4, og, acc);
            {
                float wc[8];
                *(float4*)(wc+0) = *(const float4*)(Wc2s + og*8);
                *(float4*)(wc+4) = *(const float4*)(Wc2s + og*8 + 4);
                float csp[16];
                #pragma unroll
                for (int e = 0; e < 16; e++) csp[e] = 0.f;
                #pragma unroll
                for (int o = 0; o < 8; o++) {
                    #pragma unroll
                    for (int ep = 0; ep < 8; ep++) {
                        float2 f = unpackf2(acc[o][ep]);
                        csp[2*ep]   = fmaf(siluf(f.x), wc[o], csp[2*ep]);
                        csp[2*ep+1] = fmaf(siluf(f.y), wc[o], csp[2*ep+1]);
                    }
                }
                #pragma unroll
                for (int e = 0; e < 16; e++) {
                    float vv = csp[e];
                    vv += __shfl_down_sync(0xffffffffu, vv, 4);
                    vv += __shfl_down_sync(0xffffffffu, vv, 2);
                    vv += __shfl_down_sync(0xffffffffu, vv, 1);
                    csp[e] = vv;
                }
                if (og == 0) {
                    #pragma unroll
                    for (int e = 0; e < 16; e++) {
                        int col = (e >> 2)*16 + eg4 + (e & 3);
                        csWw[col] = csp[e] + bc2l;
                    }
                }
            }
            __syncwarp();

            // -- trans aggregation (self-edge has dn = 0) --
            #pragma unroll
            for (int r = 0; r < 2; r++) {
                float cj = csWw[r*32 + lane];
                float tx = wredsum(dnx[r] * cj);
                float ty = wredsum(dny[r] * cj);
                if (lane == 0) { aggS[iR[r]*2+0] = tx; aggS[iR[r]*2+1] = ty; }
            }
            __syncwarp();
        }
        __syncthreads();

        // ==== restage node weights into edge slab ====
        {
            const float4* Wv1l = (const float4*)(Wv1 + l*HH*HH);
            const float4* Wn1l = (const float4*)(Wn1 + l*2*HH*HH);
            const float4* Wn2l = (const float4*)(Wn2 + l*HH*HH);
            float4* d = (float4*)edgeS;
            #pragma unroll
            for (int t = tid; t < 1024; t += 256) {
                d[t]        = Wv1l[t];
                d[t + 1024] = Wn1l[t];
                d[t + 2048] = Wn1l[t + 1024];
                d[t + 3072] = Wn2l[t];
            }
        }
        __syncthreads();
        const float* Wv1s = edgeS;
        const float* Wn1s = edgeS + HH*HH;
        const float* Wn2s = edgeS + 3*HH*HH;

        // ==== node phase: phi_v, vel/loc update ====
        {
            float a0[4], a1[4];
            #pragma unroll
            for (int r = 0; r < 4; r++) { a0[r] = bv1s[lane]; a1[r] = bv1s[lane+32]; }
            #pragma unroll 4
            for (int c = 0; c < HH; c++) {
                const float* wr = Wv1s + c*HH;
                float w0 = wr[lane], w1 = wr[lane+32];
                #pragma unroll
                for (int r = 0; r < 4; r++) {
                    float hv = hS[(w*4+r)*HS + c];
                    a0[r] += hv*w0; a1[r] += hv*w1;
                }
            }
            float wv2a = Wv2s[lane], wv2b = Wv2s[lane + 32];
            #pragma unroll
            for (int r = 0; r < 4; r++) {
                float part = wredsum(siluf(a0[r])*wv2a + siluf(a1[r])*wv2b);
                if (lane == 0) {
                    int i = w*4 + r;
                    float phi = part + bv2l;
                    float vx = phi*velS[i*2+0] + aggS[i*2+0]*(1.0f/31.0f);
                    float vy = phi*velS[i*2+1] + aggS[i*2+1]*(1.0f/31.0f);
                    velS[i*2+0] = vx; velS[i*2+1] = vy;
                    locS[i*2+0] += vx; locS[i*2+1] += vy;
                }
            }
        }

        // ==== U = silu([h, magg] @ Wn1 + bn1) -> AS ====
        {
            float a0[4], a1[4];
            #pragma unroll
            for (int r = 0; r < 4; r++) { a0[r] = bn1s[lane]; a1[r] = bn1s[lane+32]; }
            #pragma unroll 4
            for (int c = 0; c < HH; c++) {
                const float* wr = Wn1s + c*HH;
                float w0 = wr[lane], w1 = wr[lane+32];
                #pragma unroll
                for (int r = 0; r < 4; r++) {
                    float hv = hS[(w*4+r)*HS + c];
                    a0[r] += hv*w0; a1[r] += hv*w1;
                }
            }
            #pragma unroll 4
            for (int c = 0; c < HH; c++) {
                const float* wr = Wn1s + (HH + c)*HH;
                float w0 = wr[lane], w1 = wr[lane+32];
                #pragma unroll
                for (int r = 0; r < 4; r++) {
                    float mv = maggS[(w*4+r)*HH + c];
                    a0[r] += mv*w0; a1[r] += mv*w1;
                }
            }
            #pragma unroll
            for (int r = 0; r < 4; r++) {
                AS[(w*4+r)*HS + lane]      = siluf(a0[r]);
                AS[(w*4+r)*HS + lane + 32] = siluf(a1[r]);
            }
        }

        // ==== h += U @ Wn2 + bn2 ====
        {
            float a0[4], a1[4];
            #pragma unroll
            for (int r = 0; r < 4; r++) { a0[r] = bn2s[lane]; a1[r] = bn2s[lane+32]; }
            #pragma unroll 4
            for (int c = 0; c < HH; c++) {
                const float* wr = Wn2s + c*HH;
                float w0 = wr[lane], w1 = wr[lane+32];
                #pragma unroll
                for (int r = 0; r < 4; r++) {
                    float uv = AS[(w*4+r)*HS + c];
                    a0[r] += uv*w0; a1[r] += uv*w1;
                }
            }
            #pragma unroll
            for (int r = 0; r < 4; r++) {
                hS[(w*4+r)*HS + lane]      += a0[r];
                hS[(w*4+r)*HS + lane + 32] += a1[r];
            }
        }
        __syncthreads();
    }

    // ---- output ----
    if (tid < NA*2) {
        int i = tid >> 1, c = tid & 1;
        out[((size_t)g*NA + i)*2 + c] = scl[c]*velS[tid] + mn[c];
    }
}

extern "C" void kernel_launch(void* const* d_in, const int* in_sizes, int n_in,
                              void* d_out, int out_size) {
    const float* obs  = (const float*)d_in[0];
    const float* scl  = (const float*)d_in[3];
    const float* mn   = (const float*)d_in[4];
    const float* embW = (const float*)d_in[5];
    const float* embb = (const float*)d_in[6];
    const float* We1  = (const float*)d_in[7];
    const float* be1  = (const float*)d_in[8];
    const float* We2  = (const float*)d_in[9];
    const float* be2  = (const float*)d_in[10];
    const float* Wc1  = (const float*)d_in[11];
    const float* bc1  = (const float*)d_in[12];
    const float* Wc2  = (const float*)d_in[13];
    const float* bc2  = (const float*)d_in[14];
    const float* Wv1  = (const float*)d_in[15];
    const float* bv1  = (const float*)d_in[16];
    const float* Wv2  = (const float*)d_in[17];
    const float* bv2  = (const float*)d_in[18];
    const float* Wn1  = (const float*)d_in[19];
    const float* bn1  = (const float*)d_in[20];
    const float* Wn2  = (const float*)d_in[21];
    const float* bn2  = (const float*)d_in[22];
    float* out = (float*)d_out;

    int n_nodes = in_sizes[0] / OBSW;
    int groups  = n_nodes / NA;

    cudaFuncSetAttribute(egnn_kernel, cudaFuncAttributeMaxDynamicSharedMemorySize, SMEM_BYTES);
    egnn_kernel<<<groups, 256, SMEM_BYTES>>>(
        obs, scl, mn, embW, embb,
        We1, be1, We2, be2, Wc1, bc1, Wc2, bc2,
        Wv1, bv1, Wv2, bv2, Wn1, bn1, Wn2, bn2, out);
}

// round 7
// speedup vs baseline: 3.4378x; 1.0022x over previous
#include <cuda_runtime.h>

#define NA    32
#define HH    64
#define HS    68
#define NW    16
#define NT    512
#define SLAB  2048     // 64 k-rows x 32 edges per warp
#define NINV  16
#define NLAY  4
#define OBSW  20

#define SM_H     0
#define SM_A     (SM_H    + NA*HS)
#define SM_B     (SM_A    + NA*HS)
#define SM_MAGG  (SM_B    + NA*HS)
#define SM_EA    (SM_MAGG + NA*HH)
#define SM_WE2   (SM_EA   + NA*NA)
#define SM_WC1   (SM_WE2  + HH*HH)
#define SM_EDGE  (SM_WC1  + HH*HH)
#define SM_VEC   (SM_EDGE + NW*SLAB)
#define SM_LOC   (SM_VEC  + 10*HH)
#define SM_VEL   (SM_LOC  + 2*NA)
#define SM_AGG   (SM_VEL  + 2*NA)
#define SM_CS    (SM_AGG  + 2*NA)
#define SMEM_FLOATS (SM_CS + NW*NA)
#define SMEM_BYTES  (SMEM_FLOATS * 4)

#define V_W128 0
#define V_W129 1
#define V_BE1  2
#define V_BE2  3
#define V_BC1  4
#define V_WC2  5
#define V_BV1  6
#define V_BN1  7
#define V_BN2  8
#define V_WV2  9

typedef unsigned long long ull;

#define F4C(v,i) (((const float*)&(v))[i])

__device__ __forceinline__ float siluf(float x) {
    float hx = 0.5f * x;
    float t;
    asm("tanh.approx.f32 %0, %1;" : "=f"(t) : "f"(hx));
    return fmaf(hx, t, hx);
}

__device__ __forceinline__ ull packf2(float x) {
    unsigned int u = __float_as_uint(x);
    ull r;
    asm("mov.b64 %0, {%1, %1};" : "=l"(r) : "r"(u));
    return r;
}

__device__ __forceinline__ void fma2(ull &d, ull a, ull b) {
    asm("fma.rn.f32x2 %0, %1, %2, %0;" : "+l"(d) : "l"(a), "l"(b));
}

__device__ __forceinline__ float2 unpackf2(ull v) {
    unsigned int lo, hi;
    asm("mov.b64 {%0, %1}, %2;" : "=r"(lo), "=r"(hi) : "l"(v));
    return make_float2(__uint_as_float(lo), __uint_as_float(hi));
}

__device__ __forceinline__ float wredsum(float v) {
    v += __shfl_down_sync(0xffffffffu, v, 16);
    v += __shfl_down_sync(0xffffffffu, v, 8);
    v += __shfl_down_sync(0xffffffffu, v, 4);
    v += __shfl_down_sync(0xffffffffu, v, 2);
    v += __shfl_down_sync(0xffffffffu, v, 1);
    return v;
}

// 32 edges x 64 outputs, K=64. Lane (eg,og): 8 edges x 8 outputs.
// acc[o][ep]: output og*8+o, edge-pair ep over edges eg*8..eg*8+7.
// Slab swizzle at float4 granularity: phys_f4 = logical_f4 ^ ((row>>3)&7).
__device__ __forceinline__ void wgemm32(const float* __restrict__ slab,
                                        const float* __restrict__ Wp,
                                        const float* __restrict__ bias,
                                        int eg2, int og, ull (&acc)[8][4])
{
    {
        float b[8];
        *(float4*)(b+0) = *(const float4*)(bias + og*8);
        *(float4*)(b+4) = *(const float4*)(bias + og*8 + 4);
        #pragma unroll
        for (int o = 0; o < 8; o++) {
            ull bp = packf2(b[o]);
            acc[o][0] = bp; acc[o][1] = bp; acc[o][2] = bp; acc[o][3] = bp;
        }
    }
    #pragma unroll 1
    for (int kt = 0; kt < 8; kt++) {
        const float* rowk = slab + kt*8*32;
        const float* wpk  = Wp + kt*8*64;
        const int o0 = ((eg2    ) ^ kt) * 4;
        const int o1 = ((eg2 + 1) ^ kt) * 4;
        #pragma unroll
        for (int u = 0; u < 8; u++) {
            const float* r = rowk + u*32;
            ulonglong2 p0 = *(const ulonglong2*)(r + o0);
            ulonglong2 p1 = *(const ulonglong2*)(r + o1);
            float wv[8];
            *(float4*)(wv+0) = *(const float4*)(wpk + u*64 + og*4);
            *(float4*)(wv+4) = *(const float4*)(wpk + u*64 + 32 + og*4);
            #pragma unroll
            for (int o = 0; o < 8; o++) {
                ull wq = packf2(wv[o]);
                fma2(acc[o][0], wq, p0.x);
                fma2(acc[o][1], wq, p0.y);
                fma2(acc[o][2], wq, p1.x);
                fma2(acc[o][3], wq, p1.y);
            }
        }
    }
}

__global__ void __launch_bounds__(NT, 1)
egnn_kernel(const float* __restrict__ obs,
            const float* __restrict__ scl,
            const float* __restrict__ mn,
            const float* __restrict__ embW,
            const float* __restrict__ embb,
            const float* __restrict__ We1,
            const float* __restrict__ be1,
            const float* __restrict__ We2,
            const float* __restrict__ be2,
            const float* __restrict__ Wc1,
            const float* __restrict__ bc1,
            const float* __restrict__ Wc2,
            const float* __restrict__ bc2,
            const float* __restrict__ Wv1,
            const float* __restrict__ bv1,
            const float* __restrict__ Wv2,
            const float* __restrict__ bv2,
            const float* __restrict__ Wn1,
            const float* __restrict__ bn1,
            const float* __restrict__ Wn2,
            const float* __restrict__ bn2,
            float* __restrict__ out)
{
    extern __shared__ float sm[];
    float* hS    = sm + SM_H;
    float* AS    = sm + SM_A;
    float* BS    = sm + SM_B;
    float* maggS = sm + SM_MAGG;
    float* eaS   = sm + SM_EA;
    float* We2p  = sm + SM_WE2;
    float* Wc1p  = sm + SM_WC1;
    float* edgeS = sm + SM_EDGE;
    float* vecS  = sm + SM_VEC;
    float* locS  = sm + SM_LOC;
    float* velS  = sm + SM_VEL;
    float* aggS  = sm + SM_AGG;
    float* csS   = sm + SM_CS;

    float* w128s = vecS + V_W128*HH;
    float* w129s = vecS + V_W129*HH;
    float* be1s  = vecS + V_BE1*HH;
    float* be2s  = vecS + V_BE2*HH;
    float* bc1s  = vecS + V_BC1*HH;
    float* Wc2s  = vecS + V_WC2*HH;
    float* bv1s  = vecS + V_BV1*HH;
    float* bn1s  = vecS + V_BN1*HH;
    float* bn2s  = vecS + V_BN2*HH;
    float* Wv2s  = vecS + V_WV2*HH;

    const int tid  = threadIdx.x;
    const int w    = tid >> 5;         // 0..15
    const int lane = tid & 31;
    const int eg   = lane >> 3;        // 0..3
    const int og   = lane & 7;         // 0..7
    const int eg2  = eg * 2;
    const int g    = blockIdx.x;

    float* slabw = edgeS + w * SLAB;
    float* csWw  = csS + w * NA;

    // ---- stage obs into BS scratch ----
    const float* obsg = obs + (size_t)g * NA * OBSW;
    for (int t = tid; t < NA*OBSW; t += NT) BS[t] = obsg[t];
    __syncthreads();

    if (tid < NA*2) {
        int i = tid >> 1, c = tid & 1;
        locS[tid] = BS[i*OBSW + NINV + c];
        velS[tid] = BS[i*OBSW + NINV + 2 + c];
    }
    __syncthreads();

    for (int p = tid; p < NA*NA; p += NT) {
        int i = p >> 5, j = p & 31;
        float dx = locS[i*2+0] - locS[j*2+0];
        float dy = locS[i*2+1] - locS[j*2+1];
        eaS[p] = dx*dx + dy*dy;
    }

    // h = inv @ embW + embb  (warp w: rows 2w, 2w+1)
    {
        float a0[2], a1[2];
        #pragma unroll
        for (int r = 0; r < 2; r++) { a0[r] = embb[lane]; a1[r] = embb[lane+32]; }
        #pragma unroll
        for (int c = 0; c < NINV; c++) {
            float w0 = embW[c*HH + lane];
            float w1 = embW[c*HH + lane + 32];
            #pragma unroll
            for (int r = 0; r < 2; r++) {
                float iv = BS[(w*2+r)*OBSW + c];
                a0[r] += iv*w0; a1[r] += iv*w1;
            }
        }
        #pragma unroll
        for (int r = 0; r < 2; r++) {
            hS[(w*2+r)*HS + lane]      = a0[r];
            hS[(w*2+r)*HS + lane + 32] = a1[r];
        }
    }
    __syncthreads();

    #pragma unroll 1
    for (int l = 0; l < NLAY; l++) {
        // ==== stage per-layer weights ====
        {
            const float4* We2l = (const float4*)(We2 + l*HH*HH);
            const float4* Wc1l = (const float4*)(Wc1 + l*HH*HH);
            float4* d2 = (float4*)We2p;
            float4* dc = (float4*)Wc1p;
            #pragma unroll
            for (int t = tid; t < 1024; t += NT) {
                int k = t >> 4, o4 = t & 15;
                int ogx = o4 >> 1, h = o4 & 1;
                int dst = k*16 + h*8 + ogx;
                d2[dst] = We2l[t];
                dc[dst] = Wc1l[t];
            }
            const float4* We1l = (const float4*)(We1 + l*130*HH);
            float4* scr = (float4*)edgeS;
            #pragma unroll
            for (int t = tid; t < 2048; t += NT) scr[t] = We1l[t];
            if (tid < HH) {
                w128s[tid] = We1[(l*130 + 128)*HH + tid];
                w129s[tid] = We1[(l*130 + 129)*HH + tid];
                be1s[tid]  = be1[l*HH + tid];
                be2s[tid]  = be2[l*HH + tid];
                bc1s[tid]  = bc1[l*HH + tid];
                Wc2s[tid]  = Wc2[l*HH + tid];
                bv1s[tid]  = bv1[l*HH + tid];
                bn1s[tid]  = bn1[l*HH + tid];
                bn2s[tid]  = bn2[l*HH + tid];
                Wv2s[tid]  = Wv2[l*HH + tid];
            }
        }
        const float bc2l = bc2[l];
        const float bv2l = bv2[l];
        __syncthreads();

        // ==== phase A: A = h@We1A + be1, B = h@We1B (rows 2w, 2w+1) ====
        {
            const float* We1As = edgeS;
            const float* We1Bs = edgeS + HH*HH;
            float a0[2], a1[2], b0[2], b1[2];
            #pragma unroll
            for (int r = 0; r < 2; r++) {
                a0[r] = be1s[lane]; a1[r] = be1s[lane + 32];
                b0[r] = 0.f; b1[r] = 0.f;
            }
            #pragma unroll 8
            for (int c = 0; c < HH; c++) {
                const float* wrA = We1As + c*HH;
                const float* wrB = We1Bs + c*HH;
                float wa0 = wrA[lane], wa1 = wrA[lane+32];
                float wb0 = wrB[lane], wb1 = wrB[lane+32];
                #pragma unroll
                for (int r = 0; r < 2; r++) {
                    float hv = hS[(w*2+r)*HS + c];
                    a0[r] += hv*wa0; a1[r] += hv*wa1;
                    b0[r] += hv*wb0; b1[r] += hv*wb1;
                }
            }
            #pragma unroll
            for (int r = 0; r < 2; r++) {
                AS[(w*2+r)*HS + lane]      = a0[r];
                AS[(w*2+r)*HS + lane + 32] = a1[r];
                BS[(w*2+r)*HS + lane]      = b0[r];
                BS[(w*2+r)*HS + lane + 32] = b1[r];
            }
        }
        __syncthreads();

        // ==== edge phase: warp = one receiver per iteration ====
        #pragma unroll 1
        for (int it = 0; it < 2; it++) {
            const int i = it*NW + w;

            // -- m1 construction: lane = sender j --
            float dnx, dny;
            {
                const int j = lane;
                float dx = locS[i*2+0] - locS[j*2+0];
                float dy = locS[i*2+1] - locS[j*2+1];
                float rad = dx*dx + dy*dy;
                float invr = __fdividef(1.0f, sqrtf(rad) + 1.0f);
                dnx = dx * invr; dny = dy * invr;
                float eav = eaS[i*NA + j];
                const float* Ai = AS + i*HS;
                const float* Bj = BS + j*HS;
                const int jq = j >> 2, jr = j & 3;
                #pragma unroll
                for (int c4 = 0; c4 < 16; c4++) {
                    float4 wA = *(const float4*)(w128s + c4*4);
                    float4 wB = *(const float4*)(w129s + c4*4);
                    float4 a4 = *(const float4*)(Ai + c4*4);
                    float4 b4 = *(const float4*)(Bj + c4*4);
                    const int base = ((jq ^ (c4 >> 1)) * 4) + jr;
                    #pragma unroll
                    for (int cc = 0; cc < 4; cc++) {
                        float v = F4C(a4,cc) + F4C(b4,cc)
                                + rad * F4C(wA,cc) + eav * F4C(wB,cc);
                        slabw[(c4*4+cc)*32 + base] = siluf(v);
                    }
                }
            }
            __syncwarp();

            ull acc[8][4];

            // -- GEMM1: m2 = silu(m1 @ We2 + be2), in-place --
            wgemm32(slabw, We2p, be2s, eg2, og, acc);
            __syncwarp();
            {
                float vmv[8];
                #pragma unroll
                for (int e = 0; e < 8; e++) vmv[e] = (eg*8 + e == i) ? 0.f : 1.f;
                float part[8];
                #pragma unroll
                for (int o = 0; o < 8; o++) {
                    float2 f0 = unpackf2(acc[o][0]);
                    float2 f1 = unpackf2(acc[o][1]);
                    float2 f2 = unpackf2(acc[o][2]);
                    float2 f3 = unpackf2(acc[o][3]);
                    float v0 = siluf(f0.x), v1 = siluf(f0.y);
                    float v2 = siluf(f1.x), v3 = siluf(f1.y);
                    float v4 = siluf(f2.x), v5 = siluf(f2.y);
                    float v6 = siluf(f3.x), v7 = siluf(f3.y);
                    float p = vmv[0]*v0;
                    p = fmaf(vmv[1], v1, p); p = fmaf(vmv[2], v2, p);
                    p = fmaf(vmv[3], v3, p); p = fmaf(vmv[4], v4, p);
                    p = fmaf(vmv[5], v5, p); p = fmaf(vmv[6], v6, p);
                    p = fmaf(vmv[7], v7, p);
                    part[o] = p;
                    const int row = og*8 + o;       // row>>3 == og
                    float* rw = slabw + row*32;
                    *(float4*)(rw + (eg2 ^ og)*4)     = make_float4(v0, v1, v2, v3);
                    *(float4*)(rw + ((eg2+1) ^ og)*4) = make_float4(v4, v5, v6, v7);
                }
                __syncwarp();
                #pragma unroll
                for (int o = 0; o < 8; o++) {
                    part[o] += __shfl_xor_sync(0xffffffffu, part[o], 8);
                    part[o] += __shfl_xor_sync(0xffffffffu, part[o], 16);
                }
                if (eg == 0) {
                    *(float4*)(maggS + i*HH + og*8)     = make_float4(part[0], part[1], part[2], part[3]);
                    *(float4*)(maggS + i*HH + og*8 + 4) = make_float4(part[4], part[5], part[6], part[7]);
                }
            }

            // -- GEMM2: t = silu(m2 @ Wc1 + bc1); cs = t.Wc2 + bc2 --
            wgemm32(slabw, Wc1p, bc1s, eg2, og, acc);
            {
                float wc[8];
                *(float4*)(wc+0) = *(const float4*)(Wc2s + og*8);
                *(float4*)(wc+4) = *(const float4*)(Wc2s + og*8 + 4);
                float csp[8];
                #pragma unroll
                for (int e = 0; e < 8; e++) csp[e] = 0.f;
                #pragma unroll
                for (int o = 0; o < 8; o++) {
                    float2 f0 = unpackf2(acc[o][0]);
                    float2 f1 = unpackf2(acc[o][1]);
                    float2 f2 = unpackf2(acc[o][2]);
                    float2 f3 = unpackf2(acc[o][3]);
                    csp[0] = fmaf(siluf(f0.x), wc[o], csp[0]);
                    csp[1] = fmaf(siluf(f0.y), wc[o], csp[1]);
                    csp[2] = fmaf(siluf(f1.x), wc[o], csp[2]);
                    csp[3] = fmaf(siluf(f1.y), wc[o], csp[3]);
                    csp[4] = fmaf(siluf(f2.x), wc[o], csp[4]);
                    csp[5] = fmaf(siluf(f2.y), wc[o], csp[5]);
                    csp[6] = fmaf(siluf(f3.x), wc[o], csp[6]);
                    csp[7] = fmaf(siluf(f3.y), wc[o], csp[7]);
                }
                #pragma unroll
                for (int e = 0; e < 8; e++) {
                    float vv = csp[e];
                    vv += __shfl_down_sync(0xffffffffu, vv, 4);
                    vv += __shfl_down_sync(0xffffffffu, vv, 2);
                    vv += __shfl_down_sync(0xffffffffu, vv, 1);
                    csp[e] = vv;
                }
                if (og == 0) {
                    *(float4*)(csWw + eg*8) =
                        make_float4(csp[0]+bc2l, csp[1]+bc2l, csp[2]+bc2l, csp[3]+bc2l);
                    *(float4*)(csWw + eg*8 + 4) =
                        make_float4(csp[4]+bc2l, csp[5]+bc2l, csp[6]+bc2l, csp[7]+bc2l);
                }
            }
            __syncwarp();

            // -- trans aggregation (self-edge has dn = 0) --
            {
                float cj = csWw[lane];
                float tx = wredsum(dnx * cj);
                float ty = wredsum(dny * cj);
                if (lane == 0) { aggS[i*2+0] = tx; aggS[i*2+1] = ty; }
            }
            __syncwarp();
        }
        __syncthreads();

        // ==== restage node weights into edge slab scratch ====
        {
            const float4* Wv1l = (const float4*)(Wv1 + l*HH*HH);
            const float4* Wn1l = (const float4*)(Wn1 + l*2*HH*HH);
            const float4* Wn2l = (const float4*)(Wn2 + l*HH*HH);
            float4* d = (float4*)edgeS;
            #pragma unroll
            for (int t = tid; t < 1024; t += NT) {
                d[t]        = Wv1l[t];
                d[t + 1024] = Wn1l[t];
                d[t + 2048] = Wn1l[t + 1024];
                d[t + 3072] = Wn2l[t];
            }
        }
        __syncthreads();
        const float* Wv1s = edgeS;
        const float* Wn1s = edgeS + HH*HH;
        const float* Wn2s = edgeS + 3*HH*HH;

        // ==== node phase: phi_v, vel/loc update (rows 2w, 2w+1) ====
        {
            float a0[2], a1[2];
            #pragma unroll
            for (int r = 0; r < 2; r++) { a0[r] = bv1s[lane]; a1[r] = bv1s[lane+32]; }
            #pragma unroll 8
            for (int c = 0; c < HH; c++) {
                const float* wr = Wv1s + c*HH;
                float w0 = wr[lane], w1 = wr[lane+32];
                #pragma unroll
                for (int r = 0; r < 2; r++) {
                    float hv = hS[(w*2+r)*HS + c];
                    a0[r] += hv*w0; a1[r] += hv*w1;
                }
            }
            float wv2a = Wv2s[lane], wv2b = Wv2s[lane + 32];
            #pragma unroll
            for (int r = 0; r < 2; r++) {
                float part = wredsum(siluf(a0[r])*wv2a + siluf(a1[r])*wv2b);
                if (lane == 0) {
                    int i = w*2 + r;
                    float phi = part + bv2l;
                    float vx = phi*velS[i*2+0] + aggS[i*2+0]*(1.0f/31.0f);
                    float vy = phi*velS[i*2+1] + aggS[i*2+1]*(1.0f/31.0f);
                    velS[i*2+0] = vx; velS[i*2+1] = vy;
                    locS[i*2+0] += vx; locS[i*2+1] += vy;
                }
            }
        }

        // ==== U = silu([h, magg] @ Wn1 + bn1) -> AS ====
        {
            float a0[2], a1[2];
            #pragma unroll
            for (int r = 0; r < 2; r++) { a0[r] = bn1s[lane]; a1[r] = bn1s[lane+32]; }
            #pragma unroll 8
            for (int c = 0; c < HH; c++) {
                const float* wr = Wn1s + c*HH;
                float w0 = wr[lane], w1 = wr[lane+32];
                #pragma unroll
                for (int r = 0; r < 2; r++) {
                    float hv = hS[(w*2+r)*HS + c];
                    a0[r] += hv*w0; a1[r] += hv*w1;
                }
            }
            #pragma unroll 8
            for (int c = 0; c < HH; c++) {
                const float* wr = Wn1s + (HH + c)*HH;
                float w0 = wr[lane], w1 = wr[lane+32];
                #pragma unroll
                for (int r = 0; r < 2; r++) {
                    float mv = maggS[(w*2+r)*HH + c];
                    a0[r] += mv*w0; a1[r] += mv*w1;
                }
            }
            #pragma unroll
            for (int r = 0; r < 2; r++) {
                AS[(w*2+r)*HS + lane]      = siluf(a0[r]);
                AS[(w*2+r)*HS + lane + 32] = siluf(a1[r]);
            }
        }

        // ==== h += U @ Wn2 + bn2 ====  (warp-local rows)
        {
            float a0[2], a1[2];
            #pragma unroll
            for (int r = 0; r < 2; r++) { a0[r] = bn2s[lane]; a1[r] = bn2s[lane+32]; }
            #pragma unroll 8
            for (int c = 0; c < HH; c++) {
                const float* wr = Wn2s + c*HH;
                float w0 = wr[lane], w1 = wr[lane+32];
                #pragma unroll
                for (int r = 0; r < 2; r++) {
                    float uv = AS[(w*2+r)*HS + c];
                    a0[r] += uv*w0; a1[r] += uv*w1;
                }
            }
            #pragma unroll
            for (int r = 0; r < 2; r++) {
                hS[(w*2+r)*HS + lane]      += a0[r];
                hS[(w*2+r)*HS + lane + 32] += a1[r];
            }
        }
        __syncthreads();
    }

    // ---- output ----
    if (tid < NA*2) {
        int i = tid >> 1, c = tid & 1;
        out[((size_t)g*NA + i)*2 + c] = scl[c]*velS[tid] + mn[c];
    }
}

extern "C" void kernel_launch(void* const* d_in, const int* in_sizes, int n_in,
                              void* d_out, int out_size) {
    const float* obs  = (const float*)d_in[0];
    const float* scl  = (const float*)d_in[3];
    const float* mn   = (const float*)d_in[4];
    const float* embW = (const float*)d_in[5];
    const float* embb = (const float*)d_in[6];
    const float* We1  = (const float*)d_in[7];
    const float* be1  = (const float*)d_in[8];
    const float* We2  = (const float*)d_in[9];
    const float* be2  = (const float*)d_in[10];
    const float* Wc1  = (const float*)d_in[11];
    const float* bc1  = (const float*)d_in[12];
    const float* Wc2  = (const float*)d_in[13];
    const float* bc2  = (const float*)d_in[14];
    const float* Wv1  = (const float*)d_in[15];
    const float* bv1  = (const float*)d_in[16];
    const float* Wv2  = (const float*)d_in[17];
    const float* bv2  = (const float*)d_in[18];
    const float* Wn1  = (const float*)d_in[19];
    const float* bn1  = (const float*)d_in[20];
    const float* Wn2  = (const float*)d_in[21];
    const float* bn2  = (const float*)d_in[22];
    float* out = (float*)d_out;

    int n_nodes = in_sizes[0] / OBSW;
    int groups  = n_nodes / NA;

    cudaFuncSetAttribute(egnn_kernel, cudaFuncAttributeMaxDynamicSharedMemorySize, SMEM_BYTES);
    egnn_kernel<<<groups, NT, SMEM_BYTES>>>(
        obs, scl, mn, embW, embb,
        We1, be1, We2, be2, Wc1, bc1, Wc2, bc2,
        Wv1, bv1, Wv2, bv2, Wn1, bn1, Wn2, bn2, out);
}

// round 8
// speedup vs baseline: 4.4671x; 1.2994x over previous
#include <cuda_runtime.h>

#define NA    32
#define HH    64
#define HS    68      // h/A/B row stride
#define SS    68      // slab row stride (floats)
#define WPS   68      // weight-pair row stride (in float2)
#define NW    8
#define NT    256
#define NINV  16
#define NLAY  4
#define OBSW  20

#define SM_H     0
#define SM_A     (SM_H    + NA*HS)
#define SM_B     (SM_A    + NA*HS)
#define SM_MAGG  (SM_B    + NA*HS)
#define SM_EA    (SM_MAGG + NA*HH)
#define SM_W2P   (SM_EA   + NA*NA)        // We2 (hi,lo) pairs: 64*WPS float2
#define SM_WCP   (SM_W2P  + 2*64*WPS)     // Wc1 (hi,lo) pairs
#define SM_SLAB  (SM_WCP  + 2*64*WPS)     // 8 warps x 32x68 (also weight scratch)
#define SM_VEC   (SM_SLAB + NW*NA*SS)
#define SM_LOC   (SM_VEC  + 10*HH)
#define SM_VEL   (SM_LOC  + 2*NA)
#define SM_AGG   (SM_VEL  + 2*NA)
#define SM_CS    (SM_AGG  + 2*NA)
#define SMEM_FLOATS (SM_CS + NW*NA)
#define SMEM_BYTES  (SMEM_FLOATS * 4)

#define V_W128 0
#define V_W129 1
#define V_BE1  2
#define V_BE2  3
#define V_BC1  4
#define V_WC2  5
#define V_BV1  6
#define V_BN1  7
#define V_BN2  8
#define V_WV2  9

#define F4C(v,i) (((const float*)&(v))[i])

__device__ __forceinline__ float siluf(float x) {
    float hx = 0.5f * x;
    float t;
    asm("tanh.approx.f32 %0, %1;" : "=f"(t) : "f"(hx));
    return fmaf(hx, t, hx);
}

__device__ __forceinline__ unsigned rna_u(float x) {
    unsigned u;
    asm("cvt.rna.tf32.f32 %0, %1;" : "=r"(u) : "f"(x));
    return u;
}
__device__ __forceinline__ float rna_f(float x) { return __uint_as_float(rna_u(x)); }

__device__ __forceinline__ void mma8(float &d0, float &d1, float &d2, float &d3,
                                     unsigned a0, unsigned a1, unsigned a2, unsigned a3,
                                     unsigned b0, unsigned b1) {
    asm volatile(
        "mma.sync.aligned.m16n8k8.row.col.f32.tf32.tf32.f32 "
        "{%0,%1,%2,%3},{%4,%5,%6,%7},{%8,%9},{%0,%1,%2,%3};"
        : "+f"(d0), "+f"(d1), "+f"(d2), "+f"(d3)
        : "r"(a0), "r"(a1), "r"(a2), "r"(a3), "r"(b0), "r"(b1));
}

__device__ __forceinline__ float wredsum(float v) {
    v += __shfl_down_sync(0xffffffffu, v, 16);
    v += __shfl_down_sync(0xffffffffu, v, 8);
    v += __shfl_down_sync(0xffffffffu, v, 4);
    v += __shfl_down_sync(0xffffffffu, v, 2);
    v += __shfl_down_sync(0xffffffffu, v, 1);
    return v;
}

// D[32][64] = slab[32e][64k] @ (Whi + Wlo)[64k][64n] + bias.
// Fragments: A row-major m16n8k8, lane(g = lane>>2, t = lane&3).
__device__ __forceinline__ void mma_gemm(const unsigned* __restrict__ slabU,
                                         const float2* __restrict__ Wp,
                                         const float* __restrict__ bias,
                                         int g, int t, float (&acc)[2][8][4])
{
    #pragma unroll
    for (int nt = 0; nt < 8; nt++) {
        float2 b = *(const float2*)(bias + nt*8 + 2*t);
        #pragma unroll
        for (int mt = 0; mt < 2; mt++) {
            acc[mt][nt][0] = b.x; acc[mt][nt][1] = b.y;
            acc[mt][nt][2] = b.x; acc[mt][nt][3] = b.y;
        }
    }
    #pragma unroll
    for (int kt = 0; kt < 8; kt++) {
        unsigned a[2][4];
        #pragma unroll
        for (int mt = 0; mt < 2; mt++) {
            const unsigned* base = slabU + (mt*16 + g)*SS + kt*8 + t;
            a[mt][0] = base[0];
            a[mt][1] = base[8*SS];
            a[mt][2] = base[4];
            a[mt][3] = base[8*SS + 4];
        }
        const float2* wr0 = Wp + (kt*8 + t)*WPS + g;
        const float2* wr1 = wr0 + 4*WPS;
        #pragma unroll
        for (int nt = 0; nt < 8; nt++) {
            float2 p0 = wr0[nt*8];
            float2 p1 = wr1[nt*8];
            unsigned h0 = __float_as_uint(p0.x), l0 = __float_as_uint(p0.y);
            unsigned h1 = __float_as_uint(p1.x), l1 = __float_as_uint(p1.y);
            #pragma unroll
            for (int mt = 0; mt < 2; mt++) {
                mma8(acc[mt][nt][0], acc[mt][nt][1], acc[mt][nt][2], acc[mt][nt][3],
                     a[mt][0], a[mt][1], a[mt][2], a[mt][3], h0, h1);
                mma8(acc[mt][nt][0], acc[mt][nt][1], acc[mt][nt][2], acc[mt][nt][3],
                     a[mt][0], a[mt][1], a[mt][2], a[mt][3], l0, l1);
            }
        }
    }
}

__global__ void __launch_bounds__(NT, 1)
egnn_kernel(const float* __restrict__ obs,
            const float* __restrict__ scl,
            const float* __restrict__ mn,
            const float* __restrict__ embW,
            const float* __restrict__ embb,
            const float* __restrict__ We1,
            const float* __restrict__ be1,
            const float* __restrict__ We2,
            const float* __restrict__ be2,
            const float* __restrict__ Wc1,
            const float* __restrict__ bc1,
            const float* __restrict__ Wc2,
            const float* __restrict__ bc2,
            const float* __restrict__ Wv1,
            const float* __restrict__ bv1,
            const float* __restrict__ Wv2,
            const float* __restrict__ bv2,
            const float* __restrict__ Wn1,
            const float* __restrict__ bn1,
            const float* __restrict__ Wn2,
            const float* __restrict__ bn2,
            float* __restrict__ out)
{
    extern __shared__ float sm[];
    float* hS    = sm + SM_H;
    float* AS    = sm + SM_A;
    float* BS    = sm + SM_B;
    float* maggS = sm + SM_MAGG;
    float* eaS   = sm + SM_EA;
    float2* W2P  = (float2*)(sm + SM_W2P);
    float2* WCP  = (float2*)(sm + SM_WCP);
    float* slabF = sm + SM_SLAB;
    float* vecS  = sm + SM_VEC;
    float* locS  = sm + SM_LOC;
    float* velS  = sm + SM_VEL;
    float* aggS  = sm + SM_AGG;
    float* csS   = sm + SM_CS;

    float* w128s = vecS + V_W128*HH;
    float* w129s = vecS + V_W129*HH;
    float* be1s  = vecS + V_BE1*HH;
    float* be2s  = vecS + V_BE2*HH;
    float* bc1s  = vecS + V_BC1*HH;
    float* Wc2s  = vecS + V_WC2*HH;
    float* bv1s  = vecS + V_BV1*HH;
    float* bn1s  = vecS + V_BN1*HH;
    float* bn2s  = vecS + V_BN2*HH;
    float* Wv2s  = vecS + V_WV2*HH;

    const int tid  = threadIdx.x;
    const int w    = tid >> 5;         // 0..7
    const int lane = tid & 31;
    const int g    = lane >> 2;        // 0..7
    const int t    = lane & 3;         // 0..3
    const int gidx = blockIdx.x;

    unsigned* slabU = (unsigned*)(slabF + w * (NA*SS));
    float* csWw = csS + w * NA;

    // ---- stage obs into BS scratch ----
    const float* obsg = obs + (size_t)gidx * NA * OBSW;
    for (int q = tid; q < NA*OBSW; q += NT) BS[q] = obsg[q];
    __syncthreads();

    if (tid < NA*2) {
        int i = tid >> 1, c = tid & 1;
        locS[tid] = BS[i*OBSW + NINV + c];
        velS[tid] = BS[i*OBSW + NINV + 2 + c];
    }
    __syncthreads();

    for (int p = tid; p < NA*NA; p += NT) {
        int i = p >> 5, j = p & 31;
        float dx = locS[i*2+0] - locS[j*2+0];
        float dy = locS[i*2+1] - locS[j*2+1];
        eaS[p] = dx*dx + dy*dy;
    }

    // h = inv @ embW + embb  (warp w: rows 4w..4w+3)
    {
        float a0[4], a1[4];
        #pragma unroll
        for (int r = 0; r < 4; r++) { a0[r] = embb[lane]; a1[r] = embb[lane+32]; }
        #pragma unroll
        for (int c = 0; c < NINV; c++) {
            float w0 = embW[c*HH + lane];
            float w1 = embW[c*HH + lane + 32];
            #pragma unroll
            for (int r = 0; r < 4; r++) {
                float iv = BS[(w*4+r)*OBSW + c];
                a0[r] += iv*w0; a1[r] += iv*w1;
            }
        }
        #pragma unroll
        for (int r = 0; r < 4; r++) {
            hS[(w*4+r)*HS + lane]      = a0[r];
            hS[(w*4+r)*HS + lane + 32] = a1[r];
        }
    }
    __syncthreads();

    #pragma unroll 1
    for (int l = 0; l < NLAY; l++) {
        // ==== stage edge weights as tf32 (hi,lo) pairs + We1 + vectors ====
        {
            const float4* s2 = (const float4*)(We2 + l*HH*HH);
            const float4* sc = (const float4*)(Wc1 + l*HH*HH);
            for (int t4 = tid; t4 < 1024; t4 += NT) {
                int k = t4 >> 4, n0 = (t4 & 15) * 4;
                float4 w2 = s2[t4], wc = sc[t4];
                float2* p2 = W2P + k*WPS + n0;
                float2* pc = WCP + k*WPS + n0;
                float h;
                h = rna_f(w2.x); p2[0] = make_float2(h, rna_f(w2.x - h));
                h = rna_f(w2.y); p2[1] = make_float2(h, rna_f(w2.y - h));
                h = rna_f(w2.z); p2[2] = make_float2(h, rna_f(w2.z - h));
                h = rna_f(w2.w); p2[3] = make_float2(h, rna_f(w2.w - h));
                h = rna_f(wc.x); pc[0] = make_float2(h, rna_f(wc.x - h));
                h = rna_f(wc.y); pc[1] = make_float2(h, rna_f(wc.y - h));
                h = rna_f(wc.z); pc[2] = make_float2(h, rna_f(wc.z - h));
                h = rna_f(wc.w); pc[3] = make_float2(h, rna_f(wc.w - h));
            }
            const float4* We1l = (const float4*)(We1 + l*130*HH);
            float4* scr = (float4*)slabF;
            for (int q = tid; q < 2048; q += NT) scr[q] = We1l[q];
            if (tid < HH) {
                w128s[tid] = We1[(l*130 + 128)*HH + tid];
                w129s[tid] = We1[(l*130 + 129)*HH + tid];
                be1s[tid]  = be1[l*HH + tid];
                be2s[tid]  = be2[l*HH + tid];
                bc1s[tid]  = bc1[l*HH + tid];
                Wc2s[tid]  = Wc2[l*HH + tid];
                bv1s[tid]  = bv1[l*HH + tid];
                bn1s[tid]  = bn1[l*HH + tid];
                bn2s[tid]  = bn2[l*HH + tid];
                Wv2s[tid]  = Wv2[l*HH + tid];
            }
        }
        const float bc2l = bc2[l];
        const float bv2l = bv2[l];
        __syncthreads();

        // ==== phase A: A = h@We1A + be1, B = h@We1B ====
        {
            const float* We1As = slabF;
            const float* We1Bs = slabF + HH*HH;
            float a0[4], a1[4], b0[4], b1[4];
            #pragma unroll
            for (int r = 0; r < 4; r++) {
                a0[r] = be1s[lane]; a1[r] = be1s[lane + 32];
                b0[r] = 0.f; b1[r] = 0.f;
            }
            #pragma unroll 4
            for (int c = 0; c < HH; c++) {
                const float* wrA = We1As + c*HH;
                const float* wrB = We1Bs + c*HH;
                float wa0 = wrA[lane], wa1 = wrA[lane+32];
                float wb0 = wrB[lane], wb1 = wrB[lane+32];
                #pragma unroll
                for (int r = 0; r < 4; r++) {
                    float hv = hS[(w*4+r)*HS + c];
                    a0[r] += hv*wa0; a1[r] += hv*wa1;
                    b0[r] += hv*wb0; b1[r] += hv*wb1;
                }
            }
            #pragma unroll
            for (int r = 0; r < 4; r++) {
                AS[(w*4+r)*HS + lane]      = a0[r];
                AS[(w*4+r)*HS + lane + 32] = a1[r];
                BS[(w*4+r)*HS + lane]      = b0[r];
                BS[(w*4+r)*HS + lane + 32] = b1[r];
            }
        }
        __syncthreads();

        // ==== edge phase: warp = one receiver per iteration, 4 iterations ====
        #pragma unroll 1
        for (int it = 0; it < 4; it++) {
            const int i = it*NW + w;

            // -- m1 construction (lane = sender j) -> slab [e][k], tf32-rounded --
            float dnx, dny;
            {
                const int j = lane;
                float dx = locS[i*2+0] - locS[j*2+0];
                float dy = locS[i*2+1] - locS[j*2+1];
                float rad = dx*dx + dy*dy;
                float invr = __fdividef(1.0f, sqrtf(rad) + 1.0f);
                dnx = dx * invr; dny = dy * invr;
                float eav = eaS[i*NA + j];
                const float* Ai = AS + i*HS;
                const float* Bj = BS + j*HS;
                unsigned* srow = slabU + j*SS;
                #pragma unroll
                for (int c4 = 0; c4 < 16; c4++) {
                    float4 wA = *(const float4*)(w128s + c4*4);
                    float4 wB = *(const float4*)(w129s + c4*4);
                    float4 a4 = *(const float4*)(Ai + c4*4);
                    float4 b4 = *(const float4*)(Bj + c4*4);
                    uint4 o;
                    o.x = rna_u(siluf(a4.x + b4.x + rad*wA.x + eav*wB.x));
                    o.y = rna_u(siluf(a4.y + b4.y + rad*wA.y + eav*wB.y));
                    o.z = rna_u(siluf(a4.z + b4.z + rad*wA.z + eav*wB.z));
                    o.w = rna_u(siluf(a4.w + b4.w + rad*wA.w + eav*wB.w));
                    *(uint4*)(srow + c4*4) = o;
                }
            }
            __syncwarp();

            float acc[2][8][4];

            // -- GEMM1 (tensor): m2 = silu(m1 @ We2 + be2) --
            mma_gemm(slabU, W2P, be2s, g, t, acc);
            __syncwarp();
            {
                float maggL[16];
                #pragma unroll
                for (int s = 0; s < 16; s++) maggL[s] = 0.f;
                float vm[2][2];
                #pragma unroll
                for (int mt = 0; mt < 2; mt++) {
                    int r0 = mt*16 + g;
                    vm[mt][0] = (r0 == i) ? 0.f : 1.f;
                    vm[mt][1] = (r0 + 8 == i) ? 0.f : 1.f;
                }
                #pragma unroll
                for (int mt = 0; mt < 2; mt++) {
                    unsigned* r0p = slabU + (mt*16 + g)*SS + 2*t;
                    unsigned* r1p = r0p + 8*SS;
                    #pragma unroll
                    for (int nt = 0; nt < 8; nt++) {
                        float sv0 = siluf(acc[mt][nt][0]);
                        float sv1 = siluf(acc[mt][nt][1]);
                        float sv2 = siluf(acc[mt][nt][2]);
                        float sv3 = siluf(acc[mt][nt][3]);
                        maggL[nt*2+0] = fmaf(vm[mt][0], sv0, maggL[nt*2+0]);
                        maggL[nt*2+0] = fmaf(vm[mt][1], sv2, maggL[nt*2+0]);
                        maggL[nt*2+1] = fmaf(vm[mt][0], sv1, maggL[nt*2+1]);
                        maggL[nt*2+1] = fmaf(vm[mt][1], sv3, maggL[nt*2+1]);
                        uint2 pa = make_uint2(rna_u(sv0), rna_u(sv1));
                        uint2 pb = make_uint2(rna_u(sv2), rna_u(sv3));
                        *(uint2*)(r0p + nt*8) = pa;
                        *(uint2*)(r1p + nt*8) = pb;
                    }
                }
                #pragma unroll
                for (int s = 0; s < 16; s++) {
                    maggL[s] += __shfl_xor_sync(0xffffffffu, maggL[s], 4);
                    maggL[s] += __shfl_xor_sync(0xffffffffu, maggL[s], 8);
                    maggL[s] += __shfl_xor_sync(0xffffffffu, maggL[s], 16);
                }
                if (g == 0) {
                    #pragma unroll
                    for (int nt = 0; nt < 8; nt++)
                        *(float2*)(maggS + i*HH + nt*8 + 2*t) =
                            make_float2(maggL[2*nt], maggL[2*nt+1]);
                }
            }
            __syncwarp();

            // -- GEMM2 (tensor): t2 = silu(m2 @ Wc1 + bc1); cs = t2.Wc2 + bc2 --
            mma_gemm(slabU, WCP, bc1s, g, t, acc);
            {
                float csL[4] = {0.f, 0.f, 0.f, 0.f};
                #pragma unroll
                for (int nt = 0; nt < 8; nt++) {
                    float2 wc = *(const float2*)(Wc2s + nt*8 + 2*t);
                    #pragma unroll
                    for (int mt = 0; mt < 2; mt++) {
                        csL[mt*2+0] = fmaf(siluf(acc[mt][nt][0]), wc.x, csL[mt*2+0]);
                        csL[mt*2+0] = fmaf(siluf(acc[mt][nt][1]), wc.y, csL[mt*2+0]);
                        csL[mt*2+1] = fmaf(siluf(acc[mt][nt][2]), wc.x, csL[mt*2+1]);
                        csL[mt*2+1] = fmaf(siluf(acc[mt][nt][3]), wc.y, csL[mt*2+1]);
                    }
                }
                #pragma unroll
                for (int q = 0; q < 4; q++) {
                    csL[q] += __shfl_xor_sync(0xffffffffu, csL[q], 1);
                    csL[q] += __shfl_xor_sync(0xffffffffu, csL[q], 2);
                }
                if (t == 0) {
                    csWw[g]      = csL[0] + bc2l;
                    csWw[g + 8]  = csL[1] + bc2l;
                    csWw[g + 16] = csL[2] + bc2l;
                    csWw[g + 24] = csL[3] + bc2l;
                }
            }
            __syncwarp();

            // -- trans aggregation (self-edge has dn = 0) --
            {
                float cj = csWw[lane];
                float tx = wredsum(dnx * cj);
                float ty = wredsum(dny * cj);
                if (lane == 0) { aggS[i*2+0] = tx; aggS[i*2+1] = ty; }
            }
            __syncwarp();
        }
        __syncthreads();

        // ==== restage node weights into slab scratch ====
        {
            const float4* Wv1l = (const float4*)(Wv1 + l*HH*HH);
            const float4* Wn1l = (const float4*)(Wn1 + l*2*HH*HH);
            const float4* Wn2l = (const float4*)(Wn2 + l*HH*HH);
            float4* d = (float4*)slabF;
            for (int q = tid; q < 1024; q += NT) {
                d[q]        = Wv1l[q];
                d[q + 1024] = Wn1l[q];
                d[q + 2048] = Wn1l[q + 1024];
                d[q + 3072] = Wn2l[q];
            }
        }
        __syncthreads();
        const float* Wv1s = slabF;
        const float* Wn1s = slabF + HH*HH;
        const float* Wn2s = slabF + 3*HH*HH;

        // ==== node phase: phi_v, vel/loc update (rows 4w..4w+3) ====
        {
            float a0[4], a1[4];
            #pragma unroll
            for (int r = 0; r < 4; r++) { a0[r] = bv1s[lane]; a1[r] = bv1s[lane+32]; }
            #pragma unroll 4
            for (int c = 0; c < HH; c++) {
                const float* wr = Wv1s + c*HH;
                float w0 = wr[lane], w1 = wr[lane+32];
                #pragma unroll
                for (int r = 0; r < 4; r++) {
                    float hv = hS[(w*4+r)*HS + c];
                    a0[r] += hv*w0; a1[r] += hv*w1;
                }
            }
            float wv2a = Wv2s[lane], wv2b = Wv2s[lane + 32];
            #pragma unroll
            for (int r = 0; r < 4; r++) {
                float part = wredsum(siluf(a0[r])*wv2a + siluf(a1[r])*wv2b);
                if (lane == 0) {
                    int i = w*4 + r;
                    float phi = part + bv2l;
                    float vx = phi*velS[i*2+0] + aggS[i*2+0]*(1.0f/31.0f);
                    float vy = phi*velS[i*2+1] + aggS[i*2+1]*(1.0f/31.0f);
                    velS[i*2+0] = vx; velS[i*2+1] = vy;
                    locS[i*2+0] += vx; locS[i*2+1] += vy;
                }
            }
        }

        // ==== U = silu([h, magg] @ Wn1 + bn1) -> AS ====
        {
            float a0[4], a1[4];
            #pragma unroll
            for (int r = 0; r < 4; r++) { a0[r] = bn1s[lane]; a1[r] = bn1s[lane+32]; }
            #pragma unroll 4
            for (int c = 0; c < HH; c++) {
                const float* wr = Wn1s + c*HH;
                float w0 = wr[lane], w1 = wr[lane+32];
                #pragma unroll
                for (int r = 0; r < 4; r++) {
                    float hv = hS[(w*4+r)*HS + c];
                    a0[r] += hv*w0; a1[r] += hv*w1;
                }
            }
            #pragma unroll 4
            for (int c = 0; c < HH; c++) {
                const float* wr = Wn1s + (HH + c)*HH;
                float w0 = wr[lane], w1 = wr[lane+32];
                #pragma unroll
                for (int r = 0; r < 4; r++) {
                    float mv = maggS[(w*4+r)*HH + c];
                    a0[r] += mv*w0; a1[r] += mv*w1;
                }
            }
            #pragma unroll
            for (int r = 0; r < 4; r++) {
                AS[(w*4+r)*HS + lane]      = siluf(a0[r]);
                AS[(w*4+r)*HS + lane + 32] = siluf(a1[r]);
            }
        }

        // ==== h += U @ Wn2 + bn2 ====
        {
            float a0[4], a1[4];
            #pragma unroll
            for (int r = 0; r < 4; r++) { a0[r] = bn2s[lane]; a1[r] = bn2s[lane+32]; }
            #pragma unroll 4
            for (int c = 0; c < HH; c++) {
                const float* wr = Wn2s + c*HH;
                float w0 = wr[lane], w1 = wr[lane+32];
                #pragma unroll
                for (int r = 0; r < 4; r++) {
                    float uv = AS[(w*4+r)*HS + c];
                    a0[r] += uv*w0; a1[r] += uv*w1;
                }
            }
            #pragma unroll
            for (int r = 0; r < 4; r++) {
                hS[(w*4+r)*HS + lane]      += a0[r];
                hS[(w*4+r)*HS + lane + 32] += a1[r];
            }
        }
        __syncthreads();
    }

    // ---- output ----
    if (tid < NA*2) {
        int i = tid >> 1, c = tid & 1;
        out[((size_t)gidx*NA + i)*2 + c] = scl[c]*velS[tid] + mn[c];
    }
}

extern "C" void kernel_launch(void* const* d_in, const int* in_sizes, int n_in,
                              void* d_out, int out_size) {
    const float* obs  = (const float*)d_in[0];
    const float* scl  = (const float*)d_in[3];
    const float* mn   = (const float*)d_in[4];
    const float* embW = (const float*)d_in[5];
    const float* embb = (const float*)d_in[6];
    const float* We1  = (const float*)d_in[7];
    const float* be1  = (const float*)d_in[8];
    const float* We2  = (const float*)d_in[9];
    const float* be2  = (const float*)d_in[10];
    const float* Wc1  = (const float*)d_in[11];
    const float* bc1  = (const float*)d_in[12];
    const float* Wc2  = (const float*)d_in[13];
    const float* bc2  = (const float*)d_in[14];
    const float* Wv1  = (const float*)d_in[15];
    const float* bv1  = (const float*)d_in[16];
    const float* Wv2  = (const float*)d_in[17];
    const float* bv2  = (const float*)d_in[18];
    const float* Wn1  = (const float*)d_in[19];
    const float* bn1  = (const float*)d_in[20];
    const float* Wn2  = (const float*)d_in[21];
    const float* bn2  = (const float*)d_in[22];
    float* out = (float*)d_out;

    int n_nodes = in_sizes[0] / OBSW;
    int groups  = n_nodes / NA;

    cudaFuncSetAttribute(egnn_kernel, cudaFuncAttributeMaxDynamicSharedMemorySize, SMEM_BYTES);
    egnn_kernel<<<groups, NT, SMEM_BYTES>>>(
        obs, scl, mn, embW, embb,
        We1, be1, We2, be2, Wc1, bc1, Wc2, bc2,
        Wv1, bv1, Wv2, bv2, Wn1, bn1, Wn2, bn2, out);
}

// round 9
// speedup vs baseline: 4.8041x; 1.0754x over previous
#include <cuda_runtime.h>

#define NA    32
#define HH    64
#define HS    68      // h/A/B row stride
#define SS    68      // slab row stride (floats)
#define WPS   68      // weight-pair row stride (in float2)
#define NW    16
#define NPAIR 8
#define NT    512
#define NINV  16
#define NLAY  4
#define OBSW  20

#define SM_H     0
#define SM_A     (SM_H    + NA*HS)
#define SM_B     (SM_A    + NA*HS)
#define SM_MAGG  (SM_B    + NA*HS)
#define SM_EA    (SM_MAGG + NA*HH)
#define SM_W2P   (SM_EA   + NA*NA)        // We2 (hi,lo) pairs
#define SM_WCP   (SM_W2P  + 2*64*WPS)     // Wc1 (hi,lo) pairs
#define SM_SLAB  (SM_WCP  + 2*64*WPS)     // 8 pair-slabs 32x68 (also weight scratch)
#define SM_VEC   (SM_SLAB + NPAIR*NA*SS)
#define SM_LOC   (SM_VEC  + 10*HH)
#define SM_VEL   (SM_LOC  + 2*NA)
#define SM_AGG   (SM_VEL  + 2*NA)
#define SM_CS    (SM_AGG  + 2*NA)         // 16 warps x 32 partials
#define SMEM_FLOATS (SM_CS + NW*NA)
#define SMEM_BYTES  (SMEM_FLOATS * 4)

#define V_W128 0
#define V_W129 1
#define V_BE1  2
#define V_BE2  3
#define V_BC1  4
#define V_WC2  5
#define V_BV1  6
#define V_BN1  7
#define V_BN2  8
#define V_WV2  9

#define PAIRBAR(id) asm volatile("bar.sync %0, 64;" :: "r"(id) : "memory")

__device__ __forceinline__ float siluf(float x) {
    float hx = 0.5f * x;
    float t;
    asm("tanh.approx.f32 %0, %1;" : "=f"(t) : "f"(hx));
    return fmaf(hx, t, hx);
}

__device__ __forceinline__ unsigned rna_u(float x) {
    unsigned u;
    asm("cvt.rna.tf32.f32 %0, %1;" : "=r"(u) : "f"(x));
    return u;
}
__device__ __forceinline__ float rna_f(float x) { return __uint_as_float(rna_u(x)); }

__device__ __forceinline__ void mma8(float &d0, float &d1, float &d2, float &d3,
                                     unsigned a0, unsigned a1, unsigned a2, unsigned a3,
                                     unsigned b0, unsigned b1) {
    asm volatile(
        "mma.sync.aligned.m16n8k8.row.col.f32.tf32.tf32.f32 "
        "{%0,%1,%2,%3},{%4,%5,%6,%7},{%8,%9},{%0,%1,%2,%3};"
        : "+f"(d0), "+f"(d1), "+f"(d2), "+f"(d3)
        : "r"(a0), "r"(a1), "r"(a2), "r"(a3), "r"(b0), "r"(b1));
}

__device__ __forceinline__ float wredsum(float v) {
    v += __shfl_down_sync(0xffffffffu, v, 16);
    v += __shfl_down_sync(0xffffffffu, v, 8);
    v += __shfl_down_sync(0xffffffffu, v, 4);
    v += __shfl_down_sync(0xffffffffu, v, 2);
    v += __shfl_down_sync(0xffffffffu, v, 1);
    return v;
}

// Half GEMM: D[32e][32n] = slab[32e][64k] @ (Whi+Wlo)[64k][32n] + bias.
// Wp/bias pre-offset to this warp's n-half. acc[mt][nt][4].
__device__ __forceinline__ void mma_gemm_h(const unsigned* __restrict__ slabU,
                                           const float2* __restrict__ Wp,
                                           const float* __restrict__ bias,
                                           int g, int t, float (&acc)[2][4][4])
{
    #pragma unroll
    for (int nt = 0; nt < 4; nt++) {
        float2 b = *(const float2*)(bias + nt*8 + 2*t);
        #pragma unroll
        for (int mt = 0; mt < 2; mt++) {
            acc[mt][nt][0] = b.x; acc[mt][nt][1] = b.y;
            acc[mt][nt][2] = b.x; acc[mt][nt][3] = b.y;
        }
    }
    #pragma unroll
    for (int kt = 0; kt < 8; kt++) {
        unsigned a[2][4];
        #pragma unroll
        for (int mt = 0; mt < 2; mt++) {
            const unsigned* base = slabU + (mt*16 + g)*SS + kt*8 + t;
            a[mt][0] = base[0];
            a[mt][1] = base[8*SS];
            a[mt][2] = base[4];
            a[mt][3] = base[8*SS + 4];
        }
        const float2* wr0 = Wp + (kt*8 + t)*WPS + g;
        const float2* wr1 = wr0 + 4*WPS;
        #pragma unroll
        for (int nt = 0; nt < 4; nt++) {
            float2 p0 = wr0[nt*8];
            float2 p1 = wr1[nt*8];
            unsigned h0 = __float_as_uint(p0.x), l0 = __float_as_uint(p0.y);
            unsigned h1 = __float_as_uint(p1.x), l1 = __float_as_uint(p1.y);
            #pragma unroll
            for (int mt = 0; mt < 2; mt++) {
                mma8(acc[mt][nt][0], acc[mt][nt][1], acc[mt][nt][2], acc[mt][nt][3],
                     a[mt][0], a[mt][1], a[mt][2], a[mt][3], h0, h1);
                mma8(acc[mt][nt][0], acc[mt][nt][1], acc[mt][nt][2], acc[mt][nt][3],
                     a[mt][0], a[mt][1], a[mt][2], a[mt][3], l0, l1);
            }
        }
    }
}

__global__ void __launch_bounds__(NT, 1)
egnn_kernel(const float* __restrict__ obs,
            const float* __restrict__ scl,
            const float* __restrict__ mn,
            const float* __restrict__ embW,
            const float* __restrict__ embb,
            const float* __restrict__ We1,
            const float* __restrict__ be1,
            const float* __restrict__ We2,
            const float* __restrict__ be2,
            const float* __restrict__ Wc1,
            const float* __restrict__ bc1,
            const float* __restrict__ Wc2,
            const float* __restrict__ bc2,
            const float* __restrict__ Wv1,
            const float* __restrict__ bv1,
            const float* __restrict__ Wv2,
            const float* __restrict__ bv2,
            const float* __restrict__ Wn1,
            const float* __restrict__ bn1,
            const float* __restrict__ Wn2,
            const float* __restrict__ bn2,
            float* __restrict__ out)
{
    extern __shared__ float sm[];
    float* hS    = sm + SM_H;
    float* AS    = sm + SM_A;
    float* BS    = sm + SM_B;
    float* maggS = sm + SM_MAGG;
    float* eaS   = sm + SM_EA;
    float2* W2P  = (float2*)(sm + SM_W2P);
    float2* WCP  = (float2*)(sm + SM_WCP);
    float* slabF = sm + SM_SLAB;
    float* vecS  = sm + SM_VEC;
    float* locS  = sm + SM_LOC;
    float* velS  = sm + SM_VEL;
    float* aggS  = sm + SM_AGG;
    float* csS   = sm + SM_CS;

    float* w128s = vecS + V_W128*HH;
    float* w129s = vecS + V_W129*HH;
    float* be1s  = vecS + V_BE1*HH;
    float* be2s  = vecS + V_BE2*HH;
    float* bc1s  = vecS + V_BC1*HH;
    float* Wc2s  = vecS + V_WC2*HH;
    float* bv1s  = vecS + V_BV1*HH;
    float* bn1s  = vecS + V_BN1*HH;
    float* bn2s  = vecS + V_BN2*HH;
    float* Wv2s  = vecS + V_WV2*HH;

    const int tid  = threadIdx.x;
    const int w    = tid >> 5;         // 0..15
    const int lane = tid & 31;
    const int g    = lane >> 2;        // 0..7
    const int t    = lane & 3;         // 0..3
    const int pair = w >> 1;           // 0..7
    const int sub  = w & 1;            // n-half
    const int bid  = pair + 1;         // named barrier id
    const int gidx = blockIdx.x;

    unsigned* slabU = (unsigned*)(slabF + pair * (NA*SS));
    float* csW = csS + w * NA;

    // ---- stage obs into BS scratch ----
    const float* obsg = obs + (size_t)gidx * NA * OBSW;
    for (int q = tid; q < NA*OBSW; q += NT) BS[q] = obsg[q];
    __syncthreads();

    if (tid < NA*2) {
        int i = tid >> 1, c = tid & 1;
        locS[tid] = BS[i*OBSW + NINV + c];
        velS[tid] = BS[i*OBSW + NINV + 2 + c];
    }
    __syncthreads();

    for (int p = tid; p < NA*NA; p += NT) {
        int i = p >> 5, j = p & 31;
        float dx = locS[i*2+0] - locS[j*2+0];
        float dy = locS[i*2+1] - locS[j*2+1];
        eaS[p] = dx*dx + dy*dy;
    }

    // h = inv @ embW + embb  (warp w: rows 2w, 2w+1)
    {
        float a0[2], a1[2];
        #pragma unroll
        for (int r = 0; r < 2; r++) { a0[r] = embb[lane]; a1[r] = embb[lane+32]; }
        #pragma unroll
        for (int c = 0; c < NINV; c++) {
            float w0 = embW[c*HH + lane];
            float w1 = embW[c*HH + lane + 32];
            #pragma unroll
            for (int r = 0; r < 2; r++) {
                float iv = BS[(w*2+r)*OBSW + c];
                a0[r] += iv*w0; a1[r] += iv*w1;
            }
        }
        #pragma unroll
        for (int r = 0; r < 2; r++) {
            hS[(w*2+r)*HS + lane]      = a0[r];
            hS[(w*2+r)*HS + lane + 32] = a1[r];
        }
    }
    __syncthreads();

    #pragma unroll 1
    for (int l = 0; l < NLAY; l++) {
        // ==== stage edge weights as tf32 (hi,lo) pairs + We1 + vectors ====
        {
            const float4* s2 = (const float4*)(We2 + l*HH*HH);
            const float4* sc = (const float4*)(Wc1 + l*HH*HH);
            for (int t4 = tid; t4 < 1024; t4 += NT) {
                int k = t4 >> 4, n0 = (t4 & 15) * 4;
                float4 w2 = s2[t4], wc = sc[t4];
                float2* p2 = W2P + k*WPS + n0;
                float2* pc = WCP + k*WPS + n0;
                float h;
                h = rna_f(w2.x); p2[0] = make_float2(h, rna_f(w2.x - h));
                h = rna_f(w2.y); p2[1] = make_float2(h, rna_f(w2.y - h));
                h = rna_f(w2.z); p2[2] = make_float2(h, rna_f(w2.z - h));
                h = rna_f(w2.w); p2[3] = make_float2(h, rna_f(w2.w - h));
                h = rna_f(wc.x); pc[0] = make_float2(h, rna_f(wc.x - h));
                h = rna_f(wc.y); pc[1] = make_float2(h, rna_f(wc.y - h));
                h = rna_f(wc.z); pc[2] = make_float2(h, rna_f(wc.z - h));
                h = rna_f(wc.w); pc[3] = make_float2(h, rna_f(wc.w - h));
            }
            const float4* We1l = (const float4*)(We1 + l*130*HH);
            float4* scr = (float4*)slabF;
            for (int q = tid; q < 2048; q += NT) scr[q] = We1l[q];
            if (tid < HH) {
                w128s[tid] = We1[(l*130 + 128)*HH + tid];
                w129s[tid] = We1[(l*130 + 129)*HH + tid];
                be1s[tid]  = be1[l*HH + tid];
                be2s[tid]  = be2[l*HH + tid];
                bc1s[tid]  = bc1[l*HH + tid];
                Wc2s[tid]  = Wc2[l*HH + tid];
                bv1s[tid]  = bv1[l*HH + tid];
                bn1s[tid]  = bn1[l*HH + tid];
                bn2s[tid]  = bn2[l*HH + tid];
                Wv2s[tid]  = Wv2[l*HH + tid];
            }
        }
        const float bc2l = bc2[l];
        const float bv2l = bv2[l];
        __syncthreads();

        // ==== phase A: A = h@We1A + be1, B = h@We1B (rows 2w, 2w+1) ====
        {
            const float* We1As = slabF;
            const float* We1Bs = slabF + HH*HH;
            float a0[2], a1[2], b0[2], b1[2];
            #pragma unroll
            for (int r = 0; r < 2; r++) {
                a0[r] = be1s[lane]; a1[r] = be1s[lane + 32];
                b0[r] = 0.f; b1[r] = 0.f;
            }
            #pragma unroll 8
            for (int c = 0; c < HH; c++) {
                const float* wrA = We1As + c*HH;
                const float* wrB = We1Bs + c*HH;
                float wa0 = wrA[lane], wa1 = wrA[lane+32];
                float wb0 = wrB[lane], wb1 = wrB[lane+32];
                #pragma unroll
                for (int r = 0; r < 2; r++) {
                    float hv = hS[(w*2+r)*HS + c];
                    a0[r] += hv*wa0; a1[r] += hv*wa1;
                    b0[r] += hv*wb0; b1[r] += hv*wb1;
                }
            }
            #pragma unroll
            for (int r = 0; r < 2; r++) {
                AS[(w*2+r)*HS + lane]      = a0[r];
                AS[(w*2+r)*HS + lane + 32] = a1[r];
                BS[(w*2+r)*HS + lane]      = b0[r];
                BS[(w*2+r)*HS + lane + 32] = b1[r];
            }
        }
        __syncthreads();

        // ==== edge phase: warp pair = one receiver; sub = n-half ====
        #pragma unroll 1
        for (int it = 0; it < 4; it++) {
            const int i = it*NPAIR + pair;

            // -- m1 construction (lane = sender j), this warp's channel half --
            float dnx, dny;
            {
                const int j = lane;
                float dx = locS[i*2+0] - locS[j*2+0];
                float dy = locS[i*2+1] - locS[j*2+1];
                float rad = dx*dx + dy*dy;
                float invr = __fdividef(1.0f, sqrtf(rad) + 1.0f);
                dnx = dx * invr; dny = dy * invr;
                float eav = eaS[i*NA + j];
                const float* Ai = AS + i*HS;
                const float* Bj = BS + j*HS;
                unsigned* srow = slabU + j*SS;
                const int c4lo = sub*8;
                #pragma unroll
                for (int c4i = 0; c4i < 8; c4i++) {
                    int c4 = c4lo + c4i;
                    float4 wA = *(const float4*)(w128s + c4*4);
                    float4 wB = *(const float4*)(w129s + c4*4);
                    float4 a4 = *(const float4*)(Ai + c4*4);
                    float4 b4 = *(const float4*)(Bj + c4*4);
                    uint4 o;
                    o.x = rna_u(siluf(a4.x + b4.x + rad*wA.x + eav*wB.x));
                    o.y = rna_u(siluf(a4.y + b4.y + rad*wA.y + eav*wB.y));
                    o.z = rna_u(siluf(a4.z + b4.z + rad*wA.z + eav*wB.z));
                    o.w = rna_u(siluf(a4.w + b4.w + rad*wA.w + eav*wB.w));
                    *(uint4*)(srow + c4*4) = o;
                }
            }
            PAIRBAR(bid);                       // m1 complete (both halves)

            float acc[2][4][4];

            // -- GEMM1 (tensor): m2-half = silu(m1 @ We2 + be2) --
            mma_gemm_h(slabU, W2P + sub*32, be2s + sub*32, g, t, acc);
            PAIRBAR(bid);                       // both GEMM1 reads done
            {
                float maggL[8];
                #pragma unroll
                for (int s = 0; s < 8; s++) maggL[s] = 0.f;
                float vm[2][2];
                #pragma unroll
                for (int mt = 0; mt < 2; mt++) {
                    int r0 = mt*16 + g;
                    vm[mt][0] = (r0 == i) ? 0.f : 1.f;
                    vm[mt][1] = (r0 + 8 == i) ? 0.f : 1.f;
                }
                #pragma unroll
                for (int mt = 0; mt < 2; mt++) {
                    unsigned* r0p = slabU + (mt*16 + g)*SS + sub*32 + 2*t;
                    unsigned* r1p = r0p + 8*SS;
                    #pragma unroll
                    for (int nt = 0; nt < 4; nt++) {
                        float sv0 = siluf(acc[mt][nt][0]);
                        float sv1 = siluf(acc[mt][nt][1]);
                        float sv2 = siluf(acc[mt][nt][2]);
                        float sv3 = siluf(acc[mt][nt][3]);
                        maggL[nt*2+0] = fmaf(vm[mt][0], sv0, maggL[nt*2+0]);
                        maggL[nt*2+0] = fmaf(vm[mt][1], sv2, maggL[nt*2+0]);
                        maggL[nt*2+1] = fmaf(vm[mt][0], sv1, maggL[nt*2+1]);
                        maggL[nt*2+1] = fmaf(vm[mt][1], sv3, maggL[nt*2+1]);
                        *(uint2*)(r0p + nt*8) = make_uint2(rna_u(sv0), rna_u(sv1));
                        *(uint2*)(r1p + nt*8) = make_uint2(rna_u(sv2), rna_u(sv3));
                    }
                }
                #pragma unroll
                for (int s = 0; s < 8; s++) {
                    maggL[s] += __shfl_xor_sync(0xffffffffu, maggL[s], 4);
                    maggL[s] += __shfl_xor_sync(0xffffffffu, maggL[s], 8);
                    maggL[s] += __shfl_xor_sync(0xffffffffu, maggL[s], 16);
                }
                if (g == 0) {
                    #pragma unroll
                    for (int nt = 0; nt < 4; nt++)
                        *(float2*)(maggS + i*HH + sub*32 + nt*8 + 2*t) =
                            make_float2(maggL[2*nt], maggL[2*nt+1]);
                }
            }
            PAIRBAR(bid);                       // m2 complete (both halves)

            // -- GEMM2 (tensor): t2-half; cs partial = t2.Wc2-half --
            mma_gemm_h(slabU, WCP + sub*32, bc1s + sub*32, g, t, acc);
            {
                float csL[4] = {0.f, 0.f, 0.f, 0.f};
                #pragma unroll
                for (int nt = 0; nt < 4; nt++) {
                    float2 wc = *(const float2*)(Wc2s + sub*32 + nt*8 + 2*t);
                    #pragma unroll
                    for (int mt = 0; mt < 2; mt++) {
                        csL[mt*2+0] = fmaf(siluf(acc[mt][nt][0]), wc.x, csL[mt*2+0]);
                        csL[mt*2+0] = fmaf(siluf(acc[mt][nt][1]), wc.y, csL[mt*2+0]);
                        csL[mt*2+1] = fmaf(siluf(acc[mt][nt][2]), wc.x, csL[mt*2+1]);
                        csL[mt*2+1] = fmaf(siluf(acc[mt][nt][3]), wc.y, csL[mt*2+1]);
                    }
                }
                #pragma unroll
                for (int q = 0; q < 4; q++) {
                    csL[q] += __shfl_xor_sync(0xffffffffu, csL[q], 1);
                    csL[q] += __shfl_xor_sync(0xffffffffu, csL[q], 2);
                }
                if (t == 0) {
                    csW[g]      = csL[0];
                    csW[g + 8]  = csL[1];
                    csW[g + 16] = csL[2];
                    csW[g + 24] = csL[3];
                }
            }
            PAIRBAR(bid);                       // cs partials + GEMM2 reads done

            // -- combine cs halves + trans aggregation (sub 0 only) --
            if (sub == 0) {
                float cj = csS[w*NA + lane] + csS[(w+1)*NA + lane] + bc2l;
                float tx = wredsum(dnx * cj);
                float ty = wredsum(dny * cj);
                if (lane == 0) { aggS[i*2+0] = tx; aggS[i*2+1] = ty; }
            }
        }
        __syncthreads();

        // ==== restage node weights into slab scratch ====
        {
            const float4* Wv1l = (const float4*)(Wv1 + l*HH*HH);
            const float4* Wn1l = (const float4*)(Wn1 + l*2*HH*HH);
            const float4* Wn2l = (const float4*)(Wn2 + l*HH*HH);
            float4* d = (float4*)slabF;
            for (int q = tid; q < 1024; q += NT) {
                d[q]        = Wv1l[q];
                d[q + 1024] = Wn1l[q];
                d[q + 2048] = Wn1l[q + 1024];
                d[q + 3072] = Wn2l[q];
            }
        }
        __syncthreads();
        const float* Wv1s = slabF;
        const float* Wn1s = slabF + HH*HH;
        const float* Wn2s = slabF + 3*HH*HH;

        // ==== node phase: phi_v, vel/loc update (rows 2w, 2w+1) ====
        {
            float a0[2], a1[2];
            #pragma unroll
            for (int r = 0; r < 2; r++) { a0[r] = bv1s[lane]; a1[r] = bv1s[lane+32]; }
            #pragma unroll 8
            for (int c = 0; c < HH; c++) {
                const float* wr = Wv1s + c*HH;
                float w0 = wr[lane], w1 = wr[lane+32];
                #pragma unroll
                for (int r = 0; r < 2; r++) {
                    float hv = hS[(w*2+r)*HS + c];
                    a0[r] += hv*w0; a1[r] += hv*w1;
                }
            }
            float wv2a = Wv2s[lane], wv2b = Wv2s[lane + 32];
            #pragma unroll
            for (int r = 0; r < 2; r++) {
                float part = wredsum(siluf(a0[r])*wv2a + siluf(a1[r])*wv2b);
                if (lane == 0) {
                    int i = w*2 + r;
                    float phi = part + bv2l;
                    float vx = phi*velS[i*2+0] + aggS[i*2+0]*(1.0f/31.0f);
                    float vy = phi*velS[i*2+1] + aggS[i*2+1]*(1.0f/31.0f);
                    velS[i*2+0] = vx; velS[i*2+1] = vy;
                    locS[i*2+0] += vx; locS[i*2+1] += vy;
                }
            }
        }

        // ==== U = silu([h, magg] @ Wn1 + bn1) -> AS ====
        {
            float a0[2], a1[2];
            #pragma unroll
            for (int r = 0; r < 2; r++) { a0[r] = bn1s[lane]; a1[r] = bn1s[lane+32]; }
            #pragma unroll 8
            for (int c = 0; c < HH; c++) {
                const float* wr = Wn1s + c*HH;
                float w0 = wr[lane], w1 = wr[lane+32];
                #pragma unroll
                for (int r = 0; r < 2; r++) {
                    float hv = hS[(w*2+r)*HS + c];
                    a0[r] += hv*w0; a1[r] += hv*w1;
                }
            }
            #pragma unroll 8
            for (int c = 0; c < HH; c++) {
                const float* wr = Wn1s + (HH + c)*HH;
                float w0 = wr[lane], w1 = wr[lane+32];
                #pragma unroll
                for (int r = 0; r < 2; r++) {
                    float mv = maggS[(w*2+r)*HH + c];
                    a0[r] += mv*w0; a1[r] += mv*w1;
                }
            }
            #pragma unroll
            for (int r = 0; r < 2; r++) {
                AS[(w*2+r)*HS + lane]      = siluf(a0[r]);
                AS[(w*2+r)*HS + lane + 32] = siluf(a1[r]);
            }
        }

        // ==== h += U @ Wn2 + bn2 ====  (warp-local rows)
        {
            float a0[2], a1[2];
            #pragma unroll
            for (int r = 0; r < 2; r++) { a0[r] = bn2s[lane]; a1[r] = bn2s[lane+32]; }
            #pragma unroll 8
            for (int c = 0; c < HH; c++) {
                const float* wr = Wn2s + c*HH;
                float w0 = wr[lane], w1 = wr[lane+32];
                #pragma unroll
                for (int r = 0; r < 2; r++) {
                    float uv = AS[(w*2+r)*HS + c];
                    a0[r] += uv*w0; a1[r] += uv*w1;
                }
            }
            #pragma unroll
            for (int r = 0; r < 2; r++) {
                hS[(w*2+r)*HS + lane]      += a0[r];
                hS[(w*2+r)*HS + lane + 32] += a1[r];
            }
        }
        __syncthreads();
    }

    // ---- output ----
    if (tid < NA*2) {
        int i = tid >> 1, c = tid & 1;
        out[((size_t)gidx*NA + i)*2 + c] = scl[c]*velS[tid] + mn[c];
    }
}

extern "C" void kernel_launch(void* const* d_in, const int* in_sizes, int n_in,
                              void* d_out, int out_size) {
    const float* obs  = (const float*)d_in[0];
    const float* scl  = (const float*)d_in[3];
    const float* mn   = (const float*)d_in[4];
    const float* embW = (const float*)d_in[5];
    const float* embb = (const float*)d_in[6];
    const float* We1  = (const float*)d_in[7];
    const float* be1  = (const float*)d_in[8];
    const float* We2  = (const float*)d_in[9];
    const float* be2  = (const float*)d_in[10];
    const float* Wc1  = (const float*)d_in[11];
    const float* bc1  = (const float*)d_in[12];
    const float* Wc2  = (const float*)d_in[13];
    const float* bc2  = (const float*)d_in[14];
    const float* Wv1  = (const float*)d_in[15];
    const float* bv1  = (const float*)d_in[16];
    const float* Wv2  = (const float*)d_in[17];
    const float* bv2  = (const float*)d_in[18];
    const float* Wn1  = (const float*)d_in[19];
    const float* bn1  = (const float*)d_in[20];
    const float* Wn2  = (const float*)d_in[21];
    const float* bn2  = (const float*)d_in[22];
    float* out = (float*)d_out;

    int n_nodes = in_sizes[0] / OBSW;
    int groups  = n_nodes / NA;

    cudaFuncSetAttribute(egnn_kernel, cudaFuncAttributeMaxDynamicSharedMemorySize, SMEM_BYTES);
    egnn_kernel<<<groups, NT, SMEM_BYTES>>>(
        obs, scl, mn, embW, embb,
        We1, be1, We2, be2, Wc1, bc1, Wc2, bc2,
        Wv1, bv1, Wv2, bv2, Wn1, bn1, Wn2, bn2, out);
}